// round 1
// baseline (speedup 1.0000x reference)
#include <cuda_runtime.h>

#define NE 100000
#define NR 100
#define D  128
#define NB 10
#define NL 2
#define EG 600000
#define MAXT 64   // tiles/relation: covers E_r <= 8192 (mean 6000, sd 77 -> +28 sigma)

// ---------------- scratch (device globals: no allocation allowed) ----------------
__device__ float g_W[(size_t)NL*NR*D*D];   // per-(layer,relation) combined basis matrices
__device__ float g_X[(size_t)NE*D];        // layer-0 output
__device__ float g_AGG[(size_t)NE*D];      // pre-activation accumulator
__device__ float g_indeg[NE];
__device__ int   g_cnt[NR];
__device__ int   g_off[NR+1];
__device__ int   g_cur[NR];
__device__ int   g_ord[EG];                // edge ids sorted by relation

// ---------------- helpers ----------------
__device__ __forceinline__ unsigned long long splat2(float v){
    unsigned u = __float_as_uint(v);
    return ((unsigned long long)u << 32) | (unsigned long long)u;
}
__device__ __forceinline__ void fma2(unsigned long long &acc,
                                     unsigned long long a, unsigned long long b){
    asm("fma.rn.f32x2 %0, %1, %2, %0;" : "+l"(acc) : "l"(a), "l"(b));
}

// ---------------- prep kernels ----------------
__global__ void k_init(){
    int i = blockIdx.x*blockDim.x + threadIdx.x;
    if (i < NE) g_indeg[i] = 0.f;
    if (i < NR) g_cnt[i] = 0;
}

__global__ void k_deg_hist(const int* __restrict__ tgt, const int* __restrict__ et){
    int e = blockIdx.x*blockDim.x + threadIdx.x;
    if (e < EG){
        atomicAdd(&g_indeg[tgt[e]], 1.f);
        atomicAdd(&g_cnt[et[e]], 1);
    }
}

__global__ void k_scan(){
    if (threadIdx.x == 0){
        int run = 0;
        for (int r = 0; r < NR; r++){ g_off[r] = run; g_cur[r] = run; run += g_cnt[r]; }
        g_off[NR] = run;
    }
}

__global__ void k_scatter(const int* __restrict__ et){
    int e = blockIdx.x*blockDim.x + threadIdx.x;
    if (e < EG){
        int p = atomicAdd(&g_cur[et[e]], 1);
        g_ord[p] = e;
    }
}

// W[l,r] = sum_b coefs[l,r,b] * bases[b]
__global__ void k_relw(const float* __restrict__ bases, const float* __restrict__ coefs){
    int lr = blockIdx.x;                 // 0 .. NL*NR-1
    float c[NB];
#pragma unroll
    for (int b = 0; b < NB; b++) c[b] = coefs[lr*NB + b];
    float* w = g_W + (size_t)lr*D*D;
    for (int i = threadIdx.x; i < D*D; i += blockDim.x){
        float a = 0.f;
#pragma unroll
        for (int b = 0; b < NB; b++) a += c[b]*bases[b*D*D + i];
        w[i] = a;
    }
}

// ---------------- dense self-GEMM: AGG = X @ self_w[l] + bias[l] ----------------
// 128x128 tile, 256 threads, 8x8 microtile per thread, fma.rn.f32x2 inner loop.
__global__ void __launch_bounds__(256,2) k_self(const float* __restrict__ x0,
        const float* __restrict__ selfw, const float* __restrict__ bias, int layer){
    __shared__ __align__(16) unsigned long long As2[128*17]; // A splatted into f32 pairs, pad 1
    __shared__ __align__(16) float Ws[16*D];

    const float* X = (layer == 0) ? x0 : g_X;
    const float* W = selfw + (size_t)layer*D*D;

    int tid  = threadIdx.x;
    int tn   = tid & 15, tm = tid >> 4;
    int half = tid & 1,  row = tid >> 1;
    int wk   = tid >> 4, wseg = tid & 15;

    int row0 = blockIdx.x*128;
    int gr   = min(row0 + row, NE-1);
    const float* xrow = X + (size_t)gr*D;

    unsigned long long acc[8][4];
#pragma unroll
    for (int i = 0; i < 8; i++)
#pragma unroll
        for (int j = 0; j < 4; j++) acc[i][j] = 0ull;

    for (int kc = 0; kc < 8; kc++){
#pragma unroll
        for (int q = 0; q < 2; q++){
            float4 v = *(const float4*)(xrow + kc*16 + half*8 + q*4);
            unsigned long long* dst = &As2[row*17 + half*8 + q*4];
            dst[0] = splat2(v.x); dst[1] = splat2(v.y);
            dst[2] = splat2(v.z); dst[3] = splat2(v.w);
        }
        {
            const float4* g = (const float4*)(W + (size_t)(kc*16 + wk)*D + wseg*8);
            float4 a = g[0], b = g[1];
            float4* sh = (float4*)(Ws + wk*D + wseg*8);
            sh[0] = a; sh[1] = b;
        }
        __syncthreads();
#pragma unroll
        for (int kk = 0; kk < 16; kk++){
            unsigned long long a[8];
#pragma unroll
            for (int i = 0; i < 8; i++) a[i] = As2[(tm*8+i)*17 + kk];
            const double* bw = (const double*)(Ws + kk*D + tn*8);
            unsigned long long b[4];
#pragma unroll
            for (int j = 0; j < 4; j++) b[j] = __double_as_longlong(bw[j]);
#pragma unroll
            for (int i = 0; i < 8; i++)
#pragma unroll
                for (int j = 0; j < 4; j++) fma2(acc[i][j], a[i], b[j]);
        }
        __syncthreads();
    }

#pragma unroll
    for (int i = 0; i < 8; i++){
        int grow = row0 + tm*8 + i;
        if (grow < NE){
            float* out = g_AGG + (size_t)grow*D + tn*8;
#pragma unroll
            for (int j = 0; j < 4; j++){
                unsigned long long v = acc[i][j];
                float lo = __uint_as_float((unsigned)(v & 0xffffffffu));
                float hi = __uint_as_float((unsigned)(v >> 32));
                out[2*j]   = lo + bias[layer*D + tn*8 + 2*j];
                out[2*j+1] = hi + bias[layer*D + tn*8 + 2*j + 1];
            }
        }
    }
}

// ---------------- edge GEMM: AGG[tgt_e] += ew_e * (X[src_e] @ W[l,rel]) ----------------
// block = (relation, tile of 128 edges); W tile streamed through SMEM, atomic scatter epilogue.
__global__ void __launch_bounds__(256,2) k_edge(const float* __restrict__ x0,
        const int* __restrict__ src, const int* __restrict__ tgt, int layer){
    __shared__ __align__(16) unsigned long long As2[128*17];
    __shared__ __align__(16) float Ws[16*D];
    __shared__ int   s_src[128];
    __shared__ int   s_tgt[128];
    __shared__ float s_w[128];

    int r   = blockIdx.x;
    int s0  = g_off[r];
    int cnt = g_off[r+1] - s0;
    int t0  = blockIdx.y * 128;
    if (t0 >= cnt) return;                 // uniform across block (before any barrier)
    int valid = min(128, cnt - t0);

    const float* X = (layer == 0) ? x0 : g_X;
    int tid = threadIdx.x;
    if (tid < 128){
        int m = tid;
        int e = g_ord[s0 + t0 + min(m, valid-1)];
        s_src[m] = src[e];
        int t = tgt[e];
        s_tgt[m] = t;
        s_w[m]   = (m < valid) ? (1.f / fmaxf(g_indeg[t], 1.f)) : 0.f;
    }
    __syncthreads();

    const float* W = g_W + ((size_t)layer*NR + r)*D*D;
    int tn   = tid & 15, tm = tid >> 4;
    int half = tid & 1,  row = tid >> 1;
    int wk   = tid >> 4, wseg = tid & 15;
    const float* xrow = X + (size_t)s_src[row]*D;

    unsigned long long acc[8][4];
#pragma unroll
    for (int i = 0; i < 8; i++)
#pragma unroll
        for (int j = 0; j < 4; j++) acc[i][j] = 0ull;

    for (int kc = 0; kc < 8; kc++){
#pragma unroll
        for (int q = 0; q < 2; q++){
            float4 v = *(const float4*)(xrow + kc*16 + half*8 + q*4);
            unsigned long long* dst = &As2[row*17 + half*8 + q*4];
            dst[0] = splat2(v.x); dst[1] = splat2(v.y);
            dst[2] = splat2(v.z); dst[3] = splat2(v.w);
        }
        {
            const float4* g = (const float4*)(W + (size_t)(kc*16 + wk)*D + wseg*8);
            float4 a = g[0], b = g[1];
            float4* sh = (float4*)(Ws + wk*D + wseg*8);
            sh[0] = a; sh[1] = b;
        }
        __syncthreads();
#pragma unroll
        for (int kk = 0; kk < 16; kk++){
            unsigned long long a[8];
#pragma unroll
            for (int i = 0; i < 8; i++) a[i] = As2[(tm*8+i)*17 + kk];
            const double* bw = (const double*)(Ws + kk*D + tn*8);
            unsigned long long b[4];
#pragma unroll
            for (int j = 0; j < 4; j++) b[j] = __double_as_longlong(bw[j]);
#pragma unroll
            for (int i = 0; i < 8; i++)
#pragma unroll
                for (int j = 0; j < 4; j++) fma2(acc[i][j], a[i], b[j]);
        }
        __syncthreads();
    }

#pragma unroll
    for (int i = 0; i < 8; i++){
        int m = tm*8 + i;
        if (m < valid){
            float w = s_w[m];
            float* out = g_AGG + (size_t)s_tgt[m]*D + tn*8;
#pragma unroll
            for (int j = 0; j < 4; j++){
                unsigned long long v = acc[i][j];
                float lo = __uint_as_float((unsigned)(v & 0xffffffffu));
                float hi = __uint_as_float((unsigned)(v >> 32));
                atomicAdd(out + 2*j,     w*lo);
                atomicAdd(out + 2*j + 1, w*hi);
            }
        }
    }
}

// ---------------- ReLU ----------------
__global__ void k_relu(float* __restrict__ dout, int layer){
    int i = blockIdx.x*blockDim.x + threadIdx.x;
    if (i < NE*D/4){
        float4 v = ((const float4*)g_AGG)[i];
        v.x = fmaxf(v.x, 0.f); v.y = fmaxf(v.y, 0.f);
        v.z = fmaxf(v.z, 0.f); v.w = fmaxf(v.w, 0.f);
        float4* o = (layer == 0) ? (float4*)g_X : (float4*)dout;
        o[i] = v;
    }
}

// ---------------- launch ----------------
extern "C" void kernel_launch(void* const* d_in, const int* in_sizes, int n_in,
                              void* d_out, int out_size){
    const float* x0    = (const float*)d_in[0];
    const float* bases = (const float*)d_in[1];
    const float* coefs = (const float*)d_in[2];
    const float* selfw = (const float*)d_in[3];
    const float* bias  = (const float*)d_in[4];
    const int*   source= (const int*)d_in[5];
    const int*   target= (const int*)d_in[6];
    const int*   etype = (const int*)d_in[7];
    float* out = (float*)d_out;

    k_init<<<(NE+255)/256, 256>>>();
    k_deg_hist<<<(EG+255)/256, 256>>>(target, etype);
    k_scan<<<1, 32>>>();
    k_scatter<<<(EG+255)/256, 256>>>(etype);
    k_relw<<<NL*NR, 256>>>(bases, coefs);

    for (int l = 0; l < NL; l++){
        k_self<<<(NE+127)/128, 256>>>(x0, selfw, bias, l);
        k_edge<<<dim3(NR, MAXT), 256>>>(x0, source, target, l);
        k_relu<<<(NE*D/4+255)/256, 256>>>(out, l);
    }
}

// round 2
// speedup vs baseline: 1.4209x; 1.4209x over previous
#include <cuda_runtime.h>

#define NE 100000
#define NR 100
#define D  128
#define NB 10
#define NL 2
#define EG 600000
#define MAXT 64       // tiles/relation: covers E_r <= 8192 (mean 6000, sd 77 -> +28 sigma)
#define EPB 2048      // edges per block in prep kernels

// ---------------- scratch (device globals: no allocation allowed) ----------------
__device__ float g_W[(size_t)NL*NR*D*D];   // per-(layer,relation) combined basis matrices
__device__ float g_X[(size_t)NE*D];        // layer-0 output
__device__ float g_AGG[(size_t)NE*D];      // pre-activation accumulator
__device__ float g_indeg[NE];
__device__ int   g_cnt[NR];
__device__ int   g_off[NR+1];
__device__ int   g_cur[NR];
__device__ int   g_ord[EG];                // edge ids grouped by relation

// ---------------- helpers ----------------
__device__ __forceinline__ unsigned long long splat2(float v){
    unsigned u = __float_as_uint(v);
    return ((unsigned long long)u << 32) | (unsigned long long)u;
}
__device__ __forceinline__ void fma2(unsigned long long &acc,
                                     unsigned long long a, unsigned long long b){
    asm("fma.rn.f32x2 %0, %1, %2, %0;" : "+l"(acc) : "l"(a), "l"(b));
}
__device__ __forceinline__ void red4(float* p, float a, float b, float c, float d){
    asm volatile("red.global.add.v4.f32 [%0], {%1,%2,%3,%4};"
                 :: "l"(p), "f"(a), "f"(b), "f"(c), "f"(d) : "memory");
}

// ---------------- prep kernels ----------------
__global__ void k_init(){
    int i = blockIdx.x*blockDim.x + threadIdx.x;
    if (i < NE) g_indeg[i] = 0.f;
    if (i < NR) g_cnt[i] = 0;
}

// histogram with smem aggregation for the 100-relation counters;
// indeg atomics stay global (spread over 100k addresses -> no contention).
__global__ void k_hist(const int* __restrict__ tgt, const int* __restrict__ et){
    __shared__ int lcnt[NR];
    int tid = threadIdx.x;
    for (int i = tid; i < NR; i += 256) lcnt[i] = 0;
    __syncthreads();
    int e0 = blockIdx.x*EPB;
#pragma unroll
    for (int q = 0; q < EPB/256; q++){
        int e = e0 + q*256 + tid;
        if (e < EG){
            atomicAdd(&g_indeg[tgt[e]], 1.f);
            atomicAdd(&lcnt[et[e]], 1);
        }
    }
    __syncthreads();
    for (int i = tid; i < NR; i += 256)
        if (lcnt[i]) atomicAdd(&g_cnt[i], lcnt[i]);
}

__global__ void k_scan(){
    if (threadIdx.x == 0){
        int run = 0;
        for (int r = 0; r < NR; r++){ g_off[r] = run; g_cur[r] = run; run += g_cnt[r]; }
        g_off[NR] = run;
    }
}

// block-aggregated scatter: per-block smem ranks + one global atomic per relation.
__global__ void k_scatter(const int* __restrict__ et){
    __shared__ int lcnt[NR];
    __shared__ int lbase[NR];
    int tid = threadIdx.x;
    for (int i = tid; i < NR; i += 256) lcnt[i] = 0;
    __syncthreads();
    int e0 = blockIdx.x*EPB;
    int rel[EPB/256], lpos[EPB/256];
#pragma unroll
    for (int q = 0; q < EPB/256; q++){
        int e = e0 + q*256 + tid;
        if (e < EG){
            rel[q]  = et[e];
            lpos[q] = atomicAdd(&lcnt[rel[q]], 1);
        }
    }
    __syncthreads();
    for (int i = tid; i < NR; i += 256)
        if (lcnt[i]) lbase[i] = atomicAdd(&g_cur[i], lcnt[i]);
    __syncthreads();
#pragma unroll
    for (int q = 0; q < EPB/256; q++){
        int e = e0 + q*256 + tid;
        if (e < EG) g_ord[lbase[rel[q]] + lpos[q]] = e;
    }
}

// W[l,r] = sum_b coefs[l,r,b] * bases[b]
__global__ void k_relw(const float* __restrict__ bases, const float* __restrict__ coefs){
    int lr = blockIdx.x;
    float c[NB];
#pragma unroll
    for (int b = 0; b < NB; b++) c[b] = coefs[lr*NB + b];
    float* w = g_W + (size_t)lr*D*D;
    for (int i = threadIdx.x; i < D*D; i += blockDim.x){
        float a = 0.f;
#pragma unroll
        for (int b = 0; b < NB; b++) a += c[b]*bases[b*D*D + i];
        w[i] = a;
    }
}

// ---------------- dense self-GEMM: AGG = X @ self_w[l] + bias[l] ----------------
__global__ void __launch_bounds__(256,2) k_self(const float* __restrict__ x0,
        const float* __restrict__ selfw, const float* __restrict__ bias, int layer){
    __shared__ __align__(16) unsigned long long As2[128*17]; // A splatted pairs, pad 1
    __shared__ __align__(16) float Ws[16*D];

    const float* X = (layer == 0) ? x0 : g_X;
    const float* W = selfw + (size_t)layer*D*D;

    int tid  = threadIdx.x;
    int tn   = tid & 15, tm = tid >> 4;
    int half = tid & 1,  row = tid >> 1;
    int wk   = tid >> 4, wseg = tid & 15;

    int row0 = blockIdx.x*128;
    int gr   = min(row0 + row, NE-1);
    const float* xrow = X + (size_t)gr*D;

    unsigned long long acc[8][4];
#pragma unroll
    for (int i = 0; i < 8; i++)
#pragma unroll
        for (int j = 0; j < 4; j++) acc[i][j] = 0ull;

    for (int kc = 0; kc < 8; kc++){
#pragma unroll
        for (int q = 0; q < 2; q++){
            float4 v = *(const float4*)(xrow + kc*16 + half*8 + q*4);
            unsigned long long* dst = &As2[row*17 + half*8 + q*4];
            dst[0] = splat2(v.x); dst[1] = splat2(v.y);
            dst[2] = splat2(v.z); dst[3] = splat2(v.w);
        }
        {
            const float4* g = (const float4*)(W + (size_t)(kc*16 + wk)*D + wseg*8);
            float4 a = g[0], b = g[1];
            float4* sh = (float4*)(Ws + wk*D + wseg*8);
            sh[0] = a; sh[1] = b;
        }
        __syncthreads();
#pragma unroll
        for (int kk = 0; kk < 16; kk++){
            unsigned long long a[8];
#pragma unroll
            for (int i = 0; i < 8; i++) a[i] = As2[(tm*8+i)*17 + kk];
            double2 b0 = *(const double2*)(Ws + kk*D + tn*8);
            double2 b1 = *(const double2*)(Ws + kk*D + tn*8 + 4);
            unsigned long long b[4] = { __double_as_longlong(b0.x), __double_as_longlong(b0.y),
                                        __double_as_longlong(b1.x), __double_as_longlong(b1.y) };
#pragma unroll
            for (int i = 0; i < 8; i++)
#pragma unroll
                for (int j = 0; j < 4; j++) fma2(acc[i][j], a[i], b[j]);
        }
        __syncthreads();
    }

#pragma unroll
    for (int i = 0; i < 8; i++){
        int grow = row0 + tm*8 + i;
        if (grow < NE){
            float* out = g_AGG + (size_t)grow*D + tn*8;
#pragma unroll
            for (int j = 0; j < 4; j++){
                unsigned long long v = acc[i][j];
                float lo = __uint_as_float((unsigned)(v & 0xffffffffu));
                float hi = __uint_as_float((unsigned)(v >> 32));
                out[2*j]   = lo + bias[layer*D + tn*8 + 2*j];
                out[2*j+1] = hi + bias[layer*D + tn*8 + 2*j + 1];
            }
        }
    }
}

// ---------------- edge GEMM: AGG[tgt_e] += ew_e * (X[src_e] @ W[l,rel]) ----------------
__global__ void __launch_bounds__(256,2) k_edge(const float* __restrict__ x0,
        const int* __restrict__ src, const int* __restrict__ tgt, int layer){
    __shared__ __align__(16) unsigned long long As2[128*17];
    __shared__ __align__(16) float Ws[16*D];
    __shared__ int   s_src[128];
    __shared__ int   s_tgt[128];
    __shared__ float s_w[128];

    int r   = blockIdx.x;
    int s0  = g_off[r];
    int cnt = g_off[r+1] - s0;
    int t0  = blockIdx.y * 128;
    if (t0 >= cnt) return;                 // uniform across block (before any barrier)
    int valid = min(128, cnt - t0);

    const float* X = (layer == 0) ? x0 : g_X;
    int tid = threadIdx.x;
    if (tid < 128){
        int m = tid;
        int e = g_ord[s0 + t0 + min(m, valid-1)];
        s_src[m] = src[e];
        int t = tgt[e];
        s_tgt[m] = t;
        s_w[m]   = (m < valid) ? (1.f / fmaxf(g_indeg[t], 1.f)) : 0.f;
    }
    __syncthreads();

    const float* W = g_W + ((size_t)layer*NR + r)*D*D;
    int tn   = tid & 15, tm = tid >> 4;
    int half = tid & 1,  row = tid >> 1;
    int wk   = tid >> 4, wseg = tid & 15;
    const float* xrow = X + (size_t)s_src[row]*D;

    unsigned long long acc[8][4];
#pragma unroll
    for (int i = 0; i < 8; i++)
#pragma unroll
        for (int j = 0; j < 4; j++) acc[i][j] = 0ull;

    for (int kc = 0; kc < 8; kc++){
#pragma unroll
        for (int q = 0; q < 2; q++){
            float4 v = *(const float4*)(xrow + kc*16 + half*8 + q*4);
            unsigned long long* dst = &As2[row*17 + half*8 + q*4];
            dst[0] = splat2(v.x); dst[1] = splat2(v.y);
            dst[2] = splat2(v.z); dst[3] = splat2(v.w);
        }
        {
            const float4* g = (const float4*)(W + (size_t)(kc*16 + wk)*D + wseg*8);
            float4 a = g[0], b = g[1];
            float4* sh = (float4*)(Ws + wk*D + wseg*8);
            sh[0] = a; sh[1] = b;
        }
        __syncthreads();
#pragma unroll
        for (int kk = 0; kk < 16; kk++){
            unsigned long long a[8];
#pragma unroll
            for (int i = 0; i < 8; i++) a[i] = As2[(tm*8+i)*17 + kk];
            double2 b0 = *(const double2*)(Ws + kk*D + tn*8);
            double2 b1 = *(const double2*)(Ws + kk*D + tn*8 + 4);
            unsigned long long b[4] = { __double_as_longlong(b0.x), __double_as_longlong(b0.y),
                                        __double_as_longlong(b1.x), __double_as_longlong(b1.y) };
#pragma unroll
            for (int i = 0; i < 8; i++)
#pragma unroll
                for (int j = 0; j < 4; j++) fma2(acc[i][j], a[i], b[j]);
        }
        __syncthreads();
    }

#pragma unroll
    for (int i = 0; i < 8; i++){
        int m = tm*8 + i;
        if (m < valid){
            float w = s_w[m];
            float* out = g_AGG + (size_t)s_tgt[m]*D + tn*8;
            float v[8];
#pragma unroll
            for (int j = 0; j < 4; j++){
                unsigned long long u = acc[i][j];
                v[2*j]   = w * __uint_as_float((unsigned)(u & 0xffffffffu));
                v[2*j+1] = w * __uint_as_float((unsigned)(u >> 32));
            }
            red4(out,     v[0], v[1], v[2], v[3]);
            red4(out + 4, v[4], v[5], v[6], v[7]);
        }
    }
}

// ---------------- ReLU ----------------
__global__ void k_relu(float* __restrict__ dout, int layer){
    int i = blockIdx.x*blockDim.x + threadIdx.x;
    if (i < NE*D/4){
        float4 v = ((const float4*)g_AGG)[i];
        v.x = fmaxf(v.x, 0.f); v.y = fmaxf(v.y, 0.f);
        v.z = fmaxf(v.z, 0.f); v.w = fmaxf(v.w, 0.f);
        float4* o = (layer == 0) ? (float4*)g_X : (float4*)dout;
        o[i] = v;
    }
}

// ---------------- launch ----------------
extern "C" void kernel_launch(void* const* d_in, const int* in_sizes, int n_in,
                              void* d_out, int out_size){
    const float* x0    = (const float*)d_in[0];
    const float* bases = (const float*)d_in[1];
    const float* coefs = (const float*)d_in[2];
    const float* selfw = (const float*)d_in[3];
    const float* bias  = (const float*)d_in[4];
    const int*   source= (const int*)d_in[5];
    const int*   target= (const int*)d_in[6];
    const int*   etype = (const int*)d_in[7];
    float* out = (float*)d_out;

    k_init<<<(NE+255)/256, 256>>>();
    k_hist<<<(EG+EPB-1)/EPB, 256>>>(target, etype);
    k_scan<<<1, 32>>>();
    k_scatter<<<(EG+EPB-1)/EPB, 256>>>(etype);
    k_relw<<<NL*NR, 256>>>(bases, coefs);

    for (int l = 0; l < NL; l++){
        k_self<<<(NE+127)/128, 256>>>(x0, selfw, bias, l);
        k_edge<<<dim3(NR, MAXT), 256>>>(x0, source, target, l);
        k_relu<<<(NE*D/4+255)/256, 256>>>(out, l);
    }
}

// round 4
// speedup vs baseline: 2.1067x; 1.4826x over previous
#include <cuda_runtime.h>
#include <cuda_bf16.h>
#include <cstdint>

#define NE 100000
#define NR 100
#define D  128
#define NB 10
#define NL 2
#define EG 600000
#define EPB 2048
#define TJ 8            // y-grid: tiles of a relation strided across TJ blocks

// ---------------- scratch (device globals: no allocation allowed) ----------------
__device__ float g_AGG[(size_t)NE*D];      // pre-activation accumulator
__device__ float g_indeg[NE];
__device__ int   g_cnt[NR];
__device__ int   g_off[NR+1];
__device__ int   g_cur[NR];
__device__ int   g_ord[EG];                // edge ids grouped by relation
// bf16 split operands. W tiles stored pre-swizzled (row-major + XOR-16B), X row-major.
__device__ uint4 g_Wh4[(size_t)NL*NR*2048];   // 32KB per (l,r): Wt[n][k] bf16 hi
__device__ uint4 g_Wl4[(size_t)NL*NR*2048];   // lo
__device__ uint4 g_SWh4[(size_t)NL*2048];     // self_w transposed, split hi
__device__ uint4 g_SWl4[(size_t)NL*2048];     // lo
__device__ uint4 g_Xh4[(size_t)NE*16];        // row-major: 128 bf16 hi per row
__device__ uint4 g_Xl4[(size_t)NE*16];

// SMEM layout (dynamic, bytes)
#define SM_TGT 0
#define SM_WGT 512
#define SM_AH  2048
#define SM_AL  (SM_AH + 32768)
#define SM_BH  (SM_AL + 32768)
#define SM_BL  (SM_BH + 32768)
#define SM_TOT (SM_BL + 32768)

// ---------------- helpers ----------------
__device__ __forceinline__ void red4(float* p, float a, float b, float c, float d){
    asm volatile("red.global.add.v4.f32 [%0], {%1,%2,%3,%4};"
                 :: "l"(p), "f"(a), "f"(b), "f"(c), "f"(d) : "memory");
}
__device__ __forceinline__ void split8(const float* v, uint4& h, uint4& l){
    unsigned hh[4], ll[4];
#pragma unroll
    for (int q = 0; q < 4; q++){
        float x0 = v[2*q], x1 = v[2*q+1];
        __nv_bfloat16 h0 = __float2bfloat16(x0);
        __nv_bfloat16 h1 = __float2bfloat16(x1);
        float r0 = x0 - __bfloat162float(h0);
        float r1 = x1 - __bfloat162float(h1);
        __nv_bfloat162 hp; hp.x = h0; hp.y = h1;
        __nv_bfloat162 lp; lp.x = __float2bfloat16(r0); lp.y = __float2bfloat16(r1);
        hh[q] = *reinterpret_cast<unsigned*>(&hp);
        ll[q] = *reinterpret_cast<unsigned*>(&lp);
    }
    h = make_uint4(hh[0],hh[1],hh[2],hh[3]);
    l = make_uint4(ll[0],ll[1],ll[2],ll[3]);
}
__device__ __forceinline__ uint32_t smem_u32(const void* p){
    uint32_t a;
    asm("{ .reg .u64 t; cvta.to.shared.u64 t, %1; cvt.u32.u64 %0, t; }" : "=r"(a) : "l"(p));
    return a;
}
// row-major tile, 256B rows, 16B chunks XOR-swizzled by row
__device__ __forceinline__ uint32_t swa(uint32_t base, int r, int c){
    return base + r*256 + (((c ^ (r & 7)) & 15) << 4);
}
#define LDSM4(d0,d1,d2,d3,a) asm volatile( \
    "ldmatrix.sync.aligned.m8n8.x4.shared.b16 {%0,%1,%2,%3}, [%4];" \
    : "=r"(d0),"=r"(d1),"=r"(d2),"=r"(d3) : "r"(a))
#define LDSM2(d0,d1,a) asm volatile( \
    "ldmatrix.sync.aligned.m8n8.x2.shared.b16 {%0,%1}, [%2];" \
    : "=r"(d0),"=r"(d1) : "r"(a))
#define MMA16816(c,a0,a1,a2,a3,b0,b1) asm volatile( \
    "mma.sync.aligned.m16n8k16.row.col.f32.bf16.bf16.f32 " \
    "{%0,%1,%2,%3},{%4,%5,%6,%7},{%8,%9},{%0,%1,%2,%3};" \
    : "+f"((c)[0]),"+f"((c)[1]),"+f"((c)[2]),"+f"((c)[3]) \
    : "r"(a0),"r"(a1),"r"(a2),"r"(a3),"r"(b0),"r"(b1))

// shared 128x128x128 mainloop: acc += Ah*Bh + Ah*Bl + Al*Bh
__device__ __forceinline__ void mma_loop(uint32_t aH, uint32_t aL, uint32_t bH, uint32_t bL,
                                         int lane, int mw, int nw, float acc[2][8][4]){
    int ar = mw*32 + (lane & 15);
    int br = nw*64 + (lane & 7);
    for (int ks = 0; ks < 8; ks++){
        int ac = ks*2 + (lane >> 4);
        int bc = ks*2 + ((lane >> 3) & 1);
        uint32_t ah[2][4], al[2][4], bh[8][2], bl[8][2];
#pragma unroll
        for (int mi = 0; mi < 2; mi++){
            LDSM4(ah[mi][0],ah[mi][1],ah[mi][2],ah[mi][3], swa(aH, ar+mi*16, ac));
            LDSM4(al[mi][0],al[mi][1],al[mi][2],al[mi][3], swa(aL, ar+mi*16, ac));
        }
#pragma unroll
        for (int nf = 0; nf < 8; nf++){
            LDSM2(bh[nf][0],bh[nf][1], swa(bH, br+nf*8, bc));
            LDSM2(bl[nf][0],bl[nf][1], swa(bL, br+nf*8, bc));
        }
#pragma unroll
        for (int mi = 0; mi < 2; mi++)
#pragma unroll
        for (int nf = 0; nf < 8; nf++){
            MMA16816(acc[mi][nf], ah[mi][0],ah[mi][1],ah[mi][2],ah[mi][3], bh[nf][0],bh[nf][1]);
            MMA16816(acc[mi][nf], ah[mi][0],ah[mi][1],ah[mi][2],ah[mi][3], bl[nf][0],bl[nf][1]);
            MMA16816(acc[mi][nf], al[mi][0],al[mi][1],al[mi][2],al[mi][3], bh[nf][0],bh[nf][1]);
        }
    }
}

// ---------------- prep kernels ----------------
__global__ void k_init(){
    int i = blockIdx.x*blockDim.x + threadIdx.x;
    if (i < NE) g_indeg[i] = 0.f;
    if (i < NR) g_cnt[i] = 0;
}

__global__ void k_hist(const int* __restrict__ tgt, const int* __restrict__ et){
    __shared__ int lcnt[NR];
    int tid = threadIdx.x;
    for (int i = tid; i < NR; i += 256) lcnt[i] = 0;
    __syncthreads();
    int e0 = blockIdx.x*EPB;
#pragma unroll
    for (int q = 0; q < EPB/256; q++){
        int e = e0 + q*256 + tid;
        if (e < EG){
            atomicAdd(&g_indeg[tgt[e]], 1.f);
            atomicAdd(&lcnt[et[e]], 1);
        }
    }
    __syncthreads();
    for (int i = tid; i < NR; i += 256)
        if (lcnt[i]) atomicAdd(&g_cnt[i], lcnt[i]);
}

__global__ void k_scan(){
    if (threadIdx.x == 0){
        int run = 0;
        for (int r = 0; r < NR; r++){ g_off[r] = run; g_cur[r] = run; run += g_cnt[r]; }
        g_off[NR] = run;
    }
}

__global__ void k_scatter(const int* __restrict__ et){
    __shared__ int lcnt[NR];
    __shared__ int lbase[NR];
    int tid = threadIdx.x;
    for (int i = tid; i < NR; i += 256) lcnt[i] = 0;
    __syncthreads();
    int e0 = blockIdx.x*EPB;
    int rel[EPB/256], lpos[EPB/256];
#pragma unroll
    for (int q = 0; q < EPB/256; q++){
        int e = e0 + q*256 + tid;
        if (e < EG){
            rel[q]  = et[e];
            lpos[q] = atomicAdd(&lcnt[rel[q]], 1);
        }
    }
    __syncthreads();
    for (int i = tid; i < NR; i += 256)
        if (lcnt[i]) lbase[i] = atomicAdd(&g_cur[i], lcnt[i]);
    __syncthreads();
#pragma unroll
    for (int q = 0; q < EPB/256; q++){
        int e = e0 + q*256 + tid;
        if (e < EG) g_ord[lbase[rel[q]] + lpos[q]] = e;
    }
}

// Wt[l,r][n][k] = sum_b coefs[l,r,b]*bases[b][k][n], bf16 hi/lo, swizzled rows
__global__ void k_relw_bf(const float* __restrict__ bases, const float* __restrict__ coefs){
    int lr = blockIdx.x;
    float c[NB];
#pragma unroll
    for (int b = 0; b < NB; b++) c[b] = coefs[lr*NB + b];
    char* wh = (char*)g_Wh4 + (size_t)lr*32768;
    char* wl = (char*)g_Wl4 + (size_t)lr*32768;
    for (int ch = threadIdx.x; ch < 2048; ch += blockDim.x){
        int n  = ch & 127;
        int kc = ch >> 7;
        float v[8];
#pragma unroll
        for (int j = 0; j < 8; j++){
            int k = kc*8 + j;
            float a = 0.f;
#pragma unroll
            for (int b = 0; b < NB; b++) a += c[b]*bases[b*D*D + k*D + n];
            v[j] = a;
        }
        uint4 h, l; split8(v, h, l);
        int off = n*256 + (((kc ^ (n & 7)) & 15) << 4);
        *(uint4*)(wh + off) = h;
        *(uint4*)(wl + off) = l;
    }
}

// self_w transposed+split: SWt[l][n][k] = selfw[l][k][n]
__global__ void k_selfw_bf(const float* __restrict__ selfw){
    int l = blockIdx.x;
    char* wh = (char*)g_SWh4 + (size_t)l*32768;
    char* wl = (char*)g_SWl4 + (size_t)l*32768;
    for (int ch = threadIdx.x; ch < 2048; ch += blockDim.x){
        int n  = ch & 127;
        int kc = ch >> 7;
        float v[8];
#pragma unroll
        for (int j = 0; j < 8; j++)
            v[j] = selfw[(size_t)l*D*D + (kc*8 + j)*D + n];
        uint4 h, lo; split8(v, h, lo);
        int off = n*256 + (((kc ^ (n & 7)) & 15) << 4);
        *(uint4*)(wh + off) = h;
        *(uint4*)(wl + off) = lo;
    }
}

__global__ void k_xsplit(const float* __restrict__ x){
    int i = blockIdx.x*blockDim.x + threadIdx.x;
    if (i < NE*16){
        const float4* s = (const float4*)x + (size_t)i*2;
        float4 a = s[0], b = s[1];
        float v[8] = {a.x,a.y,a.z,a.w,b.x,b.y,b.z,b.w};
        uint4 h, l; split8(v, h, l);
        g_Xh4[i] = h; g_Xl4[i] = l;
    }
}

// ---------------- self GEMM: AGG = X @ self_w[l] + bias[l] (store) ----------------
__global__ void __launch_bounds__(256,1) k_self_mma(const float* __restrict__ bias, int layer){
    extern __shared__ __align__(16) char smem[];
    uint32_t sb = smem_u32(smem);
    int tid = threadIdx.x;
    int lane = tid & 31, wid = tid >> 5;
    int mw = wid & 3, nw = wid >> 2;
    int row0 = blockIdx.x*128;

    // B copy (pre-swizzled)
    {
        const uint4* wh = g_SWh4 + (size_t)layer*2048;
        const uint4* wl = g_SWl4 + (size_t)layer*2048;
        uint4* bh = (uint4*)(smem + SM_BH);
        uint4* bl = (uint4*)(smem + SM_BL);
        for (int i = tid; i < 2048; i += 256){ bh[i] = wh[i]; bl[i] = wl[i]; }
    }
    // A gather (consecutive rows, clamped)
    {
        int gr = tid >> 1, gh = tid & 1;
        int srow = min(row0 + gr, NE-1);
        const uint4* xh = g_Xh4 + (size_t)srow*16 + gh*8;
        const uint4* xl = g_Xl4 + (size_t)srow*16 + gh*8;
#pragma unroll
        for (int j = 0; j < 8; j++){
            int c = gh*8 + j;
            int off = gr*256 + (((c ^ (gr & 7)) & 15) << 4);
            *(uint4*)(smem + SM_AH + off) = xh[j];
            *(uint4*)(smem + SM_AL + off) = xl[j];
        }
    }
    __syncthreads();

    float acc[2][8][4];
#pragma unroll
    for (int mi = 0; mi < 2; mi++)
#pragma unroll
        for (int nf = 0; nf < 8; nf++)
#pragma unroll
            for (int q = 0; q < 4; q++) acc[mi][nf][q] = 0.f;

    mma_loop(sb+SM_AH, sb+SM_AL, sb+SM_BH, sb+SM_BL, lane, mw, nw, acc);

#pragma unroll
    for (int mi = 0; mi < 2; mi++){
        int r0 = row0 + mw*32 + mi*16 + (lane >> 2);
#pragma unroll
        for (int nf = 0; nf < 8; nf++){
            int col = nw*64 + nf*8 + (lane & 3)*2;
            float2 bs = *(const float2*)(bias + layer*D + col);
            if (r0 < NE){
                float2 v = { acc[mi][nf][0] + bs.x, acc[mi][nf][1] + bs.y };
                *(float2*)(g_AGG + (size_t)r0*D + col) = v;
            }
            if (r0 + 8 < NE){
                float2 v = { acc[mi][nf][2] + bs.x, acc[mi][nf][3] + bs.y };
                *(float2*)(g_AGG + (size_t)(r0+8)*D + col) = v;
            }
        }
    }
}

// ---------------- edge GEMM: AGG[tgt] += ew * (X[src] @ Wt[l,rel]^T) ----------------
__global__ void __launch_bounds__(256,1) k_edge_mma(const int* __restrict__ src,
        const int* __restrict__ tgt, int layer){
    int r   = blockIdx.x;
    int s0  = g_off[r];
    int cnt = g_off[r+1] - s0;
    int ntiles = (cnt + 127) >> 7;
    int j0  = blockIdx.y;
    if (j0 >= ntiles) return;   // uniform before any barrier

    extern __shared__ __align__(16) char smem[];
    uint32_t sb = smem_u32(smem);
    int tid = threadIdx.x;
    int lane = tid & 31, wid = tid >> 5;
    int mw = wid & 3, nw = wid >> 2;
    int* s_tgt = (int*)(smem + SM_TGT);
    float* s_wgt = (float*)(smem + SM_WGT);

    // B copy once per block (pre-swizzled)
    {
        const uint4* wh = g_Wh4 + ((size_t)layer*NR + r)*2048;
        const uint4* wl = g_Wl4 + ((size_t)layer*NR + r)*2048;
        uint4* bh = (uint4*)(smem + SM_BH);
        uint4* bl = (uint4*)(smem + SM_BL);
        for (int i = tid; i < 2048; i += 256){ bh[i] = wh[i]; bl[i] = wl[i]; }
    }

    int gr = tid >> 1, gh = tid & 1;
    for (int t = j0; t < ntiles; t += TJ){
        __syncthreads();   // prior iter's smem reads done (and first-iter B copy visible)
        int valid = min(128, cnt - t*128);
        int e = g_ord[s0 + t*128 + min(gr, valid-1)];
        int srow = src[e];
        const uint4* xh = g_Xh4 + (size_t)srow*16 + gh*8;
        const uint4* xl = g_Xl4 + (size_t)srow*16 + gh*8;
#pragma unroll
        for (int j = 0; j < 8; j++){
            int c = gh*8 + j;
            int off = gr*256 + (((c ^ (gr & 7)) & 15) << 4);
            *(uint4*)(smem + SM_AH + off) = xh[j];
            *(uint4*)(smem + SM_AL + off) = xl[j];
        }
        if (gh == 0){
            int tg = tgt[e];
            s_tgt[gr] = tg;
            s_wgt[gr] = (gr < valid) ? (1.f / fmaxf(g_indeg[tg], 1.f)) : 0.f;
        }
        __syncthreads();

        // preload this thread's target/weight rows into regs (frees smem for next iter)
        int tgr[2][2]; float wgr[2][2];
        int rb = mw*32 + (lane >> 2);
#pragma unroll
        for (int mi = 0; mi < 2; mi++)
#pragma unroll
            for (int h = 0; h < 2; h++){
                int rr = rb + mi*16 + h*8;
                tgr[mi][h] = s_tgt[rr];
                wgr[mi][h] = s_wgt[rr];
            }

        float acc[2][8][4];
#pragma unroll
        for (int mi = 0; mi < 2; mi++)
#pragma unroll
            for (int nf = 0; nf < 8; nf++)
#pragma unroll
                for (int q = 0; q < 4; q++) acc[mi][nf][q] = 0.f;

        mma_loop(sb+SM_AH, sb+SM_AL, sb+SM_BH, sb+SM_BL, lane, mw, nw, acc);

        // epilogue: shfl-pair lanes to form 16B, red.v4 scatter
#pragma unroll
        for (int mi = 0; mi < 2; mi++)
#pragma unroll
        for (int nf = 0; nf < 8; nf++){
            float c0 = acc[mi][nf][0], c1 = acc[mi][nf][1];
            float c2 = acc[mi][nf][2], c3 = acc[mi][nf][3];
            float o0 = __shfl_xor_sync(0xffffffffu, c0, 1);
            float o1 = __shfl_xor_sync(0xffffffffu, c1, 1);
            float o2 = __shfl_xor_sync(0xffffffffu, c2, 1);
            float o3 = __shfl_xor_sync(0xffffffffu, c3, 1);
            int colb = nw*64 + nf*8 + (lane & 2)*2;
            if (!(lane & 1)){
                float w = wgr[mi][0];
                if (w != 0.f)
                    red4(g_AGG + (size_t)tgr[mi][0]*D + colb, w*c0, w*c1, w*o0, w*o1);
            } else {
                float w = wgr[mi][1];
                if (w != 0.f)
                    red4(g_AGG + (size_t)tgr[mi][1]*D + colb, w*o2, w*o3, w*c2, w*c3);
            }
        }
    }
}

// ---------------- ReLU (+ bf16 re-split for layer-0 output) ----------------
__global__ void k_relu(float* __restrict__ dout, int layer){
    int i = blockIdx.x*blockDim.x + threadIdx.x;
    if (i < NE*16){
        const float4* s = (const float4*)g_AGG + (size_t)i*2;
        float4 a = s[0], b = s[1];
        a.x = fmaxf(a.x,0.f); a.y = fmaxf(a.y,0.f); a.z = fmaxf(a.z,0.f); a.w = fmaxf(a.w,0.f);
        b.x = fmaxf(b.x,0.f); b.y = fmaxf(b.y,0.f); b.z = fmaxf(b.z,0.f); b.w = fmaxf(b.w,0.f);
        if (layer == 0){
            float v[8] = {a.x,a.y,a.z,a.w,b.x,b.y,b.z,b.w};
            uint4 h, l; split8(v, h, l);
            g_Xh4[i] = h; g_Xl4[i] = l;
        } else {
            float4* o = (float4*)dout + (size_t)i*2;
            o[0] = a; o[1] = b;
        }
    }
}

// ---------------- launch ----------------
extern "C" void kernel_launch(void* const* d_in, const int* in_sizes, int n_in,
                              void* d_out, int out_size){
    const float* x0    = (const float*)d_in[0];
    const float* bases = (const float*)d_in[1];
    const float* coefs = (const float*)d_in[2];
    const float* selfw = (const float*)d_in[3];
    const float* bias  = (const float*)d_in[4];
    const int*   source= (const int*)d_in[5];
    const int*   target= (const int*)d_in[6];
    const int*   etype = (const int*)d_in[7];
    float* out = (float*)d_out;

    static int inited = 0;
    if (!inited){
        cudaFuncSetAttribute(k_edge_mma, cudaFuncAttributeMaxDynamicSharedMemorySize, SM_TOT);
        cudaFuncSetAttribute(k_self_mma, cudaFuncAttributeMaxDynamicSharedMemorySize, SM_TOT);
        inited = 1;
    }

    k_init<<<(NE+255)/256, 256>>>();
    k_hist<<<(EG+EPB-1)/EPB, 256>>>(target, etype);
    k_scan<<<1, 32>>>();
    k_scatter<<<(EG+EPB-1)/EPB, 256>>>(etype);
    k_relw_bf<<<NL*NR, 256>>>(bases, coefs);
    k_selfw_bf<<<NL, 256>>>(selfw);
    k_xsplit<<<(NE*16+255)/256, 256>>>(x0);

    for (int l = 0; l < NL; l++){
        k_self_mma<<<(NE+127)/128, 256, SM_TOT>>>(bias, l);
        k_edge_mma<<<dim3(NR, TJ), 256, SM_TOT>>>(source, target, l);
        k_relu<<<(NE*16+255)/256, 256>>>(out, l);
    }
}

// round 5
// speedup vs baseline: 2.3561x; 1.1184x over previous
#include <cuda_runtime.h>
#include <cuda_bf16.h>
#include <cstdint>

#define NE 100000
#define NR 100
#define D  128
#define NB 10
#define NL 2
#define EG 600000
#define EPB 2048
#define TJ 8            // y-grid: tiles of a relation strided across TJ blocks
#define SB_GRID 196     // persistent blocks for self-GEMM (782 tiles)

// ---------------- scratch (device globals: no allocation allowed) ----------------
__device__ float g_AGG[(size_t)NE*D];      // pre-activation accumulator
__device__ float g_indeg[NE];
__device__ int   g_cnt[NR];
__device__ int   g_off[NR+1];
__device__ int   g_cur[NR];
__device__ int   g_ord[EG];                // edge ids grouped by relation
// bf16 split operands. W tiles stored pre-swizzled (row-major + XOR-16B), X row-major.
__device__ uint4 g_Wh4[(size_t)NL*NR*2048];   // 32KB per (l,r): Wt[n][k] bf16 hi
__device__ uint4 g_Wl4[(size_t)NL*NR*2048];   // lo
__device__ uint4 g_SWh4[(size_t)NL*2048];     // self_w transposed, split hi
__device__ uint4 g_SWl4[(size_t)NL*2048];     // lo
__device__ uint4 g_Xh4[(size_t)NE*16];        // row-major: 128 bf16 hi per row
__device__ uint4 g_Xl4[(size_t)NE*16];

// SMEM layout (dynamic, bytes): 2 idx bufs, 2 A bufs (hi+lo), B hi+lo
#define SM_IDX(b) ((b)*1024)               // tgt 512B + wgt 512B per buffer
#define SM_AH0 2048
#define SM_AL0 (SM_AH0 + 32768)
#define SM_AH1 (SM_AL0 + 32768)
#define SM_AL1 (SM_AH1 + 32768)
#define SM_BH  (SM_AL1 + 32768)
#define SM_BL  (SM_BH + 32768)
#define SM_TOT (SM_BL + 32768)             // 198656 B

// ---------------- helpers ----------------
__device__ __forceinline__ void red4(float* p, float a, float b, float c, float d){
    asm volatile("red.global.add.v4.f32 [%0], {%1,%2,%3,%4};"
                 :: "l"(p), "f"(a), "f"(b), "f"(c), "f"(d) : "memory");
}
__device__ __forceinline__ void cpa16(uint32_t dst, const void* src){
    asm volatile("cp.async.cg.shared.global [%0], [%1], 16;" :: "r"(dst), "l"(src) : "memory");
}
#define CP_COMMIT() asm volatile("cp.async.commit_group;" ::: "memory")
#define CP_WAIT1()  asm volatile("cp.async.wait_group 1;" ::: "memory")

__device__ __forceinline__ void split8(const float* v, uint4& h, uint4& l){
    unsigned hh[4], ll[4];
#pragma unroll
    for (int q = 0; q < 4; q++){
        float x0 = v[2*q], x1 = v[2*q+1];
        __nv_bfloat16 h0 = __float2bfloat16(x0);
        __nv_bfloat16 h1 = __float2bfloat16(x1);
        float r0 = x0 - __bfloat162float(h0);
        float r1 = x1 - __bfloat162float(h1);
        __nv_bfloat162 hp; hp.x = h0; hp.y = h1;
        __nv_bfloat162 lp; lp.x = __float2bfloat16(r0); lp.y = __float2bfloat16(r1);
        hh[q] = *reinterpret_cast<unsigned*>(&hp);
        ll[q] = *reinterpret_cast<unsigned*>(&lp);
    }
    h = make_uint4(hh[0],hh[1],hh[2],hh[3]);
    l = make_uint4(ll[0],ll[1],ll[2],ll[3]);
}
__device__ __forceinline__ uint32_t smem_u32(const void* p){
    uint32_t a;
    asm("{ .reg .u64 t; cvta.to.shared.u64 t, %1; cvt.u32.u64 %0, t; }" : "=r"(a) : "l"(p));
    return a;
}
// row-major tile, 256B rows, 16B chunks XOR-swizzled by row
__device__ __forceinline__ uint32_t swa(uint32_t base, int r, int c){
    return base + r*256 + (((c ^ (r & 7)) & 15) << 4);
}
#define LDSM4(d0,d1,d2,d3,a) asm volatile( \
    "ldmatrix.sync.aligned.m8n8.x4.shared.b16 {%0,%1,%2,%3}, [%4];" \
    : "=r"(d0),"=r"(d1),"=r"(d2),"=r"(d3) : "r"(a))
#define MMA16816(c,a0,a1,a2,a3,b0,b1) asm volatile( \
    "mma.sync.aligned.m16n8k16.row.col.f32.bf16.bf16.f32 " \
    "{%0,%1,%2,%3},{%4,%5,%6,%7},{%8,%9},{%0,%1,%2,%3};" \
    : "+f"((c)[0]),"+f"((c)[1]),"+f"((c)[2]),"+f"((c)[3]) \
    : "r"(a0),"r"(a1),"r"(a2),"r"(a3),"r"(b0),"r"(b1))

// shared 128x128x128 mainloop: acc += Ah*Bh + Ah*Bl + Al*Bh
__device__ __forceinline__ void mma_loop(uint32_t aH, uint32_t aL, uint32_t bH, uint32_t bL,
                                         int lane, int mw, int nw, float acc[2][8][4]){
    int ar = mw*32 + (lane & 15);
    int ac_sel = lane >> 4;
    int br = nw*64 + ((lane >> 4) & 1)*8 + (lane & 7);
    int bc_sel = (lane >> 3) & 1;
    for (int ks = 0; ks < 8; ks++){
        int ac = ks*2 + ac_sel;
        int bc = ks*2 + bc_sel;
        uint32_t ah[2][4], al[2][4], bh[8][2], bl[8][2];
#pragma unroll
        for (int mi = 0; mi < 2; mi++){
            LDSM4(ah[mi][0],ah[mi][1],ah[mi][2],ah[mi][3], swa(aH, ar+mi*16, ac));
            LDSM4(al[mi][0],al[mi][1],al[mi][2],al[mi][3], swa(aL, ar+mi*16, ac));
        }
#pragma unroll
        for (int p = 0; p < 4; p++){
            LDSM4(bh[2*p][0],bh[2*p][1],bh[2*p+1][0],bh[2*p+1][1], swa(bH, br+p*16, bc));
            LDSM4(bl[2*p][0],bl[2*p][1],bl[2*p+1][0],bl[2*p+1][1], swa(bL, br+p*16, bc));
        }
#pragma unroll
        for (int mi = 0; mi < 2; mi++)
#pragma unroll
        for (int nf = 0; nf < 8; nf++){
            MMA16816(acc[mi][nf], ah[mi][0],ah[mi][1],ah[mi][2],ah[mi][3], bh[nf][0],bh[nf][1]);
            MMA16816(acc[mi][nf], ah[mi][0],ah[mi][1],ah[mi][2],ah[mi][3], bl[nf][0],bl[nf][1]);
            MMA16816(acc[mi][nf], al[mi][0],al[mi][1],al[mi][2],al[mi][3], bh[nf][0],bh[nf][1]);
        }
    }
}

// ---------------- prep kernels ----------------
__global__ void k_init(){
    int i = blockIdx.x*blockDim.x + threadIdx.x;
    if (i < NE) g_indeg[i] = 0.f;
    if (i < NR) g_cnt[i] = 0;
}

__global__ void k_hist(const int* __restrict__ tgt, const int* __restrict__ et){
    __shared__ int lcnt[NR];
    int tid = threadIdx.x;
    for (int i = tid; i < NR; i += 256) lcnt[i] = 0;
    __syncthreads();
    int e0 = blockIdx.x*EPB;
#pragma unroll
    for (int q = 0; q < EPB/256; q++){
        int e = e0 + q*256 + tid;
        if (e < EG){
            atomicAdd(&g_indeg[tgt[e]], 1.f);
            atomicAdd(&lcnt[et[e]], 1);
        }
    }
    __syncthreads();
    for (int i = tid; i < NR; i += 256)
        if (lcnt[i]) atomicAdd(&g_cnt[i], lcnt[i]);
}

__global__ void k_scan(){
    if (threadIdx.x == 0){
        int run = 0;
        for (int r = 0; r < NR; r++){ g_off[r] = run; g_cur[r] = run; run += g_cnt[r]; }
        g_off[NR] = run;
    }
}

__global__ void k_scatter(const int* __restrict__ et){
    __shared__ int lcnt[NR];
    __shared__ int lbase[NR];
    int tid = threadIdx.x;
    for (int i = tid; i < NR; i += 256) lcnt[i] = 0;
    __syncthreads();
    int e0 = blockIdx.x*EPB;
    int rel[EPB/256], lpos[EPB/256];
#pragma unroll
    for (int q = 0; q < EPB/256; q++){
        int e = e0 + q*256 + tid;
        if (e < EG){
            rel[q]  = et[e];
            lpos[q] = atomicAdd(&lcnt[rel[q]], 1);
        }
    }
    __syncthreads();
    for (int i = tid; i < NR; i += 256)
        if (lcnt[i]) lbase[i] = atomicAdd(&g_cur[i], lcnt[i]);
    __syncthreads();
#pragma unroll
    for (int q = 0; q < EPB/256; q++){
        int e = e0 + q*256 + tid;
        if (e < EG) g_ord[lbase[rel[q]] + lpos[q]] = e;
    }
}

// Wt[l,r][n][k] = sum_b coefs[l,r,b]*bases[b][k][n], bf16 hi/lo, swizzled rows
__global__ void k_relw_bf(const float* __restrict__ bases, const float* __restrict__ coefs){
    int lr = blockIdx.x;
    float c[NB];
#pragma unroll
    for (int b = 0; b < NB; b++) c[b] = coefs[lr*NB + b];
    char* wh = (char*)g_Wh4 + (size_t)lr*32768;
    char* wl = (char*)g_Wl4 + (size_t)lr*32768;
    for (int ch = threadIdx.x; ch < 2048; ch += blockDim.x){
        int n  = ch & 127;
        int kc = ch >> 7;
        float v[8];
#pragma unroll
        for (int j = 0; j < 8; j++){
            int k = kc*8 + j;
            float a = 0.f;
#pragma unroll
            for (int b = 0; b < NB; b++) a += c[b]*bases[b*D*D + k*D + n];
            v[j] = a;
        }
        uint4 h, l; split8(v, h, l);
        int off = n*256 + (((kc ^ (n & 7)) & 15) << 4);
        *(uint4*)(wh + off) = h;
        *(uint4*)(wl + off) = l;
    }
}

// self_w transposed+split: SWt[l][n][k] = selfw[l][k][n]
__global__ void k_selfw_bf(const float* __restrict__ selfw){
    int l = blockIdx.x;
    char* wh = (char*)g_SWh4 + (size_t)l*32768;
    char* wl = (char*)g_SWl4 + (size_t)l*32768;
    for (int ch = threadIdx.x; ch < 2048; ch += blockDim.x){
        int n  = ch & 127;
        int kc = ch >> 7;
        float v[8];
#pragma unroll
        for (int j = 0; j < 8; j++)
            v[j] = selfw[(size_t)l*D*D + (kc*8 + j)*D + n];
        uint4 h, lo; split8(v, h, lo);
        int off = n*256 + (((kc ^ (n & 7)) & 15) << 4);
        *(uint4*)(wh + off) = h;
        *(uint4*)(wl + off) = lo;
    }
}

__global__ void k_xsplit(const float* __restrict__ x){
    int i = blockIdx.x*blockDim.x + threadIdx.x;
    if (i < NE*16){
        const float4* s = (const float4*)x + (size_t)i*2;
        float4 a = s[0], b = s[1];
        float v[8] = {a.x,a.y,a.z,a.w,b.x,b.y,b.z,b.w};
        uint4 h, l; split8(v, h, l);
        g_Xh4[i] = h; g_Xl4[i] = l;
    }
}

// ---------------- self GEMM: AGG = X @ self_w[l] + bias[l] (persistent, pipelined) ----------------
__global__ void __launch_bounds__(256,1) k_self_mma(const float* __restrict__ bias, int layer){
    const int ntiles = (NE + 127) >> 7;
    int t0 = blockIdx.x;
    if (t0 >= ntiles) return;

    extern __shared__ __align__(16) char smem[];
    uint32_t sb = smem_u32(smem);
    int tid = threadIdx.x, lane = tid & 31, wid = tid >> 5;
    int mw = wid & 3, nw = wid >> 2;
    int gr = tid >> 1, gh = tid & 1;

    // B copy (pre-swizzled)
    {
        const uint4* wh = g_SWh4 + (size_t)layer*2048;
        const uint4* wl = g_SWl4 + (size_t)layer*2048;
        uint4* bh = (uint4*)(smem + SM_BH);
        uint4* bl = (uint4*)(smem + SM_BL);
        for (int i = tid; i < 2048; i += 256){ bh[i] = wh[i]; bl[i] = wl[i]; }
    }
    // bias preload (per-thread columns)
    float2 bs[8];
#pragma unroll
    for (int nf = 0; nf < 8; nf++)
        bs[nf] = *(const float2*)(bias + layer*D + nw*64 + nf*8 + (lane & 3)*2);

    auto pf = [&](int t, int b){
        int srow = min(t*128 + gr, NE-1);
        const uint4* xh = g_Xh4 + (size_t)srow*16 + gh*8;
        const uint4* xl = g_Xl4 + (size_t)srow*16 + gh*8;
        uint32_t abh = sb + (b ? SM_AH1 : SM_AH0);
        uint32_t abl = sb + (b ? SM_AL1 : SM_AL0);
#pragma unroll
        for (int j = 0; j < 8; j++){
            int c = gh*8 + j;
            uint32_t off = (uint32_t)(gr*256 + (((c ^ (gr & 7)) & 15) << 4));
            cpa16(abh + off, xh + j);
            cpa16(abl + off, xl + j);
        }
    };

    pf(t0, 0);
    CP_COMMIT();

    int buf = 0;
    for (int t = t0; t < ntiles; t += gridDim.x){
        if (t + (int)gridDim.x < ntiles) pf(t + gridDim.x, buf^1);
        CP_COMMIT();
        CP_WAIT1();
        __syncthreads();

        float acc[2][8][4];
#pragma unroll
        for (int mi = 0; mi < 2; mi++)
#pragma unroll
            for (int nf = 0; nf < 8; nf++)
#pragma unroll
                for (int q = 0; q < 4; q++) acc[mi][nf][q] = 0.f;

        mma_loop(sb + (buf ? SM_AH1 : SM_AH0), sb + (buf ? SM_AL1 : SM_AL0),
                 sb + SM_BH, sb + SM_BL, lane, mw, nw, acc);

#pragma unroll
        for (int mi = 0; mi < 2; mi++){
            int r0 = t*128 + mw*32 + mi*16 + (lane >> 2);
#pragma unroll
            for (int nf = 0; nf < 8; nf++){
                int col = nw*64 + nf*8 + (lane & 3)*2;
                if (r0 < NE){
                    float2 v = { acc[mi][nf][0] + bs[nf].x, acc[mi][nf][1] + bs[nf].y };
                    *(float2*)(g_AGG + (size_t)r0*D + col) = v;
                }
                if (r0 + 8 < NE){
                    float2 v = { acc[mi][nf][2] + bs[nf].x, acc[mi][nf][3] + bs[nf].y };
                    *(float2*)(g_AGG + (size_t)(r0+8)*D + col) = v;
                }
            }
        }
        __syncthreads();
        buf ^= 1;
    }
}

// ---------------- edge GEMM: AGG[tgt] += ew * (X[src] @ Wt[l,rel]^T), pipelined ----------------
__global__ void __launch_bounds__(256,1) k_edge_mma(const int* __restrict__ src,
        const int* __restrict__ tgt, int layer){
    int r   = blockIdx.x;
    int s0  = g_off[r];
    int cnt = g_off[r+1] - s0;
    int ntiles = (cnt + 127) >> 7;
    int j0  = blockIdx.y;
    if (j0 >= ntiles) return;   // uniform before any barrier

    extern __shared__ __align__(16) char smem[];
    uint32_t sb = smem_u32(smem);
    int tid = threadIdx.x, lane = tid & 31, wid = tid >> 5;
    int mw = wid & 3, nw = wid >> 2;
    int gr = tid >> 1, gh = tid & 1;

    // B copy once per block (pre-swizzled)
    {
        const uint4* wh = g_Wh4 + ((size_t)layer*NR + r)*2048;
        const uint4* wl = g_Wl4 + ((size_t)layer*NR + r)*2048;
        uint4* bh = (uint4*)(smem + SM_BH);
        uint4* bl = (uint4*)(smem + SM_BL);
        for (int i = tid; i < 2048; i += 256){ bh[i] = wh[i]; bl[i] = wl[i]; }
    }

    auto idx_load = [&](int t, int& srow, int& tg, float& w){
        int valid = min(128, cnt - t*128);
        int e = g_ord[s0 + t*128 + min(gr, valid-1)];
        srow = src[e];
        tg = tgt[e];
        w = (gr < valid) ? (1.f / fmaxf(g_indeg[tg], 1.f)) : 0.f;
    };
    auto pf_data = [&](int srow, int tg, float w, int b){
        const uint4* xh = g_Xh4 + (size_t)srow*16 + gh*8;
        const uint4* xl = g_Xl4 + (size_t)srow*16 + gh*8;
        uint32_t abh = sb + (b ? SM_AH1 : SM_AH0);
        uint32_t abl = sb + (b ? SM_AL1 : SM_AL0);
#pragma unroll
        for (int j = 0; j < 8; j++){
            int c = gh*8 + j;
            uint32_t off = (uint32_t)(gr*256 + (((c ^ (gr & 7)) & 15) << 4));
            cpa16(abh + off, xh + j);
            cpa16(abl + off, xl + j);
        }
        if (gh == 0){
            ((int*)(smem + SM_IDX(b)))[gr] = tg;
            ((float*)(smem + SM_IDX(b) + 512))[gr] = w;
        }
    };

    int srow, tg; float w;
    idx_load(j0, srow, tg, w);
    pf_data(srow, tg, w, 0);
    CP_COMMIT();
    int srowN = 0, tgN = 0; float wN = 0.f;
    if (j0 + TJ < ntiles) idx_load(j0 + TJ, srowN, tgN, wN);

    int buf = 0;
    for (int t = j0; t < ntiles; t += TJ){
        if (t + TJ < ntiles) pf_data(srowN, tgN, wN, buf^1);
        CP_COMMIT();
        if (t + 2*TJ < ntiles) idx_load(t + 2*TJ, srowN, tgN, wN);
        CP_WAIT1();
        __syncthreads();

        // preload epilogue targets/weights for this buffer
        int* s_tgt = (int*)(smem + SM_IDX(buf));
        float* s_wgt = (float*)(smem + SM_IDX(buf) + 512);
        int tgr[2][2]; float wgr[2][2];
        int rb = mw*32 + (lane >> 2);
#pragma unroll
        for (int mi = 0; mi < 2; mi++)
#pragma unroll
            for (int h = 0; h < 2; h++){
                int rr = rb + mi*16 + h*8;
                tgr[mi][h] = s_tgt[rr];
                wgr[mi][h] = s_wgt[rr];
            }

        float acc[2][8][4];
#pragma unroll
        for (int mi = 0; mi < 2; mi++)
#pragma unroll
            for (int nf = 0; nf < 8; nf++)
#pragma unroll
                for (int q = 0; q < 4; q++) acc[mi][nf][q] = 0.f;

        mma_loop(sb + (buf ? SM_AH1 : SM_AH0), sb + (buf ? SM_AL1 : SM_AL0),
                 sb + SM_BH, sb + SM_BL, lane, mw, nw, acc);

        // epilogue: shfl-pair lanes to form 16B, red.v4 scatter
#pragma unroll
        for (int mi = 0; mi < 2; mi++)
#pragma unroll
        for (int nf = 0; nf < 8; nf++){
            float c0 = acc[mi][nf][0], c1 = acc[mi][nf][1];
            float c2 = acc[mi][nf][2], c3 = acc[mi][nf][3];
            float o0 = __shfl_xor_sync(0xffffffffu, c0, 1);
            float o1 = __shfl_xor_sync(0xffffffffu, c1, 1);
            float o2 = __shfl_xor_sync(0xffffffffu, c2, 1);
            float o3 = __shfl_xor_sync(0xffffffffu, c3, 1);
            int colb = nw*64 + nf*8 + (lane & 2)*2;
            if (!(lane & 1)){
                float ww = wgr[mi][0];
                if (ww != 0.f)
                    red4(g_AGG + (size_t)tgr[mi][0]*D + colb, ww*c0, ww*c1, ww*o0, ww*o1);
            } else {
                float ww = wgr[mi][1];
                if (ww != 0.f)
                    red4(g_AGG + (size_t)tgr[mi][1]*D + colb, ww*o2, ww*o3, ww*c2, ww*c3);
            }
        }
        __syncthreads();
        buf ^= 1;
    }
}

// ---------------- ReLU (+ bf16 re-split for layer-0 output) ----------------
__global__ void k_relu(float* __restrict__ dout, int layer){
    int i = blockIdx.x*blockDim.x + threadIdx.x;
    if (i < NE*16){
        const float4* s = (const float4*)g_AGG + (size_t)i*2;
        float4 a = s[0], b = s[1];
        a.x = fmaxf(a.x,0.f); a.y = fmaxf(a.y,0.f); a.z = fmaxf(a.z,0.f); a.w = fmaxf(a.w,0.f);
        b.x = fmaxf(b.x,0.f); b.y = fmaxf(b.y,0.f); b.z = fmaxf(b.z,0.f); b.w = fmaxf(b.w,0.f);
        if (layer == 0){
            float v[8] = {a.x,a.y,a.z,a.w,b.x,b.y,b.z,b.w};
            uint4 h, l; split8(v, h, l);
            g_Xh4[i] = h; g_Xl4[i] = l;
        } else {
            float4* o = (float4*)dout + (size_t)i*2;
            o[0] = a; o[1] = b;
        }
    }
}

// ---------------- launch ----------------
extern "C" void kernel_launch(void* const* d_in, const int* in_sizes, int n_in,
                              void* d_out, int out_size){
    const float* x0    = (const float*)d_in[0];
    const float* bases = (const float*)d_in[1];
    const float* coefs = (const float*)d_in[2];
    const float* selfw = (const float*)d_in[3];
    const float* bias  = (const float*)d_in[4];
    const int*   source= (const int*)d_in[5];
    const int*   target= (const int*)d_in[6];
    const int*   etype = (const int*)d_in[7];
    float* out = (float*)d_out;

    static int inited = 0;
    if (!inited){
        cudaFuncSetAttribute(k_edge_mma, cudaFuncAttributeMaxDynamicSharedMemorySize, SM_TOT);
        cudaFuncSetAttribute(k_self_mma, cudaFuncAttributeMaxDynamicSharedMemorySize, SM_TOT);
        inited = 1;
    }

    k_init<<<(NE+255)/256, 256>>>();
    k_hist<<<(EG+EPB-1)/EPB, 256>>>(target, etype);
    k_scan<<<1, 32>>>();
    k_scatter<<<(EG+EPB-1)/EPB, 256>>>(etype);
    k_relw_bf<<<NL*NR, 256>>>(bases, coefs);
    k_selfw_bf<<<NL, 256>>>(selfw);
    k_xsplit<<<(NE*16+255)/256, 256>>>(x0);

    for (int l = 0; l < NL; l++){
        k_self_mma<<<SB_GRID, 256, SM_TOT>>>(bias, l);
        k_edge_mma<<<dim3(NR, TJ), 256, SM_TOT>>>(source, target, l);
        k_relu<<<(NE*16+255)/256, 256>>>(out, l);
    }
}

// round 6
// speedup vs baseline: 3.7568x; 1.5945x over previous
#include <cuda_runtime.h>
#include <cuda_fp16.h>
#include <cstdint>

#define NE 100000
#define NR 100
#define D  128
#define NB 10
#define NL 2
#define EG 600000
#define EPB 2048
#define TJ 8            // y-grid: tiles of a relation strided across TJ blocks
#define SB_GRID 296     // persistent blocks for self-GEMM (782 tiles, occ 2)

// ---------------- scratch (device globals: no allocation allowed) ----------------
__device__ float g_AGG[(size_t)NE*D];      // pre-activation accumulator
__device__ float g_indeg[NE];
__device__ int   g_cnt[NR];
__device__ int   g_off[NR+1];
__device__ int   g_cur[NR];
__device__ int   g_ord[EG];                // edge ids grouped by relation
// fp16 operands. W tiles stored pre-swizzled (row-major + XOR-16B) hi/lo; X single fp16.
__device__ uint4 g_Wh4[(size_t)NL*NR*2048];   // 32KB per (l,r): Wt[n][k] fp16 hi
__device__ uint4 g_Wl4[(size_t)NL*NR*2048];   // fp16 lo (residual)
__device__ uint4 g_SWh4[(size_t)NL*2048];     // self_w transposed hi
__device__ uint4 g_SWl4[(size_t)NL*2048];     // lo
__device__ uint4 g_Xh4[(size_t)NE*16];        // row-major: 128 fp16 per row (256B)

// SMEM layout (dynamic, bytes): idx, 1 A buf, B hi+lo  -> 100352 B (occ 2)
#define SM_TGT 0
#define SM_WGT 512
#define SM_A   2048
#define SM_BH  (SM_A + 32768)
#define SM_BL  (SM_BH + 32768)
#define SM_TOT (SM_BL + 32768)

// ---------------- helpers ----------------
__device__ __forceinline__ void red4(float* p, float a, float b, float c, float d){
    asm volatile("red.global.add.v4.f32 [%0], {%1,%2,%3,%4};"
                 :: "l"(p), "f"(a), "f"(b), "f"(c), "f"(d) : "memory");
}
__device__ __forceinline__ void cpa16(uint32_t dst, const void* src){
    asm volatile("cp.async.cg.shared.global [%0], [%1], 16;" :: "r"(dst), "l"(src) : "memory");
}
#define CP_COMMIT() asm volatile("cp.async.commit_group;" ::: "memory")
#define CP_WAIT0()  asm volatile("cp.async.wait_group 0;" ::: "memory")

__device__ __forceinline__ uint4 pack8h(const float* v){
    unsigned u[4];
#pragma unroll
    for (int q = 0; q < 4; q++){
        __half2 h = __floats2half2_rn(v[2*q], v[2*q+1]);
        u[q] = *reinterpret_cast<unsigned*>(&h);
    }
    return make_uint4(u[0],u[1],u[2],u[3]);
}
__device__ __forceinline__ void splitW8(const float* v, uint4& h, uint4& l){
    unsigned hh[4], ll[4];
#pragma unroll
    for (int q = 0; q < 4; q++){
        float x0 = v[2*q], x1 = v[2*q+1];
        __half h0 = __float2half_rn(x0), h1 = __float2half_rn(x1);
        float r0 = x0 - __half2float(h0), r1 = x1 - __half2float(h1);
        __half2 hp = __halves2half2(h0, h1);
        __half2 lp = __floats2half2_rn(r0, r1);
        hh[q] = *reinterpret_cast<unsigned*>(&hp);
        ll[q] = *reinterpret_cast<unsigned*>(&lp);
    }
    h = make_uint4(hh[0],hh[1],hh[2],hh[3]);
    l = make_uint4(ll[0],ll[1],ll[2],ll[3]);
}
__device__ __forceinline__ uint32_t smem_u32(const void* p){
    uint32_t a;
    asm("{ .reg .u64 t; cvta.to.shared.u64 t, %1; cvt.u32.u64 %0, t; }" : "=r"(a) : "l"(p));
    return a;
}
// row-major tile, 256B rows, 16B chunks XOR-swizzled by row
__device__ __forceinline__ uint32_t swa(uint32_t base, int r, int c){
    return base + r*256 + (((c ^ (r & 7)) & 15) << 4);
}
#define LDSM4(d0,d1,d2,d3,a) asm volatile( \
    "ldmatrix.sync.aligned.m8n8.x4.shared.b16 {%0,%1,%2,%3}, [%4];" \
    : "=r"(d0),"=r"(d1),"=r"(d2),"=r"(d3) : "r"(a))
#define MMA16816(c,a0,a1,a2,a3,b0,b1) asm volatile( \
    "mma.sync.aligned.m16n8k16.row.col.f32.f16.f16.f32 " \
    "{%0,%1,%2,%3},{%4,%5,%6,%7},{%8,%9},{%0,%1,%2,%3};" \
    : "+f"((c)[0]),"+f"((c)[1]),"+f"((c)[2]),"+f"((c)[3]) \
    : "r"(a0),"r"(a1),"r"(a2),"r"(a3),"r"(b0),"r"(b1))

// 128x128x128 mainloop: acc += A*Bh + A*Bl   (A fp16 single, B fp16 split)
__device__ __forceinline__ void mma_loop(uint32_t aT, uint32_t bH, uint32_t bL,
                                         int lane, int mw, int nw, float acc[2][8][4]){
    int ar = mw*32 + (lane & 15);
    int ac_sel = lane >> 4;
    int br = nw*64 + ((lane >> 4) & 1)*8 + (lane & 7);
    int bc_sel = (lane >> 3) & 1;
    for (int ks = 0; ks < 8; ks++){
        int ac = ks*2 + ac_sel;
        int bc = ks*2 + bc_sel;
        uint32_t a[2][4], bh[8][2], bl[8][2];
#pragma unroll
        for (int mi = 0; mi < 2; mi++)
            LDSM4(a[mi][0],a[mi][1],a[mi][2],a[mi][3], swa(aT, ar+mi*16, ac));
#pragma unroll
        for (int p = 0; p < 4; p++){
            LDSM4(bh[2*p][0],bh[2*p][1],bh[2*p+1][0],bh[2*p+1][1], swa(bH, br+p*16, bc));
            LDSM4(bl[2*p][0],bl[2*p][1],bl[2*p+1][0],bl[2*p+1][1], swa(bL, br+p*16, bc));
        }
#pragma unroll
        for (int mi = 0; mi < 2; mi++)
#pragma unroll
        for (int nf = 0; nf < 8; nf++){
            MMA16816(acc[mi][nf], a[mi][0],a[mi][1],a[mi][2],a[mi][3], bh[nf][0],bh[nf][1]);
            MMA16816(acc[mi][nf], a[mi][0],a[mi][1],a[mi][2],a[mi][3], bl[nf][0],bl[nf][1]);
        }
    }
}

// ---------------- prep kernels ----------------
__global__ void k_init(){
    int i = blockIdx.x*blockDim.x + threadIdx.x;
    if (i < NE) g_indeg[i] = 0.f;
    if (i < NR) g_cnt[i] = 0;
}

__global__ void k_hist(const int* __restrict__ tgt, const int* __restrict__ et){
    __shared__ int lcnt[NR];
    int tid = threadIdx.x;
    for (int i = tid; i < NR; i += 256) lcnt[i] = 0;
    __syncthreads();
    int e0 = blockIdx.x*EPB;
#pragma unroll
    for (int q = 0; q < EPB/256; q++){
        int e = e0 + q*256 + tid;
        if (e < EG){
            atomicAdd(&g_indeg[tgt[e]], 1.f);
            atomicAdd(&lcnt[et[e]], 1);
        }
    }
    __syncthreads();
    for (int i = tid; i < NR; i += 256)
        if (lcnt[i]) atomicAdd(&g_cnt[i], lcnt[i]);
}

__global__ void k_scan(){
    if (threadIdx.x == 0){
        int run = 0;
        for (int r = 0; r < NR; r++){ g_off[r] = run; g_cur[r] = run; run += g_cnt[r]; }
        g_off[NR] = run;
    }
}

__global__ void k_scatter(const int* __restrict__ et){
    __shared__ int lcnt[NR];
    __shared__ int lbase[NR];
    int tid = threadIdx.x;
    for (int i = tid; i < NR; i += 256) lcnt[i] = 0;
    __syncthreads();
    int e0 = blockIdx.x*EPB;
    int rel[EPB/256], lpos[EPB/256];
#pragma unroll
    for (int q = 0; q < EPB/256; q++){
        int e = e0 + q*256 + tid;
        if (e < EG){
            rel[q]  = et[e];
            lpos[q] = atomicAdd(&lcnt[rel[q]], 1);
        }
    }
    __syncthreads();
    for (int i = tid; i < NR; i += 256)
        if (lcnt[i]) lbase[i] = atomicAdd(&g_cur[i], lcnt[i]);
    __syncthreads();
#pragma unroll
    for (int q = 0; q < EPB/256; q++){
        int e = e0 + q*256 + tid;
        if (e < EG) g_ord[lbase[rel[q]] + lpos[q]] = e;
    }
}

// Wt[l,r][n][k] = sum_b coefs[l,r,b]*bases[b][k][n], fp16 hi/lo, swizzled rows
__global__ void k_relw_hf(const float* __restrict__ bases, const float* __restrict__ coefs){
    int lr = blockIdx.x;
    float c[NB];
#pragma unroll
    for (int b = 0; b < NB; b++) c[b] = coefs[lr*NB + b];
    char* wh = (char*)g_Wh4 + (size_t)lr*32768;
    char* wl = (char*)g_Wl4 + (size_t)lr*32768;
    for (int ch = threadIdx.x; ch < 2048; ch += blockDim.x){
        int n  = ch & 127;
        int kc = ch >> 7;
        float v[8];
#pragma unroll
        for (int j = 0; j < 8; j++){
            int k = kc*8 + j;
            float a = 0.f;
#pragma unroll
            for (int b = 0; b < NB; b++) a += c[b]*bases[b*D*D + k*D + n];
            v[j] = a;
        }
        uint4 h, l; splitW8(v, h, l);
        int off = n*256 + (((kc ^ (n & 7)) & 15) << 4);
        *(uint4*)(wh + off) = h;
        *(uint4*)(wl + off) = l;
    }
}

// self_w transposed+split: SWt[l][n][k] = selfw[l][k][n]
__global__ void k_selfw_hf(const float* __restrict__ selfw){
    int l = blockIdx.x;
    char* wh = (char*)g_SWh4 + (size_t)l*32768;
    char* wl = (char*)g_SWl4 + (size_t)l*32768;
    for (int ch = threadIdx.x; ch < 2048; ch += blockDim.x){
        int n  = ch & 127;
        int kc = ch >> 7;
        float v[8];
#pragma unroll
        for (int j = 0; j < 8; j++)
            v[j] = selfw[(size_t)l*D*D + (kc*8 + j)*D + n];
        uint4 h, lo; splitW8(v, h, lo);
        int off = n*256 + (((kc ^ (n & 7)) & 15) << 4);
        *(uint4*)(wh + off) = h;
        *(uint4*)(wl + off) = lo;
    }
}

// x0 -> fp16 (row-major)
__global__ void k_xh(const float* __restrict__ x){
    int i = blockIdx.x*blockDim.x + threadIdx.x;
    if (i < NE*16){
        const float4* s = (const float4*)x + (size_t)i*2;
        float4 a = s[0], b = s[1];
        float v[8] = {a.x,a.y,a.z,a.w,b.x,b.y,b.z,b.w};
        g_Xh4[i] = pack8h(v);
    }
}

// ---------------- self GEMM: AGG = X @ self_w[l] + bias[l] (persistent) ----------------
__global__ void __launch_bounds__(256,2) k_self_mma(const float* __restrict__ bias, int layer){
    const int ntiles = (NE + 127) >> 7;
    int t0 = blockIdx.x;
    if (t0 >= ntiles) return;

    extern __shared__ __align__(16) char smem[];
    uint32_t sb = smem_u32(smem);
    int tid = threadIdx.x, lane = tid & 31, wid = tid >> 5;
    int mw = wid & 3, nw = wid >> 2;
    int gr = tid >> 1, gh = tid & 1;

    // B copy (pre-swizzled fp16 hi/lo)
    {
        const uint4* wh = g_SWh4 + (size_t)layer*2048;
        const uint4* wl = g_SWl4 + (size_t)layer*2048;
        uint4* bh = (uint4*)(smem + SM_BH);
        uint4* bl = (uint4*)(smem + SM_BL);
        for (int i = tid; i < 2048; i += 256){ bh[i] = wh[i]; bl[i] = wl[i]; }
    }
    float2 bs[8];
#pragma unroll
    for (int nf = 0; nf < 8; nf++)
        bs[nf] = *(const float2*)(bias + layer*D + nw*64 + nf*8 + (lane & 3)*2);

    for (int t = t0; t < ntiles; t += gridDim.x){
        // gather A tile (consecutive rows, clamped): each thread 8x16B
        int srow = min(t*128 + gr, NE-1);
        const uint4* xh = g_Xh4 + (size_t)srow*16 + gh*8;
#pragma unroll
        for (int j = 0; j < 8; j++){
            int c = gh*8 + j;
            uint32_t off = (uint32_t)(gr*256 + (((c ^ (gr & 7)) & 15) << 4));
            cpa16(sb + SM_A + off, xh + j);
        }
        CP_COMMIT();
        CP_WAIT0();
        __syncthreads();

        float acc[2][8][4];
#pragma unroll
        for (int mi = 0; mi < 2; mi++)
#pragma unroll
            for (int nf = 0; nf < 8; nf++)
#pragma unroll
                for (int q = 0; q < 4; q++) acc[mi][nf][q] = 0.f;

        mma_loop(sb + SM_A, sb + SM_BH, sb + SM_BL, lane, mw, nw, acc);

#pragma unroll
        for (int mi = 0; mi < 2; mi++){
            int r0 = t*128 + mw*32 + mi*16 + (lane >> 2);
#pragma unroll
            for (int nf = 0; nf < 8; nf++){
                int col = nw*64 + nf*8 + (lane & 3)*2;
                if (r0 < NE){
                    float2 v = { acc[mi][nf][0] + bs[nf].x, acc[mi][nf][1] + bs[nf].y };
                    *(float2*)(g_AGG + (size_t)r0*D + col) = v;
                }
                if (r0 + 8 < NE){
                    float2 v = { acc[mi][nf][2] + bs[nf].x, acc[mi][nf][3] + bs[nf].y };
                    *(float2*)(g_AGG + (size_t)(r0+8)*D + col) = v;
                }
            }
        }
        __syncthreads();
    }
}

// ---------------- edge GEMM: AGG[tgt] += ew * (X[src] @ Wt[l,rel]^T) ----------------
__global__ void __launch_bounds__(256,2) k_edge_mma(const int* __restrict__ src,
        const int* __restrict__ tgt, int layer){
    int r   = blockIdx.x;
    int s0  = g_off[r];
    int cnt = g_off[r+1] - s0;
    int ntiles = (cnt + 127) >> 7;
    int j0  = blockIdx.y;
    if (j0 >= ntiles) return;   // uniform before any barrier

    extern __shared__ __align__(16) char smem[];
    uint32_t sb = smem_u32(smem);
    int tid = threadIdx.x, lane = tid & 31, wid = tid >> 5;
    int mw = wid & 3, nw = wid >> 2;
    int gr = tid >> 1, gh = tid & 1;

    // B copy once per block (pre-swizzled fp16 hi/lo)
    {
        const uint4* wh = g_Wh4 + ((size_t)layer*NR + r)*2048;
        const uint4* wl = g_Wl4 + ((size_t)layer*NR + r)*2048;
        uint4* bh = (uint4*)(smem + SM_BH);
        uint4* bl = (uint4*)(smem + SM_BL);
        for (int i = tid; i < 2048; i += 256){ bh[i] = wh[i]; bl[i] = wl[i]; }
    }

    auto idx_load = [&](int t, int& srow, int& tg, float& w){
        int valid = min(128, cnt - t*128);
        int e = g_ord[s0 + t*128 + min(gr, valid-1)];
        srow = src[e];
        tg = tgt[e];
        w = (gr < valid) ? (1.f / fmaxf(g_indeg[tg], 1.f)) : 0.f;
    };

    int srow, tg; float w;
    idx_load(j0, srow, tg, w);

    for (int t = j0; t < ntiles; t += TJ){
        // gather A tile from prefetched indices
        {
            const uint4* xh = g_Xh4 + (size_t)srow*16 + gh*8;
#pragma unroll
            for (int j = 0; j < 8; j++){
                int c = gh*8 + j;
                uint32_t off = (uint32_t)(gr*256 + (((c ^ (gr & 7)) & 15) << 4));
                cpa16(sb + SM_A + off, xh + j);
            }
            if (gh == 0){
                ((int*)(smem + SM_TGT))[gr] = tg;
                ((float*)(smem + SM_WGT))[gr] = w;
            }
        }
        CP_COMMIT();
        if (t + TJ < ntiles) idx_load(t + TJ, srow, tg, w);  // overlaps cp.async
        CP_WAIT0();
        __syncthreads();

        int* s_tgt = (int*)(smem + SM_TGT);
        float* s_wgt = (float*)(smem + SM_WGT);
        int tgr[2][2]; float wgr[2][2];
        int rb = mw*32 + (lane >> 2);
#pragma unroll
        for (int mi = 0; mi < 2; mi++)
#pragma unroll
            for (int h = 0; h < 2; h++){
                int rr = rb + mi*16 + h*8;
                tgr[mi][h] = s_tgt[rr];
                wgr[mi][h] = s_wgt[rr];
            }

        float acc[2][8][4];
#pragma unroll
        for (int mi = 0; mi < 2; mi++)
#pragma unroll
            for (int nf = 0; nf < 8; nf++)
#pragma unroll
                for (int q = 0; q < 4; q++) acc[mi][nf][q] = 0.f;

        mma_loop(sb + SM_A, sb + SM_BH, sb + SM_BL, lane, mw, nw, acc);

        // epilogue: shfl-pair lanes to form 16B, red.v4 scatter
#pragma unroll
        for (int mi = 0; mi < 2; mi++)
#pragma unroll
        for (int nf = 0; nf < 8; nf++){
            float c0 = acc[mi][nf][0], c1 = acc[mi][nf][1];
            float c2 = acc[mi][nf][2], c3 = acc[mi][nf][3];
            float o0 = __shfl_xor_sync(0xffffffffu, c0, 1);
            float o1 = __shfl_xor_sync(0xffffffffu, c1, 1);
            float o2 = __shfl_xor_sync(0xffffffffu, c2, 1);
            float o3 = __shfl_xor_sync(0xffffffffu, c3, 1);
            int colb = nw*64 + nf*8 + (lane & 2)*2;
            if (!(lane & 1)){
                float ww = wgr[mi][0];
                if (ww != 0.f)
                    red4(g_AGG + (size_t)tgr[mi][0]*D + colb, ww*c0, ww*c1, ww*o0, ww*o1);
            } else {
                float ww = wgr[mi][1];
                if (ww != 0.f)
                    red4(g_AGG + (size_t)tgr[mi][1]*D + colb, ww*o2, ww*o3, ww*c2, ww*c3);
            }
        }
        __syncthreads();
    }
}

// ---------------- ReLU (+ fp16 re-pack for layer-0 output) ----------------
__global__ void k_relu(float* __restrict__ dout, int layer){
    int i = blockIdx.x*blockDim.x + threadIdx.x;
    if (i < NE*16){
        const float4* s = (const float4*)g_AGG + (size_t)i*2;
        float4 a = s[0], b = s[1];
        a.x = fmaxf(a.x,0.f); a.y = fmaxf(a.y,0.f); a.z = fmaxf(a.z,0.f); a.w = fmaxf(a.w,0.f);
        b.x = fmaxf(b.x,0.f); b.y = fmaxf(b.y,0.f); b.z = fmaxf(b.z,0.f); b.w = fmaxf(b.w,0.f);
        if (layer == 0){
            float v[8] = {a.x,a.y,a.z,a.w,b.x,b.y,b.z,b.w};
            g_Xh4[i] = pack8h(v);
        } else {
            float4* o = (float4*)dout + (size_t)i*2;
            o[0] = a; o[1] = b;
        }
    }
}

// ---------------- launch ----------------
extern "C" void kernel_launch(void* const* d_in, const int* in_sizes, int n_in,
                              void* d_out, int out_size){
    const float* x0    = (const float*)d_in[0];
    const float* bases = (const float*)d_in[1];
    const float* coefs = (const float*)d_in[2];
    const float* selfw = (const float*)d_in[3];
    const float* bias  = (const float*)d_in[4];
    const int*   source= (const int*)d_in[5];
    const int*   target= (const int*)d_in[6];
    const int*   etype = (const int*)d_in[7];
    float* out = (float*)d_out;

    static int inited = 0;
    if (!inited){
        cudaFuncSetAttribute(k_edge_mma, cudaFuncAttributeMaxDynamicSharedMemorySize, SM_TOT);
        cudaFuncSetAttribute(k_self_mma, cudaFuncAttributeMaxDynamicSharedMemorySize, SM_TOT);
        inited = 1;
    }

    k_init<<<(NE+255)/256, 256>>>();
    k_hist<<<(EG+EPB-1)/EPB, 256>>>(target, etype);
    k_scan<<<1, 32>>>();
    k_scatter<<<(EG+EPB-1)/EPB, 256>>>(etype);
    k_relw_hf<<<NL*NR, 256>>>(bases, coefs);
    k_selfw_hf<<<NL, 256>>>(selfw);
    k_xh<<<(NE*16+255)/256, 256>>>(x0);

    for (int l = 0; l < NL; l++){
        k_self_mma<<<SB_GRID, 256, SM_TOT>>>(bias, l);
        k_edge_mma<<<dim3(NR, TJ), 256, SM_TOT>>>(source, target, l);
        k_relu<<<(NE*16+255)/256, 256>>>(out, l);
    }
}

// round 7
// speedup vs baseline: 3.9620x; 1.0546x over previous
#include <cuda_runtime.h>
#include <cuda_fp16.h>
#include <cstdint>

#define NE 100000
#define NR 100
#define D  128
#define NB 10
#define NL 2
#define EG 600000
#define EPB 2048
#define EG_GRID 296     // persistent blocks, occ 2 on 148 SMs
#define SB_GRID 296

// ---------------- scratch (device globals: no allocation allowed) ----------------
__device__ float g_AGG[(size_t)NE*D];      // pre-activation accumulator
__device__ float g_indeg[NE];
__device__ int   g_cnt[NR];
__device__ int   g_off[NR+1];
__device__ int   g_cur[NR];
__device__ int   g_ord[EG];                // edge ids grouped by relation
__device__ int   g_tiles[8192];            // flat tile table: (r<<16)|t
__device__ int   g_ntile;
// fp16 operands. W tiles stored pre-swizzled (row-major + XOR-16B) hi/lo; X single fp16.
__device__ uint4 g_Wh4[(size_t)NL*NR*2048];   // 32KB per (l,r): Wt[n][k] fp16 hi
__device__ uint4 g_Wl4[(size_t)NL*NR*2048];   // fp16 lo (residual)
__device__ uint4 g_SWh4[(size_t)NL*2048];     // self_w transposed hi
__device__ uint4 g_SWl4[(size_t)NL*2048];     // lo
__device__ uint4 g_Xh4[(size_t)NE*16];        // row-major: 128 fp16 per row (256B)

// SMEM layout (dynamic, bytes): idx, 1 A buf, B hi+lo  -> 100352 B (occ 2)
#define SM_TGT 0
#define SM_WGT 512
#define SM_A   2048
#define SM_BH  (SM_A + 32768)
#define SM_BL  (SM_BH + 32768)
#define SM_TOT (SM_BL + 32768)

// ---------------- helpers ----------------
__device__ __forceinline__ void red4(float* p, float a, float b, float c, float d){
    asm volatile("red.global.add.v4.f32 [%0], {%1,%2,%3,%4};"
                 :: "l"(p), "f"(a), "f"(b), "f"(c), "f"(d) : "memory");
}
__device__ __forceinline__ void cpa16(uint32_t dst, const void* src){
    asm volatile("cp.async.cg.shared.global [%0], [%1], 16;" :: "r"(dst), "l"(src) : "memory");
}
#define CP_COMMIT() asm volatile("cp.async.commit_group;" ::: "memory")
#define CP_WAIT0()  asm volatile("cp.async.wait_group 0;" ::: "memory")

__device__ __forceinline__ uint4 pack8h(const float* v){
    unsigned u[4];
#pragma unroll
    for (int q = 0; q < 4; q++){
        __half2 h = __floats2half2_rn(v[2*q], v[2*q+1]);
        u[q] = *reinterpret_cast<unsigned*>(&h);
    }
    return make_uint4(u[0],u[1],u[2],u[3]);
}
__device__ __forceinline__ void splitW8(const float* v, uint4& h, uint4& l){
    unsigned hh[4], ll[4];
#pragma unroll
    for (int q = 0; q < 4; q++){
        float x0 = v[2*q], x1 = v[2*q+1];
        __half h0 = __float2half_rn(x0), h1 = __float2half_rn(x1);
        float r0 = x0 - __half2float(h0), r1 = x1 - __half2float(h1);
        __half2 hp = __halves2half2(h0, h1);
        __half2 lp = __floats2half2_rn(r0, r1);
        hh[q] = *reinterpret_cast<unsigned*>(&hp);
        ll[q] = *reinterpret_cast<unsigned*>(&lp);
    }
    h = make_uint4(hh[0],hh[1],hh[2],hh[3]);
    l = make_uint4(ll[0],ll[1],ll[2],ll[3]);
}
__device__ __forceinline__ uint32_t smem_u32(const void* p){
    uint32_t a;
    asm("{ .reg .u64 t; cvta.to.shared.u64 t, %1; cvt.u32.u64 %0, t; }" : "=r"(a) : "l"(p));
    return a;
}
// row-major tile, 256B rows, 16B chunks XOR-swizzled by row
__device__ __forceinline__ uint32_t swa(uint32_t base, int r, int c){
    return base + r*256 + (((c ^ (r & 7)) & 15) << 4);
}
#define LDSM4(d0,d1,d2,d3,a) asm volatile( \
    "ldmatrix.sync.aligned.m8n8.x4.shared.b16 {%0,%1,%2,%3}, [%4];" \
    : "=r"(d0),"=r"(d1),"=r"(d2),"=r"(d3) : "r"(a))
#define MMA16816(c,a0,a1,a2,a3,b0,b1) asm volatile( \
    "mma.sync.aligned.m16n8k16.row.col.f32.f16.f16.f32 " \
    "{%0,%1,%2,%3},{%4,%5,%6,%7},{%8,%9},{%0,%1,%2,%3};" \
    : "+f"((c)[0]),"+f"((c)[1]),"+f"((c)[2]),"+f"((c)[3]) \
    : "r"(a0),"r"(a1),"r"(a2),"r"(a3),"r"(b0),"r"(b1))

// 128x128x128 mainloop: acc += A*Bh + A*Bl   (A fp16 single, B fp16 split)
__device__ __forceinline__ void mma_loop(uint32_t aT, uint32_t bH, uint32_t bL,
                                         int lane, int mw, int nw, float acc[2][8][4]){
    int ar = mw*32 + (lane & 15);
    int ac_sel = lane >> 4;
    int br = nw*64 + ((lane >> 4) & 1)*8 + (lane & 7);
    int bc_sel = (lane >> 3) & 1;
    for (int ks = 0; ks < 8; ks++){
        int ac = ks*2 + ac_sel;
        int bc = ks*2 + bc_sel;
        uint32_t a[2][4], bh[8][2], bl[8][2];
#pragma unroll
        for (int mi = 0; mi < 2; mi++)
            LDSM4(a[mi][0],a[mi][1],a[mi][2],a[mi][3], swa(aT, ar+mi*16, ac));
#pragma unroll
        for (int p = 0; p < 4; p++){
            LDSM4(bh[2*p][0],bh[2*p][1],bh[2*p+1][0],bh[2*p+1][1], swa(bH, br+p*16, bc));
            LDSM4(bl[2*p][0],bl[2*p][1],bl[2*p+1][0],bl[2*p+1][1], swa(bL, br+p*16, bc));
        }
#pragma unroll
        for (int mi = 0; mi < 2; mi++)
#pragma unroll
        for (int nf = 0; nf < 8; nf++){
            MMA16816(acc[mi][nf], a[mi][0],a[mi][1],a[mi][2],a[mi][3], bh[nf][0],bh[nf][1]);
            MMA16816(acc[mi][nf], a[mi][0],a[mi][1],a[mi][2],a[mi][3], bl[nf][0],bl[nf][1]);
        }
    }
}

// ---------------- prep kernels ----------------
__global__ void k_init(){
    int i = blockIdx.x*blockDim.x + threadIdx.x;
    if (i < NE) g_indeg[i] = 0.f;
    if (i < NR) g_cnt[i] = 0;
}

__global__ void k_hist(const int* __restrict__ tgt, const int* __restrict__ et){
    __shared__ int lcnt[NR];
    int tid = threadIdx.x;
    for (int i = tid; i < NR; i += 256) lcnt[i] = 0;
    __syncthreads();
    int e0 = blockIdx.x*EPB;
#pragma unroll
    for (int q = 0; q < EPB/256; q++){
        int e = e0 + q*256 + tid;
        if (e < EG){
            atomicAdd(&g_indeg[tgt[e]], 1.f);
            atomicAdd(&lcnt[et[e]], 1);
        }
    }
    __syncthreads();
    for (int i = tid; i < NR; i += 256)
        if (lcnt[i]) atomicAdd(&g_cnt[i], lcnt[i]);
}

// offsets + flat tile table
__global__ void k_scan(){
    __shared__ int ptil[NR];
    int tid = threadIdx.x;
    if (tid == 0){
        int run = 0, trun = 0;
        for (int r = 0; r < NR; r++){
            g_off[r] = run; g_cur[r] = run;
            ptil[r] = trun;
            trun += (g_cnt[r] + 127) >> 7;
            run += g_cnt[r];
        }
        g_off[NR] = run;
        g_ntile = trun;
    }
    __syncthreads();
    for (int r = tid; r < NR; r += blockDim.x){
        int nt = (g_cnt[r] + 127) >> 7;
        int base = ptil[r];
        for (int t = 0; t < nt; t++) g_tiles[base + t] = (r << 16) | t;
    }
}

__global__ void k_scatter(const int* __restrict__ et){
    __shared__ int lcnt[NR];
    __shared__ int lbase[NR];
    int tid = threadIdx.x;
    for (int i = tid; i < NR; i += 256) lcnt[i] = 0;
    __syncthreads();
    int e0 = blockIdx.x*EPB;
    int rel[EPB/256], lpos[EPB/256];
#pragma unroll
    for (int q = 0; q < EPB/256; q++){
        int e = e0 + q*256 + tid;
        if (e < EG){
            rel[q]  = et[e];
            lpos[q] = atomicAdd(&lcnt[rel[q]], 1);
        }
    }
    __syncthreads();
    for (int i = tid; i < NR; i += 256)
        if (lcnt[i]) lbase[i] = atomicAdd(&g_cur[i], lcnt[i]);
    __syncthreads();
#pragma unroll
    for (int q = 0; q < EPB/256; q++){
        int e = e0 + q*256 + tid;
        if (e < EG) g_ord[lbase[rel[q]] + lpos[q]] = e;
    }
}

// Wt[l,r][n][k] = sum_b coefs[l,r,b]*bases[b][k][n], fp16 hi/lo, swizzled rows
__global__ void k_relw_hf(const float* __restrict__ bases, const float* __restrict__ coefs){
    int lr = blockIdx.x;
    float c[NB];
#pragma unroll
    for (int b = 0; b < NB; b++) c[b] = coefs[lr*NB + b];
    char* wh = (char*)g_Wh4 + (size_t)lr*32768;
    char* wl = (char*)g_Wl4 + (size_t)lr*32768;
    for (int ch = threadIdx.x; ch < 2048; ch += blockDim.x){
        int n  = ch & 127;
        int kc = ch >> 7;
        float v[8];
#pragma unroll
        for (int j = 0; j < 8; j++){
            int k = kc*8 + j;
            float a = 0.f;
#pragma unroll
            for (int b = 0; b < NB; b++) a += c[b]*bases[b*D*D + k*D + n];
            v[j] = a;
        }
        uint4 h, l; splitW8(v, h, l);
        int off = n*256 + (((kc ^ (n & 7)) & 15) << 4);
        *(uint4*)(wh + off) = h;
        *(uint4*)(wl + off) = l;
    }
}

// self_w transposed+split: SWt[l][n][k] = selfw[l][k][n]
__global__ void k_selfw_hf(const float* __restrict__ selfw){
    int l = blockIdx.x;
    char* wh = (char*)g_SWh4 + (size_t)l*32768;
    char* wl = (char*)g_SWl4 + (size_t)l*32768;
    for (int ch = threadIdx.x; ch < 2048; ch += blockDim.x){
        int n  = ch & 127;
        int kc = ch >> 7;
        float v[8];
#pragma unroll
        for (int j = 0; j < 8; j++)
            v[j] = selfw[(size_t)l*D*D + (kc*8 + j)*D + n];
        uint4 h, lo; splitW8(v, h, lo);
        int off = n*256 + (((kc ^ (n & 7)) & 15) << 4);
        *(uint4*)(wh + off) = h;
        *(uint4*)(wl + off) = lo;
    }
}

// x0 -> fp16 (row-major)
__global__ void k_xh(const float* __restrict__ x){
    int i = blockIdx.x*blockDim.x + threadIdx.x;
    if (i < NE*16){
        const float4* s = (const float4*)x + (size_t)i*2;
        float4 a = s[0], b = s[1];
        float v[8] = {a.x,a.y,a.z,a.w,b.x,b.y,b.z,b.w};
        g_Xh4[i] = pack8h(v);
    }
}

// ---------------- self GEMM: AGG = X @ self_w[l] + bias[l] (persistent) ----------------
__global__ void __launch_bounds__(256,2) k_self_mma(const float* __restrict__ bias, int layer){
    const int ntiles = (NE + 127) >> 7;
    int t0 = blockIdx.x;
    if (t0 >= ntiles) return;

    extern __shared__ __align__(16) char smem[];
    uint32_t sb = smem_u32(smem);
    int tid = threadIdx.x, lane = tid & 31, wid = tid >> 5;
    int mw = wid & 3, nw = wid >> 2;
    int gr = tid >> 1, gh = tid & 1;

    // B copy (pre-swizzled fp16 hi/lo)
    {
        const uint4* wh = g_SWh4 + (size_t)layer*2048;
        const uint4* wl = g_SWl4 + (size_t)layer*2048;
        uint4* bh = (uint4*)(smem + SM_BH);
        uint4* bl = (uint4*)(smem + SM_BL);
        for (int i = tid; i < 2048; i += 256){ bh[i] = wh[i]; bl[i] = wl[i]; }
    }
    float2 bs[8];
#pragma unroll
    for (int nf = 0; nf < 8; nf++)
        bs[nf] = *(const float2*)(bias + layer*D + nw*64 + nf*8 + (lane & 3)*2);

    for (int t = t0; t < ntiles; t += gridDim.x){
        int srow = min(t*128 + gr, NE-1);
        const uint4* xh = g_Xh4 + (size_t)srow*16 + gh*8;
#pragma unroll
        for (int j = 0; j < 8; j++){
            int c = gh*8 + j;
            uint32_t off = (uint32_t)(gr*256 + (((c ^ (gr & 7)) & 15) << 4));
            cpa16(sb + SM_A + off, xh + j);
        }
        CP_COMMIT();
        CP_WAIT0();
        __syncthreads();

        float acc[2][8][4];
#pragma unroll
        for (int mi = 0; mi < 2; mi++)
#pragma unroll
            for (int nf = 0; nf < 8; nf++)
#pragma unroll
                for (int q = 0; q < 4; q++) acc[mi][nf][q] = 0.f;

        mma_loop(sb + SM_A, sb + SM_BH, sb + SM_BL, lane, mw, nw, acc);

#pragma unroll
        for (int mi = 0; mi < 2; mi++){
            int r0 = t*128 + mw*32 + mi*16 + (lane >> 2);
#pragma unroll
            for (int nf = 0; nf < 8; nf++){
                int col = nw*64 + nf*8 + (lane & 3)*2;
                if (r0 < NE){
                    float2 v = { acc[mi][nf][0] + bs[nf].x, acc[mi][nf][1] + bs[nf].y };
                    *(float2*)(g_AGG + (size_t)r0*D + col) = v;
                }
                if (r0 + 8 < NE){
                    float2 v = { acc[mi][nf][2] + bs[nf].x, acc[mi][nf][3] + bs[nf].y };
                    *(float2*)(g_AGG + (size_t)(r0+8)*D + col) = v;
                }
            }
        }
        __syncthreads();
    }
}

// ---------------- edge GEMM: persistent flat-scheduled tiles ----------------
__global__ void __launch_bounds__(256,2) k_edge_mma(const int* __restrict__ src,
        const int* __restrict__ tgt, int layer){
    int ntile = g_ntile;
    int per = (ntile + gridDim.x - 1) / gridDim.x;
    int i0 = blockIdx.x*per;
    int i1 = min(i0 + per, ntile);
    if (i0 >= i1) return;   // uniform before any barrier

    extern __shared__ __align__(16) char smem[];
    uint32_t sb = smem_u32(smem);
    int tid = threadIdx.x, lane = tid & 31, wid = tid >> 5;
    int mw = wid & 3, nw = wid >> 2;
    int gr = tid >> 1, gh = tid & 1;

    auto idx_load = [&](int i, int& srow, int& tg, float& w){
        int ent = g_tiles[i];
        int r = ent >> 16, t = ent & 0xffff;
        int s0 = g_off[r];
        int valid = min(128, g_off[r+1] - s0 - t*128);
        int e = g_ord[s0 + t*128 + min(gr, valid-1)];
        srow = src[e];
        tg = tgt[e];
        w = (gr < valid) ? (1.f / fmaxf(g_indeg[tg], 1.f)) : 0.f;
    };
    auto copyB = [&](int r){
        const uint4* wh = g_Wh4 + ((size_t)layer*NR + r)*2048;
        const uint4* wl = g_Wl4 + ((size_t)layer*NR + r)*2048;
        for (int i = tid; i < 2048; i += 256){
            uint32_t off = (uint32_t)(i*16);
            cpa16(sb + SM_BH + off, wh + i);
            cpa16(sb + SM_BL + off, wl + i);
        }
    };

    int cur_r = -1;
    int srow, tg; float w;
    idx_load(i0, srow, tg, w);

    for (int i = i0; i < i1; i++){
        int r = g_tiles[i] >> 16;
        if (r != cur_r){ copyB(r); cur_r = r; }   // end-of-iter sync protects prior reads
        {
            const uint4* xh = g_Xh4 + (size_t)srow*16 + gh*8;
#pragma unroll
            for (int j = 0; j < 8; j++){
                int c = gh*8 + j;
                uint32_t off = (uint32_t)(gr*256 + (((c ^ (gr & 7)) & 15) << 4));
                cpa16(sb + SM_A + off, xh + j);
            }
            if (gh == 0){
                ((int*)(smem + SM_TGT))[gr] = tg;
                ((float*)(smem + SM_WGT))[gr] = w;
            }
        }
        CP_COMMIT();
        if (i + 1 < i1) idx_load(i + 1, srow, tg, w);  // overlaps cp.async
        CP_WAIT0();
        __syncthreads();

        int* s_tgt = (int*)(smem + SM_TGT);
        float* s_wgt = (float*)(smem + SM_WGT);
        int tgr[2][2]; float wgr[2][2];
        int rb = mw*32 + (lane >> 2);
#pragma unroll
        for (int mi = 0; mi < 2; mi++)
#pragma unroll
            for (int h = 0; h < 2; h++){
                int rr = rb + mi*16 + h*8;
                tgr[mi][h] = s_tgt[rr];
                wgr[mi][h] = s_wgt[rr];
            }

        float acc[2][8][4];
#pragma unroll
        for (int mi = 0; mi < 2; mi++)
#pragma unroll
            for (int nf = 0; nf < 8; nf++)
#pragma unroll
                for (int q = 0; q < 4; q++) acc[mi][nf][q] = 0.f;

        mma_loop(sb + SM_A, sb + SM_BH, sb + SM_BL, lane, mw, nw, acc);

        // epilogue: 2 parity-selected shfls per fragment, red.v4 scatter
        bool odd = (lane & 1);
#pragma unroll
        for (int mi = 0; mi < 2; mi++)
#pragma unroll
        for (int nf = 0; nf < 8; nf++){
            float c0 = acc[mi][nf][0], c1 = acc[mi][nf][1];
            float c2 = acc[mi][nf][2], c3 = acc[mi][nf][3];
            float s0 = __shfl_xor_sync(0xffffffffu, odd ? c0 : c2, 1);
            float s1 = __shfl_xor_sync(0xffffffffu, odd ? c1 : c3, 1);
            int colb = nw*64 + nf*8 + (lane & 2)*2;
            if (!odd){
                float ww = wgr[mi][0];
                if (ww != 0.f)
                    red4(g_AGG + (size_t)tgr[mi][0]*D + colb, ww*c0, ww*c1, ww*s0, ww*s1);
            } else {
                float ww = wgr[mi][1];
                if (ww != 0.f)
                    red4(g_AGG + (size_t)tgr[mi][1]*D + colb, ww*s0, ww*s1, ww*c2, ww*c3);
            }
        }
        __syncthreads();
    }
}

// ---------------- ReLU (+ fp16 re-pack for layer-0 output) ----------------
__global__ void k_relu(float* __restrict__ dout, int layer){
    int i = blockIdx.x*blockDim.x + threadIdx.x;
    if (i < NE*16){
        const float4* s = (const float4*)g_AGG + (size_t)i*2;
        float4 a = s[0], b = s[1];
        a.x = fmaxf(a.x,0.f); a.y = fmaxf(a.y,0.f); a.z = fmaxf(a.z,0.f); a.w = fmaxf(a.w,0.f);
        b.x = fmaxf(b.x,0.f); b.y = fmaxf(b.y,0.f); b.z = fmaxf(b.z,0.f); b.w = fmaxf(b.w,0.f);
        if (layer == 0){
            float v[8] = {a.x,a.y,a.z,a.w,b.x,b.y,b.z,b.w};
            g_Xh4[i] = pack8h(v);
        } else {
            float4* o = (float4*)dout + (size_t)i*2;
            o[0] = a; o[1] = b;
        }
    }
}

// ---------------- launch ----------------
extern "C" void kernel_launch(void* const* d_in, const int* in_sizes, int n_in,
                              void* d_out, int out_size){
    const float* x0    = (const float*)d_in[0];
    const float* bases = (const float*)d_in[1];
    const float* coefs = (const float*)d_in[2];
    const float* selfw = (const float*)d_in[3];
    const float* bias  = (const float*)d_in[4];
    const int*   source= (const int*)d_in[5];
    const int*   target= (const int*)d_in[6];
    const int*   etype = (const int*)d_in[7];
    float* out = (float*)d_out;

    static int inited = 0;
    if (!inited){
        cudaFuncSetAttribute(k_edge_mma, cudaFuncAttributeMaxDynamicSharedMemorySize, SM_TOT);
        cudaFuncSetAttribute(k_self_mma, cudaFuncAttributeMaxDynamicSharedMemorySize, SM_TOT);
        inited = 1;
    }

    k_init<<<(NE+255)/256, 256>>>();
    k_hist<<<(EG+EPB-1)/EPB, 256>>>(target, etype);
    k_scan<<<1, 128>>>();
    k_scatter<<<(EG+EPB-1)/EPB, 256>>>(etype);
    k_relw_hf<<<NL*NR, 256>>>(bases, coefs);
    k_selfw_hf<<<NL, 256>>>(selfw);
    k_xh<<<(NE*16+255)/256, 256>>>(x0);

    for (int l = 0; l < NL; l++){
        k_self_mma<<<SB_GRID, 256, SM_TOT>>>(bias, l);
        k_edge_mma<<<EG_GRID, 256, SM_TOT>>>(source, target, l);
        k_relu<<<(NE*16+255)/256, 256>>>(out, l);
    }
}

// round 8
// speedup vs baseline: 4.0533x; 1.0230x over previous
#include <cuda_runtime.h>
#include <cuda_fp16.h>
#include <cstdint>

#define NE 100000
#define NR 100
#define D  128
#define NB 10
#define NL 2
#define EG 600000
#define EPB 2048
#define EG_GRID 296     // persistent blocks, occ 2 on 148 SMs
#define SB_GRID 296

// ---------------- scratch (device globals: no allocation allowed) ----------------
__device__ float g_AGG[(size_t)NE*D];      // pre-activation accumulator
__device__ float g_indeg[NE];
__device__ int   g_cnt[NR];
__device__ int   g_off[NR+1];
__device__ int   g_cur[NR];
__device__ int   g_ord[EG];                // edge ids grouped by relation
__device__ int   g_tiles[8192];            // flat tile table: (r<<16)|t
__device__ int   g_ntile;
// fp16 operands. W tiles stored pre-swizzled (row-major + XOR-16B) hi/lo; X single fp16.
__device__ uint4 g_Wh4[(size_t)NL*NR*2048];   // 32KB per (l,r): Wt[n][k] fp16 hi
__device__ uint4 g_Wl4[(size_t)NL*NR*2048];   // fp16 lo (residual)
__device__ uint4 g_SWh4[(size_t)NL*2048];     // self_w transposed hi
__device__ uint4 g_SWl4[(size_t)NL*2048];     // lo
__device__ uint4 g_Xh4[(size_t)NE*16];        // row-major: 128 fp16 per row (256B)

// SMEM layout (dynamic, bytes): idx, 1 A buf, B hi+lo  -> 100352 B (occ 2)
#define SM_TGT 0
#define SM_WGT 512
#define SM_A   2048
#define SM_BH  (SM_A + 32768)
#define SM_BL  (SM_BH + 32768)
#define SM_TOT (SM_BL + 32768)

// ---------------- helpers ----------------
__device__ __forceinline__ void red4(float* p, float a, float b, float c, float d){
    asm volatile("red.global.add.v4.f32 [%0], {%1,%2,%3,%4};"
                 :: "l"(p), "f"(a), "f"(b), "f"(c), "f"(d) : "memory");
}
__device__ __forceinline__ void cpa16(uint32_t dst, const void* src){
    asm volatile("cp.async.cg.shared.global [%0], [%1], 16;" :: "r"(dst), "l"(src) : "memory");
}
#define CP_COMMIT() asm volatile("cp.async.commit_group;" ::: "memory")
#define CP_WAIT0()  asm volatile("cp.async.wait_group 0;" ::: "memory")

__device__ __forceinline__ uint4 pack8h(const float* v){
    unsigned u[4];
#pragma unroll
    for (int q = 0; q < 4; q++){
        __half2 h = __floats2half2_rn(v[2*q], v[2*q+1]);
        u[q] = *reinterpret_cast<unsigned*>(&h);
    }
    return make_uint4(u[0],u[1],u[2],u[3]);
}
__device__ __forceinline__ void splitW8(const float* v, uint4& h, uint4& l){
    unsigned hh[4], ll[4];
#pragma unroll
    for (int q = 0; q < 4; q++){
        float x0 = v[2*q], x1 = v[2*q+1];
        __half h0 = __float2half_rn(x0), h1 = __float2half_rn(x1);
        float r0 = x0 - __half2float(h0), r1 = x1 - __half2float(h1);
        __half2 hp = __halves2half2(h0, h1);
        __half2 lp = __floats2half2_rn(r0, r1);
        hh[q] = *reinterpret_cast<unsigned*>(&hp);
        ll[q] = *reinterpret_cast<unsigned*>(&lp);
    }
    h = make_uint4(hh[0],hh[1],hh[2],hh[3]);
    l = make_uint4(ll[0],ll[1],ll[2],ll[3]);
}
__device__ __forceinline__ uint32_t smem_u32(const void* p){
    uint32_t a;
    asm("{ .reg .u64 t; cvta.to.shared.u64 t, %1; cvt.u32.u64 %0, t; }" : "=r"(a) : "l"(p));
    return a;
}
// row-major tile, 256B rows, 16B chunks XOR-swizzled by row
__device__ __forceinline__ uint32_t swa(uint32_t base, int r, int c){
    return base + r*256 + (((c ^ (r & 7)) & 15) << 4);
}
#define LDSM4(d0,d1,d2,d3,a) asm volatile( \
    "ldmatrix.sync.aligned.m8n8.x4.shared.b16 {%0,%1,%2,%3}, [%4];" \
    : "=r"(d0),"=r"(d1),"=r"(d2),"=r"(d3) : "r"(a))
#define MMA16816(c,a0,a1,a2,a3,b0,b1) asm volatile( \
    "mma.sync.aligned.m16n8k16.row.col.f32.f16.f16.f32 " \
    "{%0,%1,%2,%3},{%4,%5,%6,%7},{%8,%9},{%0,%1,%2,%3};" \
    : "+f"((c)[0]),"+f"((c)[1]),"+f"((c)[2]),"+f"((c)[3]) \
    : "r"(a0),"r"(a1),"r"(a2),"r"(a3),"r"(b0),"r"(b1))

// 128x128x128 mainloop: acc += A*Bh + A*Bl   (A fp16 single, B fp16 split)
__device__ __forceinline__ void mma_loop(uint32_t aT, uint32_t bH, uint32_t bL,
                                         int lane, int mw, int nw, float acc[2][8][4]){
    int ar = mw*32 + (lane & 15);
    int ac_sel = lane >> 4;
    int br = nw*64 + ((lane >> 4) & 1)*8 + (lane & 7);
    int bc_sel = (lane >> 3) & 1;
    for (int ks = 0; ks < 8; ks++){
        int ac = ks*2 + ac_sel;
        int bc = ks*2 + bc_sel;
        uint32_t a[2][4], bh[8][2], bl[8][2];
#pragma unroll
        for (int mi = 0; mi < 2; mi++)
            LDSM4(a[mi][0],a[mi][1],a[mi][2],a[mi][3], swa(aT, ar+mi*16, ac));
#pragma unroll
        for (int p = 0; p < 4; p++){
            LDSM4(bh[2*p][0],bh[2*p][1],bh[2*p+1][0],bh[2*p+1][1], swa(bH, br+p*16, bc));
            LDSM4(bl[2*p][0],bl[2*p][1],bl[2*p+1][0],bl[2*p+1][1], swa(bL, br+p*16, bc));
        }
#pragma unroll
        for (int mi = 0; mi < 2; mi++)
#pragma unroll
        for (int nf = 0; nf < 8; nf++){
            MMA16816(acc[mi][nf], a[mi][0],a[mi][1],a[mi][2],a[mi][3], bh[nf][0],bh[nf][1]);
            MMA16816(acc[mi][nf], a[mi][0],a[mi][1],a[mi][2],a[mi][3], bl[nf][0],bl[nf][1]);
        }
    }
}

// ---------------- prep kernels ----------------
__global__ void k_init(){
    int i = blockIdx.x*blockDim.x + threadIdx.x;
    if (i < NE) g_indeg[i] = 0.f;
    if (i < NR) g_cnt[i] = 0;
}

__global__ void k_hist(const int* __restrict__ tgt, const int* __restrict__ et){
    __shared__ int lcnt[NR];
    int tid = threadIdx.x;
    for (int i = tid; i < NR; i += 256) lcnt[i] = 0;
    __syncthreads();
    int e0 = blockIdx.x*EPB;
#pragma unroll
    for (int q = 0; q < EPB/256; q++){
        int e = e0 + q*256 + tid;
        if (e < EG){
            atomicAdd(&g_indeg[tgt[e]], 1.f);
            atomicAdd(&lcnt[et[e]], 1);
        }
    }
    __syncthreads();
    for (int i = tid; i < NR; i += 256)
        if (lcnt[i]) atomicAdd(&g_cnt[i], lcnt[i]);
}

// offsets + flat tile table
__global__ void k_scan(){
    __shared__ int ptil[NR];
    int tid = threadIdx.x;
    if (tid == 0){
        int run = 0, trun = 0;
        for (int r = 0; r < NR; r++){
            g_off[r] = run; g_cur[r] = run;
            ptil[r] = trun;
            trun += (g_cnt[r] + 127) >> 7;
            run += g_cnt[r];
        }
        g_off[NR] = run;
        g_ntile = trun;
    }
    __syncthreads();
    for (int r = tid; r < NR; r += blockDim.x){
        int nt = (g_cnt[r] + 127) >> 7;
        int base = ptil[r];
        for (int t = 0; t < nt; t++) g_tiles[base + t] = (r << 16) | t;
    }
}

__global__ void k_scatter(const int* __restrict__ et){
    __shared__ int lcnt[NR];
    __shared__ int lbase[NR];
    int tid = threadIdx.x;
    for (int i = tid; i < NR; i += 256) lcnt[i] = 0;
    __syncthreads();
    int e0 = blockIdx.x*EPB;
    int rel[EPB/256], lpos[EPB/256];
#pragma unroll
    for (int q = 0; q < EPB/256; q++){
        int e = e0 + q*256 + tid;
        if (e < EG){
            rel[q]  = et[e];
            lpos[q] = atomicAdd(&lcnt[rel[q]], 1);
        }
    }
    __syncthreads();
    for (int i = tid; i < NR; i += 256)
        if (lcnt[i]) lbase[i] = atomicAdd(&g_cur[i], lcnt[i]);
    __syncthreads();
#pragma unroll
    for (int q = 0; q < EPB/256; q++){
        int e = e0 + q*256 + tid;
        if (e < EG) g_ord[lbase[rel[q]] + lpos[q]] = e;
    }
}

// Wt[l,r][n][k] = sum_b coefs[l,r,b]*bases[b][k][n], fp16 hi/lo, swizzled rows
__global__ void k_relw_hf(const float* __restrict__ bases, const float* __restrict__ coefs){
    int lr = blockIdx.x;
    float c[NB];
#pragma unroll
    for (int b = 0; b < NB; b++) c[b] = coefs[lr*NB + b];
    char* wh = (char*)g_Wh4 + (size_t)lr*32768;
    char* wl = (char*)g_Wl4 + (size_t)lr*32768;
    for (int ch = threadIdx.x; ch < 2048; ch += blockDim.x){
        int n  = ch & 127;
        int kc = ch >> 7;
        float v[8];
#pragma unroll
        for (int j = 0; j < 8; j++){
            int k = kc*8 + j;
            float a = 0.f;
#pragma unroll
            for (int b = 0; b < NB; b++) a += c[b]*bases[b*D*D + k*D + n];
            v[j] = a;
        }
        uint4 h, l; splitW8(v, h, l);
        int off = n*256 + (((kc ^ (n & 7)) & 15) << 4);
        *(uint4*)(wh + off) = h;
        *(uint4*)(wl + off) = l;
    }
}

// self_w transposed+split: SWt[l][n][k] = selfw[l][k][n]
__global__ void k_selfw_hf(const float* __restrict__ selfw){
    int l = blockIdx.x;
    char* wh = (char*)g_SWh4 + (size_t)l*32768;
    char* wl = (char*)g_SWl4 + (size_t)l*32768;
    for (int ch = threadIdx.x; ch < 2048; ch += blockDim.x){
        int n  = ch & 127;
        int kc = ch >> 7;
        float v[8];
#pragma unroll
        for (int j = 0; j < 8; j++)
            v[j] = selfw[(size_t)l*D*D + (kc*8 + j)*D + n];
        uint4 h, lo; splitW8(v, h, lo);
        int off = n*256 + (((kc ^ (n & 7)) & 15) << 4);
        *(uint4*)(wh + off) = h;
        *(uint4*)(wl + off) = lo;
    }
}

// x0 -> fp16 (row-major)
__global__ void k_xh(const float* __restrict__ x){
    int i = blockIdx.x*blockDim.x + threadIdx.x;
    if (i < NE*16){
        const float4* s = (const float4*)x + (size_t)i*2;
        float4 a = s[0], b = s[1];
        float v[8] = {a.x,a.y,a.z,a.w,b.x,b.y,b.z,b.w};
        g_Xh4[i] = pack8h(v);
    }
}

// ---------------- self GEMM: AGG = X @ self_w[l] + bias[l] (persistent, pipelined) ----------------
__global__ void __launch_bounds__(256,2) k_self_mma(const float* __restrict__ bias, int layer){
    const int ntiles = (NE + 127) >> 7;
    int t0 = blockIdx.x;
    if (t0 >= ntiles) return;

    extern __shared__ __align__(16) char smem[];
    uint32_t sb = smem_u32(smem);
    int tid = threadIdx.x, lane = tid & 31, wid = tid >> 5;
    int mw = wid & 3, nw = wid >> 2;
    int gr = tid >> 1, gh = tid & 1;

    // B copy (pre-swizzled fp16 hi/lo)
    {
        const uint4* wh = g_SWh4 + (size_t)layer*2048;
        const uint4* wl = g_SWl4 + (size_t)layer*2048;
        uint4* bh = (uint4*)(smem + SM_BH);
        uint4* bl = (uint4*)(smem + SM_BL);
        for (int i = tid; i < 2048; i += 256){ bh[i] = wh[i]; bl[i] = wl[i]; }
    }
    float2 bs[8];
#pragma unroll
    for (int nf = 0; nf < 8; nf++)
        bs[nf] = *(const float2*)(bias + layer*D + nw*64 + nf*8 + (lane & 3)*2);

    auto gatherA = [&](int t){
        int srow = min(t*128 + gr, NE-1);
        const uint4* xh = g_Xh4 + (size_t)srow*16 + gh*8;
#pragma unroll
        for (int j = 0; j < 8; j++){
            int c = gh*8 + j;
            uint32_t off = (uint32_t)(gr*256 + (((c ^ (gr & 7)) & 15) << 4));
            cpa16(sb + SM_A + off, xh + j);
        }
    };

    gatherA(t0);
    CP_COMMIT();

    for (int t = t0; t < ntiles; t += gridDim.x){
        CP_WAIT0();
        __syncthreads();

        float acc[2][8][4];
#pragma unroll
        for (int mi = 0; mi < 2; mi++)
#pragma unroll
            for (int nf = 0; nf < 8; nf++)
#pragma unroll
                for (int q = 0; q < 4; q++) acc[mi][nf][q] = 0.f;

        mma_loop(sb + SM_A, sb + SM_BH, sb + SM_BL, lane, mw, nw, acc);
        __syncthreads();                       // A reads done

        if (t + (int)gridDim.x < ntiles){      // overlap next gather with epilogue
            gatherA(t + gridDim.x);
            CP_COMMIT();
        }

#pragma unroll
        for (int mi = 0; mi < 2; mi++){
            int r0 = t*128 + mw*32 + mi*16 + (lane >> 2);
#pragma unroll
            for (int nf = 0; nf < 8; nf++){
                int col = nw*64 + nf*8 + (lane & 3)*2;
                if (r0 < NE){
                    float2 v = { acc[mi][nf][0] + bs[nf].x, acc[mi][nf][1] + bs[nf].y };
                    *(float2*)(g_AGG + (size_t)r0*D + col) = v;
                }
                if (r0 + 8 < NE){
                    float2 v = { acc[mi][nf][2] + bs[nf].x, acc[mi][nf][3] + bs[nf].y };
                    *(float2*)(g_AGG + (size_t)(r0+8)*D + col) = v;
                }
            }
        }
    }
}

// ---------------- edge GEMM: persistent flat-scheduled tiles, 3-phase pipelined ----------------
__global__ void __launch_bounds__(256,2) k_edge_mma(const int* __restrict__ src,
        const int* __restrict__ tgt, int layer){
    int ntile = g_ntile;
    int per = (ntile + gridDim.x - 1) / gridDim.x;
    int i0 = blockIdx.x*per;
    int i1 = min(i0 + per, ntile);
    if (i0 >= i1) return;   // uniform before any barrier

    extern __shared__ __align__(16) char smem[];
    uint32_t sb = smem_u32(smem);
    int tid = threadIdx.x, lane = tid & 31, wid = tid >> 5;
    int mw = wid & 3, nw = wid >> 2;
    int gr = tid >> 1, gh = tid & 1;

    auto idx_load = [&](int i, int& srow, int& tg, float& w){
        int ent = g_tiles[i];
        int r = ent >> 16, t = ent & 0xffff;
        int s0 = g_off[r];
        int valid = min(128, g_off[r+1] - s0 - t*128);
        int e = g_ord[s0 + t*128 + min(gr, valid-1)];
        srow = src[e];
        tg = tgt[e];
        w = (gr < valid) ? (1.f / fmaxf(g_indeg[tg], 1.f)) : 0.f;
    };
    auto copyB = [&](int r){
        const uint4* wh = g_Wh4 + ((size_t)layer*NR + r)*2048;
        const uint4* wl = g_Wl4 + ((size_t)layer*NR + r)*2048;
        for (int i = tid; i < 2048; i += 256){
            uint32_t off = (uint32_t)(i*16);
            cpa16(sb + SM_BH + off, wh + i);
            cpa16(sb + SM_BL + off, wl + i);
        }
    };
    auto gatherA = [&](int srow, int tg, float w){
        const uint4* xh = g_Xh4 + (size_t)srow*16 + gh*8;
#pragma unroll
        for (int j = 0; j < 8; j++){
            int c = gh*8 + j;
            uint32_t off = (uint32_t)(gr*256 + (((c ^ (gr & 7)) & 15) << 4));
            cpa16(sb + SM_A + off, xh + j);
        }
        if (gh == 0){
            ((int*)(smem + SM_TGT))[gr] = tg;
            ((float*)(smem + SM_WGT))[gr] = w;
        }
    };

    // prologue: issue B + A for first tile
    int cur_r = g_tiles[i0] >> 16;
    int srow, tg; float w;
    idx_load(i0, srow, tg, w);
    copyB(cur_r);
    gatherA(srow, tg, w);
    CP_COMMIT();

    for (int i = i0; i < i1; i++){
        bool more = (i + 1 < i1);
        if (more) idx_load(i + 1, srow, tg, w);  // regs; overlaps in-flight cp.async
        CP_WAIT0();
        __syncthreads();

        int* s_tgt = (int*)(smem + SM_TGT);
        float* s_wgt = (float*)(smem + SM_WGT);
        int tgr[2][2]; float wgr[2][2];
        int rb = mw*32 + (lane >> 2);
#pragma unroll
        for (int mi = 0; mi < 2; mi++)
#pragma unroll
            for (int h = 0; h < 2; h++){
                int rr = rb + mi*16 + h*8;
                tgr[mi][h] = s_tgt[rr];
                wgr[mi][h] = s_wgt[rr];
            }

        float acc[2][8][4];
#pragma unroll
        for (int mi = 0; mi < 2; mi++)
#pragma unroll
            for (int nf = 0; nf < 8; nf++)
#pragma unroll
                for (int q = 0; q < 4; q++) acc[mi][nf][q] = 0.f;

        mma_loop(sb + SM_A, sb + SM_BH, sb + SM_BL, lane, mw, nw, acc);
        __syncthreads();                         // A/B/idx reads done

        if (more){                               // overlap next gather with epilogue
            int rn = g_tiles[i + 1] >> 16;
            if (rn != cur_r){ copyB(rn); cur_r = rn; }
            gatherA(srow, tg, w);
            CP_COMMIT();
        }

        // epilogue: 2 parity-selected shfls per fragment, red.v4 scatter
        bool odd = (lane & 1);
#pragma unroll
        for (int mi = 0; mi < 2; mi++)
#pragma unroll
        for (int nf = 0; nf < 8; nf++){
            float c0 = acc[mi][nf][0], c1 = acc[mi][nf][1];
            float c2 = acc[mi][nf][2], c3 = acc[mi][nf][3];
            float s0 = __shfl_xor_sync(0xffffffffu, odd ? c0 : c2, 1);
            float s1 = __shfl_xor_sync(0xffffffffu, odd ? c1 : c3, 1);
            int colb = nw*64 + nf*8 + (lane & 2)*2;
            if (!odd){
                float ww = wgr[mi][0];
                if (ww != 0.f)
                    red4(g_AGG + (size_t)tgr[mi][0]*D + colb, ww*c0, ww*c1, ww*s0, ww*s1);
            } else {
                float ww = wgr[mi][1];
                if (ww != 0.f)
                    red4(g_AGG + (size_t)tgr[mi][1]*D + colb, ww*s0, ww*s1, ww*c2, ww*c3);
            }
        }
    }
}

// ---------------- ReLU (+ fp16 re-pack for layer-0 output) ----------------
__global__ void k_relu(float* __restrict__ dout, int layer){
    int i = blockIdx.x*blockDim.x + threadIdx.x;
    if (i < NE*16){
        const float4* s = (const float4*)g_AGG + (size_t)i*2;
        float4 a = s[0], b = s[1];
        a.x = fmaxf(a.x,0.f); a.y = fmaxf(a.y,0.f); a.z = fmaxf(a.z,0.f); a.w = fmaxf(a.w,0.f);
        b.x = fmaxf(b.x,0.f); b.y = fmaxf(b.y,0.f); b.z = fmaxf(b.z,0.f); b.w = fmaxf(b.w,0.f);
        if (layer == 0){
            float v[8] = {a.x,a.y,a.z,a.w,b.x,b.y,b.z,b.w};
            g_Xh4[i] = pack8h(v);
        } else {
            float4* o = (float4*)dout + (size_t)i*2;
            o[0] = a; o[1] = b;
        }
    }
}

// ---------------- launch ----------------
extern "C" void kernel_launch(void* const* d_in, const int* in_sizes, int n_in,
                              void* d_out, int out_size){
    const float* x0    = (const float*)d_in[0];
    const float* bases = (const float*)d_in[1];
    const float* coefs = (const float*)d_in[2];
    const float* selfw = (const float*)d_in[3];
    const float* bias  = (const float*)d_in[4];
    const int*   source= (const int*)d_in[5];
    const int*   target= (const int*)d_in[6];
    const int*   etype = (const int*)d_in[7];
    float* out = (float*)d_out;

    static int inited = 0;
    if (!inited){
        cudaFuncSetAttribute(k_edge_mma, cudaFuncAttributeMaxDynamicSharedMemorySize, SM_TOT);
        cudaFuncSetAttribute(k_self_mma, cudaFuncAttributeMaxDynamicSharedMemorySize, SM_TOT);
        inited = 1;
    }

    k_init<<<(NE+255)/256, 256>>>();
    k_hist<<<(EG+EPB-1)/EPB, 256>>>(target, etype);
    k_scan<<<1, 128>>>();
    k_scatter<<<(EG+EPB-1)/EPB, 256>>>(etype);
    k_relw_hf<<<NL*NR, 256>>>(bases, coefs);
    k_selfw_hf<<<NL, 256>>>(selfw);
    k_xh<<<(NE*16+255)/256, 256>>>(x0);

    for (int l = 0; l < NL; l++){
        k_self_mma<<<SB_GRID, 256, SM_TOT>>>(bias, l);
        k_edge_mma<<<EG_GRID, 256, SM_TOT>>>(source, target, l);
        k_relu<<<(NE*16+255)/256, 256>>>(out, l);
    }
}

// round 9
// speedup vs baseline: 4.3150x; 1.0646x over previous
#include <cuda_runtime.h>
#include <cuda_fp16.h>
#include <cstdint>

#define NE 100000
#define NR 100
#define D  128
#define NB 10
#define NL 2
#define EG 600000
#define EPB 2048
#define EG_GRID 296     // persistent blocks, occ 2 on 148 SMs
#define SB_GRID 296

// ---------------- scratch (device globals: no allocation allowed) ----------------
__device__ float g_AGG[(size_t)NE*D];      // pre-activation accumulator
__device__ float g_indeg[NE];
__device__ int   g_cnt[NR];
__device__ int   g_off[NR+1];
__device__ int   g_cur[NR];
__device__ int   g_ord[EG];                // edge ids grouped by relation
__device__ int   g_tiles[8192];            // flat tile table: (r<<16)|t
__device__ int   g_ntile;
// fp16 operands, all single precision-level (A-quant dominates error; W-quant adds ~sqrt2)
__device__ uint4 g_Wh4[(size_t)NL*NR*2048];   // 32KB per (l,r): Wt[n][k] fp16, swizzled rows
__device__ uint4 g_SWh4[(size_t)NL*2048];     // self_w transposed fp16
__device__ uint4 g_Xh4[(size_t)NE*16];        // row-major: 128 fp16 per row (256B)

// SMEM layout (dynamic, bytes): idx, 1 A buf, B  -> 67584 B (occ 2)
#define SM_TGT 0
#define SM_WGT 512
#define SM_A   2048
#define SM_BH  (SM_A + 32768)
#define SM_TOT (SM_BH + 32768)

// ---------------- helpers ----------------
__device__ __forceinline__ void red4(float* p, float a, float b, float c, float d){
    asm volatile("red.global.add.v4.f32 [%0], {%1,%2,%3,%4};"
                 :: "l"(p), "f"(a), "f"(b), "f"(c), "f"(d) : "memory");
}
__device__ __forceinline__ void cpa16(uint32_t dst, const void* src){
    asm volatile("cp.async.cg.shared.global [%0], [%1], 16;" :: "r"(dst), "l"(src) : "memory");
}
#define CP_COMMIT() asm volatile("cp.async.commit_group;" ::: "memory")
#define CP_WAIT0()  asm volatile("cp.async.wait_group 0;" ::: "memory")

__device__ __forceinline__ uint4 pack8h(const float* v){
    unsigned u[4];
#pragma unroll
    for (int q = 0; q < 4; q++){
        __half2 h = __floats2half2_rn(v[2*q], v[2*q+1]);
        u[q] = *reinterpret_cast<unsigned*>(&h);
    }
    return make_uint4(u[0],u[1],u[2],u[3]);
}
__device__ __forceinline__ uint32_t smem_u32(const void* p){
    uint32_t a;
    asm("{ .reg .u64 t; cvta.to.shared.u64 t, %1; cvt.u32.u64 %0, t; }" : "=r"(a) : "l"(p));
    return a;
}
// row-major tile, 256B rows, 16B chunks XOR-swizzled by row
__device__ __forceinline__ uint32_t swa(uint32_t base, int r, int c){
    return base + r*256 + (((c ^ (r & 7)) & 15) << 4);
}
#define LDSM4(d0,d1,d2,d3,a) asm volatile( \
    "ldmatrix.sync.aligned.m8n8.x4.shared.b16 {%0,%1,%2,%3}, [%4];" \
    : "=r"(d0),"=r"(d1),"=r"(d2),"=r"(d3) : "r"(a))
#define MMA16816(c,a0,a1,a2,a3,b0,b1) asm volatile( \
    "mma.sync.aligned.m16n8k16.row.col.f32.f16.f16.f32 " \
    "{%0,%1,%2,%3},{%4,%5,%6,%7},{%8,%9},{%0,%1,%2,%3};" \
    : "+f"((c)[0]),"+f"((c)[1]),"+f"((c)[2]),"+f"((c)[3]) \
    : "r"(a0),"r"(a1),"r"(a2),"r"(a3),"r"(b0),"r"(b1))

// 128x128x128 mainloop: acc += A*B   (A and B single fp16)
__device__ __forceinline__ void mma_loop(uint32_t aT, uint32_t bH,
                                         int lane, int mw, int nw, float acc[2][8][4]){
    int ar = mw*32 + (lane & 15);
    int ac_sel = lane >> 4;
    int br = nw*64 + ((lane >> 4) & 1)*8 + (lane & 7);
    int bc_sel = (lane >> 3) & 1;
    for (int ks = 0; ks < 8; ks++){
        int ac = ks*2 + ac_sel;
        int bc = ks*2 + bc_sel;
        uint32_t a[2][4], bh[8][2];
#pragma unroll
        for (int mi = 0; mi < 2; mi++)
            LDSM4(a[mi][0],a[mi][1],a[mi][2],a[mi][3], swa(aT, ar+mi*16, ac));
#pragma unroll
        for (int p = 0; p < 4; p++)
            LDSM4(bh[2*p][0],bh[2*p][1],bh[2*p+1][0],bh[2*p+1][1], swa(bH, br+p*16, bc));
#pragma unroll
        for (int mi = 0; mi < 2; mi++)
#pragma unroll
        for (int nf = 0; nf < 8; nf++)
            MMA16816(acc[mi][nf], a[mi][0],a[mi][1],a[mi][2],a[mi][3], bh[nf][0],bh[nf][1]);
    }
}

// ---------------- prep kernels ----------------
__global__ void k_init(){
    int i = blockIdx.x*blockDim.x + threadIdx.x;
    if (i < NE) g_indeg[i] = 0.f;
    if (i < NR) g_cnt[i] = 0;
}

__global__ void k_hist(const int* __restrict__ tgt, const int* __restrict__ et){
    __shared__ int lcnt[NR];
    int tid = threadIdx.x;
    for (int i = tid; i < NR; i += 256) lcnt[i] = 0;
    __syncthreads();
    int e0 = blockIdx.x*EPB;
#pragma unroll
    for (int q = 0; q < EPB/256; q++){
        int e = e0 + q*256 + tid;
        if (e < EG){
            atomicAdd(&g_indeg[tgt[e]], 1.f);
            atomicAdd(&lcnt[et[e]], 1);
        }
    }
    __syncthreads();
    for (int i = tid; i < NR; i += 256)
        if (lcnt[i]) atomicAdd(&g_cnt[i], lcnt[i]);
}

// offsets + flat tile table
__global__ void k_scan(){
    __shared__ int ptil[NR];
    int tid = threadIdx.x;
    if (tid == 0){
        int run = 0, trun = 0;
        for (int r = 0; r < NR; r++){
            g_off[r] = run; g_cur[r] = run;
            ptil[r] = trun;
            trun += (g_cnt[r] + 127) >> 7;
            run += g_cnt[r];
        }
        g_off[NR] = run;
        g_ntile = trun;
    }
    __syncthreads();
    for (int r = tid; r < NR; r += blockDim.x){
        int nt = (g_cnt[r] + 127) >> 7;
        int base = ptil[r];
        for (int t = 0; t < nt; t++) g_tiles[base + t] = (r << 16) | t;
    }
}

__global__ void k_scatter(const int* __restrict__ et){
    __shared__ int lcnt[NR];
    __shared__ int lbase[NR];
    int tid = threadIdx.x;
    for (int i = tid; i < NR; i += 256) lcnt[i] = 0;
    __syncthreads();
    int e0 = blockIdx.x*EPB;
    int rel[EPB/256], lpos[EPB/256];
#pragma unroll
    for (int q = 0; q < EPB/256; q++){
        int e = e0 + q*256 + tid;
        if (e < EG){
            rel[q]  = et[e];
            lpos[q] = atomicAdd(&lcnt[rel[q]], 1);
        }
    }
    __syncthreads();
    for (int i = tid; i < NR; i += 256)
        if (lcnt[i]) lbase[i] = atomicAdd(&g_cur[i], lcnt[i]);
    __syncthreads();
#pragma unroll
    for (int q = 0; q < EPB/256; q++){
        int e = e0 + q*256 + tid;
        if (e < EG) g_ord[lbase[rel[q]] + lpos[q]] = e;
    }
}

// Wt[l,r][n][k] = sum_b coefs[l,r,b]*bases[b][k][n], fp16, swizzled rows
__global__ void k_relw_hf(const float* __restrict__ bases, const float* __restrict__ coefs){
    int lr = blockIdx.x;
    float c[NB];
#pragma unroll
    for (int b = 0; b < NB; b++) c[b] = coefs[lr*NB + b];
    char* wh = (char*)g_Wh4 + (size_t)lr*32768;
    for (int ch = threadIdx.x; ch < 2048; ch += blockDim.x){
        int n  = ch & 127;
        int kc = ch >> 7;
        float v[8];
#pragma unroll
        for (int j = 0; j < 8; j++){
            int k = kc*8 + j;
            float a = 0.f;
#pragma unroll
            for (int b = 0; b < NB; b++) a += c[b]*bases[b*D*D + k*D + n];
            v[j] = a;
        }
        int off = n*256 + (((kc ^ (n & 7)) & 15) << 4);
        *(uint4*)(wh + off) = pack8h(v);
    }
}

// self_w transposed: SWt[l][n][k] = selfw[l][k][n], fp16
__global__ void k_selfw_hf(const float* __restrict__ selfw){
    int l = blockIdx.x;
    char* wh = (char*)g_SWh4 + (size_t)l*32768;
    for (int ch = threadIdx.x; ch < 2048; ch += blockDim.x){
        int n  = ch & 127;
        int kc = ch >> 7;
        float v[8];
#pragma unroll
        for (int j = 0; j < 8; j++)
            v[j] = selfw[(size_t)l*D*D + (kc*8 + j)*D + n];
        int off = n*256 + (((kc ^ (n & 7)) & 15) << 4);
        *(uint4*)(wh + off) = pack8h(v);
    }
}

// x0 -> fp16 (row-major)
__global__ void k_xh(const float* __restrict__ x){
    int i = blockIdx.x*blockDim.x + threadIdx.x;
    if (i < NE*16){
        const float4* s = (const float4*)x + (size_t)i*2;
        float4 a = s[0], b = s[1];
        float v[8] = {a.x,a.y,a.z,a.w,b.x,b.y,b.z,b.w};
        g_Xh4[i] = pack8h(v);
    }
}

// ---------------- self GEMM: AGG = X @ self_w[l] + bias[l] (persistent, pipelined) ----------------
__global__ void __launch_bounds__(256,2) k_self_mma(const float* __restrict__ bias, int layer){
    const int ntiles = (NE + 127) >> 7;
    int t0 = blockIdx.x;
    if (t0 >= ntiles) return;

    extern __shared__ __align__(16) char smem[];
    uint32_t sb = smem_u32(smem);
    int tid = threadIdx.x, lane = tid & 31, wid = tid >> 5;
    int mw = wid & 3, nw = wid >> 2;
    int gr = tid >> 1, gh = tid & 1;

    // B copy (pre-swizzled fp16)
    {
        const uint4* wh = g_SWh4 + (size_t)layer*2048;
        uint4* bh = (uint4*)(smem + SM_BH);
        for (int i = tid; i < 2048; i += 256) bh[i] = wh[i];
    }
    float2 bs[8];
#pragma unroll
    for (int nf = 0; nf < 8; nf++)
        bs[nf] = *(const float2*)(bias + layer*D + nw*64 + nf*8 + (lane & 3)*2);

    auto gatherA = [&](int t){
        int srow = min(t*128 + gr, NE-1);
        const uint4* xh = g_Xh4 + (size_t)srow*16 + gh*8;
#pragma unroll
        for (int j = 0; j < 8; j++){
            int c = gh*8 + j;
            uint32_t off = (uint32_t)(gr*256 + (((c ^ (gr & 7)) & 15) << 4));
            cpa16(sb + SM_A + off, xh + j);
        }
    };

    gatherA(t0);
    CP_COMMIT();

    for (int t = t0; t < ntiles; t += gridDim.x){
        CP_WAIT0();
        __syncthreads();

        float acc[2][8][4];
#pragma unroll
        for (int mi = 0; mi < 2; mi++)
#pragma unroll
            for (int nf = 0; nf < 8; nf++)
#pragma unroll
                for (int q = 0; q < 4; q++) acc[mi][nf][q] = 0.f;

        mma_loop(sb + SM_A, sb + SM_BH, lane, mw, nw, acc);
        __syncthreads();                       // A reads done

        if (t + (int)gridDim.x < ntiles){      // overlap next gather with epilogue
            gatherA(t + gridDim.x);
            CP_COMMIT();
        }

#pragma unroll
        for (int mi = 0; mi < 2; mi++){
            int r0 = t*128 + mw*32 + mi*16 + (lane >> 2);
#pragma unroll
            for (int nf = 0; nf < 8; nf++){
                int col = nw*64 + nf*8 + (lane & 3)*2;
                if (r0 < NE){
                    float2 v = { acc[mi][nf][0] + bs[nf].x, acc[mi][nf][1] + bs[nf].y };
                    *(float2*)(g_AGG + (size_t)r0*D + col) = v;
                }
                if (r0 + 8 < NE){
                    float2 v = { acc[mi][nf][2] + bs[nf].x, acc[mi][nf][3] + bs[nf].y };
                    *(float2*)(g_AGG + (size_t)(r0+8)*D + col) = v;
                }
            }
        }
    }
}

// ---------------- edge GEMM: persistent flat-scheduled tiles, 3-phase pipelined ----------------
__global__ void __launch_bounds__(256,2) k_edge_mma(const int* __restrict__ src,
        const int* __restrict__ tgt, int layer){
    int ntile = g_ntile;
    int per = (ntile + gridDim.x - 1) / gridDim.x;
    int i0 = blockIdx.x*per;
    int i1 = min(i0 + per, ntile);
    if (i0 >= i1) return;   // uniform before any barrier

    extern __shared__ __align__(16) char smem[];
    uint32_t sb = smem_u32(smem);
    int tid = threadIdx.x, lane = tid & 31, wid = tid >> 5;
    int mw = wid & 3, nw = wid >> 2;
    int gr = tid >> 1, gh = tid & 1;

    auto idx_load = [&](int i, int& srow, int& tg, float& w){
        int ent = g_tiles[i];
        int r = ent >> 16, t = ent & 0xffff;
        int s0 = g_off[r];
        int valid = min(128, g_off[r+1] - s0 - t*128);
        int e = g_ord[s0 + t*128 + min(gr, valid-1)];
        srow = src[e];
        tg = tgt[e];
        w = (gr < valid) ? (1.f / fmaxf(g_indeg[tg], 1.f)) : 0.f;
    };
    auto copyB = [&](int r){
        const uint4* wh = g_Wh4 + ((size_t)layer*NR + r)*2048;
        for (int i = tid; i < 2048; i += 256)
            cpa16(sb + SM_BH + (uint32_t)(i*16), wh + i);
    };
    auto gatherA = [&](int srow, int tg, float w){
        const uint4* xh = g_Xh4 + (size_t)srow*16 + gh*8;
#pragma unroll
        for (int j = 0; j < 8; j++){
            int c = gh*8 + j;
            uint32_t off = (uint32_t)(gr*256 + (((c ^ (gr & 7)) & 15) << 4));
            cpa16(sb + SM_A + off, xh + j);
        }
        if (gh == 0){
            ((int*)(smem + SM_TGT))[gr] = tg;
            ((float*)(smem + SM_WGT))[gr] = w;
        }
    };

    // prologue: issue B + A for first tile
    int cur_r = g_tiles[i0] >> 16;
    int srow, tg; float w;
    idx_load(i0, srow, tg, w);
    copyB(cur_r);
    gatherA(srow, tg, w);
    CP_COMMIT();

    for (int i = i0; i < i1; i++){
        bool more = (i + 1 < i1);
        if (more) idx_load(i + 1, srow, tg, w);  // regs; overlaps in-flight cp.async
        CP_WAIT0();
        __syncthreads();

        int* s_tgt = (int*)(smem + SM_TGT);
        float* s_wgt = (float*)(smem + SM_WGT);
        int tgr[2][2]; float wgr[2][2];
        int rb = mw*32 + (lane >> 2);
#pragma unroll
        for (int mi = 0; mi < 2; mi++)
#pragma unroll
            for (int h = 0; h < 2; h++){
                int rr = rb + mi*16 + h*8;
                tgr[mi][h] = s_tgt[rr];
                wgr[mi][h] = s_wgt[rr];
            }

        float acc[2][8][4];
#pragma unroll
        for (int mi = 0; mi < 2; mi++)
#pragma unroll
            for (int nf = 0; nf < 8; nf++)
#pragma unroll
                for (int q = 0; q < 4; q++) acc[mi][nf][q] = 0.f;

        mma_loop(sb + SM_A, sb + SM_BH, lane, mw, nw, acc);
        __syncthreads();                         // A/B/idx reads done

        if (more){                               // overlap next gather with epilogue
            int rn = g_tiles[i + 1] >> 16;
            if (rn != cur_r){ copyB(rn); cur_r = rn; }
            gatherA(srow, tg, w);
            CP_COMMIT();
        }

        // epilogue: 2 parity-selected shfls per fragment, red.v4 scatter
        bool odd = (lane & 1);
#pragma unroll
        for (int mi = 0; mi < 2; mi++)
#pragma unroll
        for (int nf = 0; nf < 8; nf++){
            float c0 = acc[mi][nf][0], c1 = acc[mi][nf][1];
            float c2 = acc[mi][nf][2], c3 = acc[mi][nf][3];
            float s0 = __shfl_xor_sync(0xffffffffu, odd ? c0 : c2, 1);
            float s1 = __shfl_xor_sync(0xffffffffu, odd ? c1 : c3, 1);
            int colb = nw*64 + nf*8 + (lane & 2)*2;
            if (!odd){
                float ww = wgr[mi][0];
                if (ww != 0.f)
                    red4(g_AGG + (size_t)tgr[mi][0]*D + colb, ww*c0, ww*c1, ww*s0, ww*s1);
            } else {
                float ww = wgr[mi][1];
                if (ww != 0.f)
                    red4(g_AGG + (size_t)tgr[mi][1]*D + colb, ww*s0, ww*s1, ww*c2, ww*c3);
            }
        }
    }
}

// ---------------- ReLU (+ fp16 re-pack for layer-0 output) ----------------
__global__ void k_relu(float* __restrict__ dout, int layer){
    int i = blockIdx.x*blockDim.x + threadIdx.x;
    if (i < NE*16){
        const float4* s = (const float4*)g_AGG + (size_t)i*2;
        float4 a = s[0], b = s[1];
        a.x = fmaxf(a.x,0.f); a.y = fmaxf(a.y,0.f); a.z = fmaxf(a.z,0.f); a.w = fmaxf(a.w,0.f);
        b.x = fmaxf(b.x,0.f); b.y = fmaxf(b.y,0.f); b.z = fmaxf(b.z,0.f); b.w = fmaxf(b.w,0.f);
        if (layer == 0){
            float v[8] = {a.x,a.y,a.z,a.w,b.x,b.y,b.z,b.w};
            g_Xh4[i] = pack8h(v);
        } else {
            float4* o = (float4*)dout + (size_t)i*2;
            o[0] = a; o[1] = b;
        }
    }
}

// ---------------- launch ----------------
extern "C" void kernel_launch(void* const* d_in, const int* in_sizes, int n_in,
                              void* d_out, int out_size){
    const float* x0    = (const float*)d_in[0];
    const float* bases = (const float*)d_in[1];
    const float* coefs = (const float*)d_in[2];
    const float* selfw = (const float*)d_in[3];
    const float* bias  = (const float*)d_in[4];
    const int*   source= (const int*)d_in[5];
    const int*   target= (const int*)d_in[6];
    const int*   etype = (const int*)d_in[7];
    float* out = (float*)d_out;

    static int inited = 0;
    if (!inited){
        cudaFuncSetAttribute(k_edge_mma, cudaFuncAttributeMaxDynamicSharedMemorySize, SM_TOT);
        cudaFuncSetAttribute(k_self_mma, cudaFuncAttributeMaxDynamicSharedMemorySize, SM_TOT);
        inited = 1;
    }

    k_init<<<(NE+255)/256, 256>>>();
    k_hist<<<(EG+EPB-1)/EPB, 256>>>(target, etype);
    k_scan<<<1, 128>>>();
    k_scatter<<<(EG+EPB-1)/EPB, 256>>>(etype);
    k_relw_hf<<<NL*NR, 256>>>(bases, coefs);
    k_selfw_hf<<<NL, 256>>>(selfw);
    k_xh<<<(NE*16+255)/256, 256>>>(x0);

    for (int l = 0; l < NL; l++){
        k_self_mma<<<SB_GRID, 256, SM_TOT>>>(bias, l);
        k_edge_mma<<<EG_GRID, 256, SM_TOT>>>(source, target, l);
        k_relu<<<(NE*16+255)/256, 256>>>(out, l);
    }
}

// round 10
// speedup vs baseline: 4.8181x; 1.1166x over previous
#include <cuda_runtime.h>
#include <cuda_fp16.h>
#include <cstdint>

#define NE 100000
#define NR 100
#define D  128
#define NB 10
#define NL 2
#define EG 600000
#define EPB 2048
#define EG_GRID 296     // persistent blocks, occ 2 on 148 SMs
#define SB_GRID 296

// ---------------- scratch (device globals: no allocation allowed) ----------------
__device__ unsigned g_AGGh[(size_t)NE*64];  // pre-activation accumulator, packed half2 per uint
__device__ float g_indeg[NE];
__device__ int   g_cnt[NR];
__device__ int   g_off[NR+1];
__device__ int   g_cur[NR];
__device__ int   g_ord[EG];                // edge ids grouped by relation
__device__ int   g_tiles[8192];            // flat tile table: (r<<16)|t
__device__ int   g_ntile;
// fp16 operands (single precision-level)
__device__ uint4 g_Wh4[(size_t)NL*NR*2048];   // 32KB per (l,r): Wt[n][k] fp16, swizzled rows
__device__ uint4 g_SWh4[(size_t)NL*2048];     // self_w transposed fp16
__device__ uint4 g_Xh4[(size_t)NE*16];        // row-major: 128 fp16 per row (256B)

// SMEM layout (dynamic, bytes): idx, 1 A buf, B  -> 67584 B (occ 2)
#define SM_TGT 0
#define SM_WGT 512
#define SM_A   2048
#define SM_BH  (SM_A + 32768)
#define SM_TOT (SM_BH + 32768)

// ---------------- helpers ----------------
__device__ __forceinline__ void red16h(unsigned* p, unsigned a, unsigned b, unsigned c, unsigned d){
    asm volatile("red.global.add.noftz.v4.f16x2 [%0], {%1,%2,%3,%4};"
                 :: "l"(p), "r"(a), "r"(b), "r"(c), "r"(d) : "memory");
}
__device__ __forceinline__ void cpa16(uint32_t dst, const void* src){
    asm volatile("cp.async.cg.shared.global [%0], [%1], 16;" :: "r"(dst), "l"(src) : "memory");
}
#define CP_COMMIT() asm volatile("cp.async.commit_group;" ::: "memory")
#define CP_WAIT0()  asm volatile("cp.async.wait_group 0;" ::: "memory")

__device__ __forceinline__ unsigned packh2(float a, float b){
    __half2 h = __floats2half2_rn(a, b);
    return *reinterpret_cast<unsigned*>(&h);
}
__device__ __forceinline__ uint4 pack8h(const float* v){
    return make_uint4(packh2(v[0],v[1]), packh2(v[2],v[3]),
                      packh2(v[4],v[5]), packh2(v[6],v[7]));
}
__device__ __forceinline__ unsigned relu_h2(unsigned u){
    __half2 h = *reinterpret_cast<__half2*>(&u);
    __half2 z = __floats2half2_rn(0.f, 0.f);
    __half2 r = __hmax2(h, z);
    return *reinterpret_cast<unsigned*>(&r);
}
__device__ __forceinline__ uint32_t smem_u32(const void* p){
    uint32_t a;
    asm("{ .reg .u64 t; cvta.to.shared.u64 t, %1; cvt.u32.u64 %0, t; }" : "=r"(a) : "l"(p));
    return a;
}
// row-major tile, 256B rows, 16B chunks XOR-swizzled by row
__device__ __forceinline__ uint32_t swa(uint32_t base, int r, int c){
    return base + r*256 + (((c ^ (r & 7)) & 15) << 4);
}
#define LDSM4(d0,d1,d2,d3,a) asm volatile( \
    "ldmatrix.sync.aligned.m8n8.x4.shared.b16 {%0,%1,%2,%3}, [%4];" \
    : "=r"(d0),"=r"(d1),"=r"(d2),"=r"(d3) : "r"(a))
#define MMA16816(c,a0,a1,a2,a3,b0,b1) asm volatile( \
    "mma.sync.aligned.m16n8k16.row.col.f32.f16.f16.f32 " \
    "{%0,%1,%2,%3},{%4,%5,%6,%7},{%8,%9},{%0,%1,%2,%3};" \
    : "+f"((c)[0]),"+f"((c)[1]),"+f"((c)[2]),"+f"((c)[3]) \
    : "r"(a0),"r"(a1),"r"(a2),"r"(a3),"r"(b0),"r"(b1))

// 128x128x128 mainloop: acc += A*B   (A and B single fp16)
__device__ __forceinline__ void mma_loop(uint32_t aT, uint32_t bH,
                                         int lane, int mw, int nw, float acc[2][8][4]){
    int ar = mw*32 + (lane & 15);
    int ac_sel = lane >> 4;
    int br = nw*64 + ((lane >> 4) & 1)*8 + (lane & 7);
    int bc_sel = (lane >> 3) & 1;
    for (int ks = 0; ks < 8; ks++){
        int ac = ks*2 + ac_sel;
        int bc = ks*2 + bc_sel;
        uint32_t a[2][4], bh[8][2];
#pragma unroll
        for (int mi = 0; mi < 2; mi++)
            LDSM4(a[mi][0],a[mi][1],a[mi][2],a[mi][3], swa(aT, ar+mi*16, ac));
#pragma unroll
        for (int p = 0; p < 4; p++)
            LDSM4(bh[2*p][0],bh[2*p][1],bh[2*p+1][0],bh[2*p+1][1], swa(bH, br+p*16, bc));
#pragma unroll
        for (int mi = 0; mi < 2; mi++)
#pragma unroll
        for (int nf = 0; nf < 8; nf++)
            MMA16816(acc[mi][nf], a[mi][0],a[mi][1],a[mi][2],a[mi][3], bh[nf][0],bh[nf][1]);
    }
}

// ---------------- prep kernels ----------------
__global__ void k_init(){
    int i = blockIdx.x*blockDim.x + threadIdx.x;
    if (i < NE) g_indeg[i] = 0.f;
    if (i < NR) g_cnt[i] = 0;
}

__global__ void k_hist(const int* __restrict__ tgt, const int* __restrict__ et){
    __shared__ int lcnt[NR];
    int tid = threadIdx.x;
    for (int i = tid; i < NR; i += 256) lcnt[i] = 0;
    __syncthreads();
    int e0 = blockIdx.x*EPB;
#pragma unroll
    for (int q = 0; q < EPB/256; q++){
        int e = e0 + q*256 + tid;
        if (e < EG){
            atomicAdd(&g_indeg[tgt[e]], 1.f);
            atomicAdd(&lcnt[et[e]], 1);
        }
    }
    __syncthreads();
    for (int i = tid; i < NR; i += 256)
        if (lcnt[i]) atomicAdd(&g_cnt[i], lcnt[i]);
}

// offsets + flat tile table
__global__ void k_scan(){
    __shared__ int ptil[NR];
    int tid = threadIdx.x;
    if (tid == 0){
        int run = 0, trun = 0;
        for (int r = 0; r < NR; r++){
            g_off[r] = run; g_cur[r] = run;
            ptil[r] = trun;
            trun += (g_cnt[r] + 127) >> 7;
            run += g_cnt[r];
        }
        g_off[NR] = run;
        g_ntile = trun;
    }
    __syncthreads();
    for (int r = tid; r < NR; r += blockDim.x){
        int nt = (g_cnt[r] + 127) >> 7;
        int base = ptil[r];
        for (int t = 0; t < nt; t++) g_tiles[base + t] = (r << 16) | t;
    }
}

__global__ void k_scatter(const int* __restrict__ et){
    __shared__ int lcnt[NR];
    __shared__ int lbase[NR];
    int tid = threadIdx.x;
    for (int i = tid; i < NR; i += 256) lcnt[i] = 0;
    __syncthreads();
    int e0 = blockIdx.x*EPB;
    int rel[EPB/256], lpos[EPB/256];
#pragma unroll
    for (int q = 0; q < EPB/256; q++){
        int e = e0 + q*256 + tid;
        if (e < EG){
            rel[q]  = et[e];
            lpos[q] = atomicAdd(&lcnt[rel[q]], 1);
        }
    }
    __syncthreads();
    for (int i = tid; i < NR; i += 256)
        if (lcnt[i]) lbase[i] = atomicAdd(&g_cur[i], lcnt[i]);
    __syncthreads();
#pragma unroll
    for (int q = 0; q < EPB/256; q++){
        int e = e0 + q*256 + tid;
        if (e < EG) g_ord[lbase[rel[q]] + lpos[q]] = e;
    }
}

// Wt[l,r][n][k] = sum_b coefs[l,r,b]*bases[b][k][n], fp16, swizzled rows
__global__ void k_relw_hf(const float* __restrict__ bases, const float* __restrict__ coefs){
    int lr = blockIdx.x;
    float c[NB];
#pragma unroll
    for (int b = 0; b < NB; b++) c[b] = coefs[lr*NB + b];
    char* wh = (char*)g_Wh4 + (size_t)lr*32768;
    for (int ch = threadIdx.x; ch < 2048; ch += blockDim.x){
        int n  = ch & 127;
        int kc = ch >> 7;
        float v[8];
#pragma unroll
        for (int j = 0; j < 8; j++){
            int k = kc*8 + j;
            float a = 0.f;
#pragma unroll
            for (int b = 0; b < NB; b++) a += c[b]*bases[b*D*D + k*D + n];
            v[j] = a;
        }
        int off = n*256 + (((kc ^ (n & 7)) & 15) << 4);
        *(uint4*)(wh + off) = pack8h(v);
    }
}

// self_w transposed: SWt[l][n][k] = selfw[l][k][n], fp16
__global__ void k_selfw_hf(const float* __restrict__ selfw){
    int l = blockIdx.x;
    char* wh = (char*)g_SWh4 + (size_t)l*32768;
    for (int ch = threadIdx.x; ch < 2048; ch += blockDim.x){
        int n  = ch & 127;
        int kc = ch >> 7;
        float v[8];
#pragma unroll
        for (int j = 0; j < 8; j++)
            v[j] = selfw[(size_t)l*D*D + (kc*8 + j)*D + n];
        int off = n*256 + (((kc ^ (n & 7)) & 15) << 4);
        *(uint4*)(wh + off) = pack8h(v);
    }
}

// x0 -> fp16 (row-major)
__global__ void k_xh(const float* __restrict__ x){
    int i = blockIdx.x*blockDim.x + threadIdx.x;
    if (i < NE*16){
        const float4* s = (const float4*)x + (size_t)i*2;
        float4 a = s[0], b = s[1];
        float v[8] = {a.x,a.y,a.z,a.w,b.x,b.y,b.z,b.w};
        g_Xh4[i] = pack8h(v);
    }
}

// ---------------- self GEMM: AGGh = fp16(X @ self_w[l] + bias[l]) ----------------
__global__ void __launch_bounds__(256,2) k_self_mma(const float* __restrict__ bias, int layer){
    const int ntiles = (NE + 127) >> 7;
    int t0 = blockIdx.x;
    if (t0 >= ntiles) return;

    extern __shared__ __align__(16) char smem[];
    uint32_t sb = smem_u32(smem);
    int tid = threadIdx.x, lane = tid & 31, wid = tid >> 5;
    int mw = wid & 3, nw = wid >> 2;
    int gr = tid >> 1, gh = tid & 1;

    // B copy (pre-swizzled fp16)
    {
        const uint4* wh = g_SWh4 + (size_t)layer*2048;
        uint4* bh = (uint4*)(smem + SM_BH);
        for (int i = tid; i < 2048; i += 256) bh[i] = wh[i];
    }
    float2 bs[8];
#pragma unroll
    for (int nf = 0; nf < 8; nf++)
        bs[nf] = *(const float2*)(bias + layer*D + nw*64 + nf*8 + (lane & 3)*2);

    auto gatherA = [&](int t){
        int srow = min(t*128 + gr, NE-1);
        const uint4* xh = g_Xh4 + (size_t)srow*16 + gh*8;
#pragma unroll
        for (int j = 0; j < 8; j++){
            int c = gh*8 + j;
            uint32_t off = (uint32_t)(gr*256 + (((c ^ (gr & 7)) & 15) << 4));
            cpa16(sb + SM_A + off, xh + j);
        }
    };

    gatherA(t0);
    CP_COMMIT();

    for (int t = t0; t < ntiles; t += gridDim.x){
        CP_WAIT0();
        __syncthreads();

        float acc[2][8][4];
#pragma unroll
        for (int mi = 0; mi < 2; mi++)
#pragma unroll
            for (int nf = 0; nf < 8; nf++)
#pragma unroll
                for (int q = 0; q < 4; q++) acc[mi][nf][q] = 0.f;

        mma_loop(sb + SM_A, sb + SM_BH, lane, mw, nw, acc);
        __syncthreads();                       // A reads done

        if (t + (int)gridDim.x < ntiles){      // overlap next gather with epilogue
            gatherA(t + gridDim.x);
            CP_COMMIT();
        }

#pragma unroll
        for (int mi = 0; mi < 2; mi++){
            int r0 = t*128 + mw*32 + mi*16 + (lane >> 2);
#pragma unroll
            for (int nf = 0; nf < 8; nf++){
                int cu = nw*32 + nf*4 + (lane & 3);   // uint (half2) index within row
                if (r0 < NE)
                    g_AGGh[(size_t)r0*64 + cu] = packh2(acc[mi][nf][0] + bs[nf].x,
                                                        acc[mi][nf][1] + bs[nf].y);
                if (r0 + 8 < NE)
                    g_AGGh[(size_t)(r0+8)*64 + cu] = packh2(acc[mi][nf][2] + bs[nf].x,
                                                            acc[mi][nf][3] + bs[nf].y);
            }
        }
    }
}

// ---------------- edge GEMM: persistent flat-scheduled tiles, fp16 atomic epilogue ----------------
__global__ void __launch_bounds__(256,2) k_edge_mma(const int* __restrict__ src,
        const int* __restrict__ tgt, int layer){
    int ntile = g_ntile;
    int per = (ntile + gridDim.x - 1) / gridDim.x;
    int i0 = blockIdx.x*per;
    int i1 = min(i0 + per, ntile);
    if (i0 >= i1) return;   // uniform before any barrier

    extern __shared__ __align__(16) char smem[];
    uint32_t sb = smem_u32(smem);
    int tid = threadIdx.x, lane = tid & 31, wid = tid >> 5;
    int mw = wid & 3, nw = wid >> 2;
    int gr = tid >> 1, gh = tid & 1;

    auto idx_load = [&](int i, int& srow, int& tg, float& w){
        int ent = g_tiles[i];
        int r = ent >> 16, t = ent & 0xffff;
        int s0 = g_off[r];
        int valid = min(128, g_off[r+1] - s0 - t*128);
        int e = g_ord[s0 + t*128 + min(gr, valid-1)];
        srow = src[e];
        tg = tgt[e];
        w = (gr < valid) ? (1.f / fmaxf(g_indeg[tg], 1.f)) : 0.f;
    };
    auto copyB = [&](int r){
        const uint4* wh = g_Wh4 + ((size_t)layer*NR + r)*2048;
        for (int i = tid; i < 2048; i += 256)
            cpa16(sb + SM_BH + (uint32_t)(i*16), wh + i);
    };
    auto gatherA = [&](int srow, int tg, float w){
        const uint4* xh = g_Xh4 + (size_t)srow*16 + gh*8;
#pragma unroll
        for (int j = 0; j < 8; j++){
            int c = gh*8 + j;
            uint32_t off = (uint32_t)(gr*256 + (((c ^ (gr & 7)) & 15) << 4));
            cpa16(sb + SM_A + off, xh + j);
        }
        if (gh == 0){
            ((int*)(smem + SM_TGT))[gr] = tg;
            ((float*)(smem + SM_WGT))[gr] = w;
        }
    };

    // prologue: issue B + A for first tile
    int cur_r = g_tiles[i0] >> 16;
    int srow, tg; float w;
    idx_load(i0, srow, tg, w);
    copyB(cur_r);
    gatherA(srow, tg, w);
    CP_COMMIT();

    for (int i = i0; i < i1; i++){
        bool more = (i + 1 < i1);
        if (more) idx_load(i + 1, srow, tg, w);  // regs; overlaps in-flight cp.async
        CP_WAIT0();
        __syncthreads();

        int* s_tgt = (int*)(smem + SM_TGT);
        float* s_wgt = (float*)(smem + SM_WGT);
        int tgr[2][2]; float wgr[2][2];
        int rb = mw*32 + (lane >> 2);
#pragma unroll
        for (int mi = 0; mi < 2; mi++)
#pragma unroll
            for (int h = 0; h < 2; h++){
                int rr = rb + mi*16 + h*8;
                tgr[mi][h] = s_tgt[rr];
                wgr[mi][h] = s_wgt[rr];
            }

        float acc[2][8][4];
#pragma unroll
        for (int mi = 0; mi < 2; mi++)
#pragma unroll
            for (int nf = 0; nf < 8; nf++)
#pragma unroll
                for (int q = 0; q < 4; q++) acc[mi][nf][q] = 0.f;

        mma_loop(sb + SM_A, sb + SM_BH, lane, mw, nw, acc);
        __syncthreads();                         // A/B/idx reads done

        if (more){                               // overlap next gather with epilogue
            int rn = g_tiles[i + 1] >> 16;
            if (rn != cur_r){ copyB(rn); cur_r = rn; }
            gatherA(srow, tg, w);
            CP_COMMIT();
        }

        // epilogue: assemble 16B (8 halves) per row, one v4.f16x2 atomic per 8 cols
        int odd = lane & 1;
#pragma unroll
        for (int mi = 0; mi < 2; mi++){
            float ww = wgr[mi][odd];
            int   tt = tgr[mi][odd];
            unsigned* rowp = g_AGGh + (size_t)tt*64 + nw*32;
#pragma unroll
            for (int nf = 0; nf < 8; nf++){
                float c0 = acc[mi][nf][0], c1 = acc[mi][nf][1];
                float c2 = acc[mi][nf][2], c3 = acc[mi][nf][3];
                float s0 = __shfl_xor_sync(0xffffffffu, odd ? c0 : c2, 1);
                float s1 = __shfl_xor_sync(0xffffffffu, odd ? c1 : c3, 1);
                float v0, v1, v2, v3;
                if (!odd){ v0 = c0; v1 = c1; v2 = s0; v3 = s1; }
                else     { v0 = s0; v1 = s1; v2 = c2; v3 = c3; }
                unsigned p0 = packh2(ww*v0, ww*v1);
                unsigned p1 = packh2(ww*v2, ww*v3);
                unsigned q0 = __shfl_xor_sync(0xffffffffu, p0, 2);
                unsigned q1 = __shfl_xor_sync(0xffffffffu, p1, 2);
                if (!(lane & 2) && ww != 0.f)
                    red16h(rowp + nf*4, p0, p1, q0, q1);
            }
        }
    }
}

// ---------------- ReLU: half2 in, fp16 repack (layer 0) or fp32 out (layer 1) ----------------
__global__ void k_relu(float* __restrict__ dout, int layer){
    int i = blockIdx.x*blockDim.x + threadIdx.x;
    if (i < NE*16){
        uint4 u = ((const uint4*)g_AGGh)[i];
        u.x = relu_h2(u.x); u.y = relu_h2(u.y);
        u.z = relu_h2(u.z); u.w = relu_h2(u.w);
        if (layer == 0){
            g_Xh4[i] = u;            // identical packed layout
        } else {
            float2 f0 = __half22float2(*reinterpret_cast<__half2*>(&u.x));
            float2 f1 = __half22float2(*reinterpret_cast<__half2*>(&u.y));
            float2 f2 = __half22float2(*reinterpret_cast<__half2*>(&u.z));
            float2 f3 = __half22float2(*reinterpret_cast<__half2*>(&u.w));
            float4* o = (float4*)dout + (size_t)i*2;
            o[0] = make_float4(f0.x, f0.y, f1.x, f1.y);
            o[1] = make_float4(f2.x, f2.y, f3.x, f3.y);
        }
    }
}

// ---------------- launch ----------------
extern "C" void kernel_launch(void* const* d_in, const int* in_sizes, int n_in,
                              void* d_out, int out_size){
    const float* x0    = (const float*)d_in[0];
    const float* bases = (const float*)d_in[1];
    const float* coefs = (const float*)d_in[2];
    const float* selfw = (const float*)d_in[3];
    const float* bias  = (const float*)d_in[4];
    const int*   source= (const int*)d_in[5];
    const int*   target= (const int*)d_in[6];
    const int*   etype = (const int*)d_in[7];
    float* out = (float*)d_out;

    static int inited = 0;
    if (!inited){
        cudaFuncSetAttribute(k_edge_mma, cudaFuncAttributeMaxDynamicSharedMemorySize, SM_TOT);
        cudaFuncSetAttribute(k_self_mma, cudaFuncAttributeMaxDynamicSharedMemorySize, SM_TOT);
        inited = 1;
    }

    k_init<<<(NE+255)/256, 256>>>();
    k_hist<<<(EG+EPB-1)/EPB, 256>>>(target, etype);
    k_scan<<<1, 128>>>();
    k_scatter<<<(EG+EPB-1)/EPB, 256>>>(etype);
    k_relw_hf<<<NL*NR, 256>>>(bases, coefs);
    k_selfw_hf<<<NL, 256>>>(selfw);
    k_xh<<<(NE*16+255)/256, 256>>>(x0);

    for (int l = 0; l < NL; l++){
        k_self_mma<<<SB_GRID, 256, SM_TOT>>>(bias, l);
        k_edge_mma<<<EG_GRID, 256, SM_TOT>>>(source, target, l);
        k_relu<<<(NE*16+255)/256, 256>>>(out, l);
    }
}

// round 11
// speedup vs baseline: 4.9233x; 1.0218x over previous
#include <cuda_runtime.h>
#include <cuda_fp16.h>
#include <cstdint>

#define NE 100000
#define NR 100
#define D  128
#define NB 10
#define NL 2
#define EG 600000
#define EPB 2048
#define EG_GRID 296     // persistent blocks, occ 2 on 148 SMs
#define NSELF 782       // ceil(NE/128)

// ---------------- scratch (device globals: no allocation allowed) ----------------
__device__ unsigned g_AGGh[(size_t)NE*64];   // edge-sum accumulator, packed half2 (atomics, from 0)
__device__ unsigned g_SELFh[(size_t)NE*64];  // self-term + bias, packed half2 (stores)
__device__ float g_indeg[NE];
__device__ int   g_cnt[NR];
__device__ int   g_off[NR+1];
__device__ int   g_cur[NR];
__device__ int   g_ord[EG];                // edge ids grouped by relation
__device__ int   g_tiles[8192];            // flat tile table: (r<<16)|t ; r==NR -> self tile
__device__ int   g_ntile_all;
// fp16 operands (single precision-level)
__device__ uint4 g_Wh4[(size_t)NL*NR*2048];   // 32KB per (l,r): Wt[n][k] fp16, swizzled rows
__device__ uint4 g_SWh4[(size_t)NL*2048];     // self_w transposed fp16
__device__ uint4 g_Xh4[(size_t)NE*16];        // row-major: 128 fp16 per row (256B)

// SMEM layout (dynamic, bytes): idx, 1 A buf, B  -> 67584 B (occ 2)
#define SM_TGT 0
#define SM_WGT 512
#define SM_A   2048
#define SM_BH  (SM_A + 32768)
#define SM_TOT (SM_BH + 32768)

// ---------------- helpers ----------------
__device__ __forceinline__ void red16h(unsigned* p, unsigned a, unsigned b, unsigned c, unsigned d){
    asm volatile("red.global.add.noftz.v4.f16x2 [%0], {%1,%2,%3,%4};"
                 :: "l"(p), "r"(a), "r"(b), "r"(c), "r"(d) : "memory");
}
__device__ __forceinline__ void cpa16(uint32_t dst, const void* src){
    asm volatile("cp.async.cg.shared.global [%0], [%1], 16;" :: "r"(dst), "l"(src) : "memory");
}
#define CP_COMMIT() asm volatile("cp.async.commit_group;" ::: "memory")
#define CP_WAIT0()  asm volatile("cp.async.wait_group 0;" ::: "memory")

__device__ __forceinline__ unsigned packh2(float a, float b){
    __half2 h = __floats2half2_rn(a, b);
    return *reinterpret_cast<unsigned*>(&h);
}
__device__ __forceinline__ uint4 pack8h(const float* v){
    return make_uint4(packh2(v[0],v[1]), packh2(v[2],v[3]),
                      packh2(v[4],v[5]), packh2(v[6],v[7]));
}
__device__ __forceinline__ float2 h2f(unsigned u){
    return __half22float2(*reinterpret_cast<__half2*>(&u));
}
__device__ __forceinline__ uint32_t smem_u32(const void* p){
    uint32_t a;
    asm("{ .reg .u64 t; cvta.to.shared.u64 t, %1; cvt.u32.u64 %0, t; }" : "=r"(a) : "l"(p));
    return a;
}
// row-major tile, 256B rows, 16B chunks XOR-swizzled by row
__device__ __forceinline__ uint32_t swa(uint32_t base, int r, int c){
    return base + r*256 + (((c ^ (r & 7)) & 15) << 4);
}
#define LDSM4(d0,d1,d2,d3,a) asm volatile( \
    "ldmatrix.sync.aligned.m8n8.x4.shared.b16 {%0,%1,%2,%3}, [%4];" \
    : "=r"(d0),"=r"(d1),"=r"(d2),"=r"(d3) : "r"(a))
#define MMA16816(c,a0,a1,a2,a3,b0,b1) asm volatile( \
    "mma.sync.aligned.m16n8k16.row.col.f32.f16.f16.f32 " \
    "{%0,%1,%2,%3},{%4,%5,%6,%7},{%8,%9},{%0,%1,%2,%3};" \
    : "+f"((c)[0]),"+f"((c)[1]),"+f"((c)[2]),"+f"((c)[3]) \
    : "r"(a0),"r"(a1),"r"(a2),"r"(a3),"r"(b0),"r"(b1))

// 128x128x128 mainloop: acc += A*B   (A and B single fp16)
__device__ __forceinline__ void mma_loop(uint32_t aT, uint32_t bH,
                                         int lane, int mw, int nw, float acc[2][8][4]){
    int ar = mw*32 + (lane & 15);
    int ac_sel = lane >> 4;
    int br = nw*64 + ((lane >> 4) & 1)*8 + (lane & 7);
    int bc_sel = (lane >> 3) & 1;
    for (int ks = 0; ks < 8; ks++){
        int ac = ks*2 + ac_sel;
        int bc = ks*2 + bc_sel;
        uint32_t a[2][4], bh[8][2];
#pragma unroll
        for (int mi = 0; mi < 2; mi++)
            LDSM4(a[mi][0],a[mi][1],a[mi][2],a[mi][3], swa(aT, ar+mi*16, ac));
#pragma unroll
        for (int p = 0; p < 4; p++)
            LDSM4(bh[2*p][0],bh[2*p][1],bh[2*p+1][0],bh[2*p+1][1], swa(bH, br+p*16, bc));
#pragma unroll
        for (int mi = 0; mi < 2; mi++)
#pragma unroll
        for (int nf = 0; nf < 8; nf++)
            MMA16816(acc[mi][nf], a[mi][0],a[mi][1],a[mi][2],a[mi][3], bh[nf][0],bh[nf][1]);
    }
}

// ---------------- prep kernels ----------------
__global__ void k_init(){
    int i = blockIdx.x*blockDim.x + threadIdx.x;
    if (i < NE) g_indeg[i] = 0.f;
    if (i < NR) g_cnt[i] = 0;
    if (i < NE*16) ((uint4*)g_AGGh)[i] = make_uint4(0,0,0,0);
}

__global__ void k_hist(const int* __restrict__ tgt, const int* __restrict__ et){
    __shared__ int lcnt[NR];
    int tid = threadIdx.x;
    for (int i = tid; i < NR; i += 256) lcnt[i] = 0;
    __syncthreads();
    int e0 = blockIdx.x*EPB;
#pragma unroll
    for (int q = 0; q < EPB/256; q++){
        int e = e0 + q*256 + tid;
        if (e < EG){
            atomicAdd(&g_indeg[tgt[e]], 1.f);
            atomicAdd(&lcnt[et[e]], 1);
        }
    }
    __syncthreads();
    for (int i = tid; i < NR; i += 256)
        if (lcnt[i]) atomicAdd(&g_cnt[i], lcnt[i]);
}

// offsets + flat tile table (edge tiles, then NSELF self tiles with r==NR)
__global__ void k_scan(){
    __shared__ int ptil[NR];
    __shared__ int strun;
    int tid = threadIdx.x;
    if (tid == 0){
        int run = 0, trun = 0;
        for (int r = 0; r < NR; r++){
            g_off[r] = run; g_cur[r] = run;
            ptil[r] = trun;
            trun += (g_cnt[r] + 127) >> 7;
            run += g_cnt[r];
        }
        g_off[NR] = run;
        strun = trun;
        g_ntile_all = trun + NSELF;
    }
    __syncthreads();
    for (int r = tid; r < NR; r += blockDim.x){
        int nt = (g_cnt[r] + 127) >> 7;
        int base = ptil[r];
        for (int t = 0; t < nt; t++) g_tiles[base + t] = (r << 16) | t;
    }
    int et = strun;
    for (int t = tid; t < NSELF; t += blockDim.x)
        g_tiles[et + t] = (NR << 16) | t;
}

__global__ void k_scatter(const int* __restrict__ et){
    __shared__ int lcnt[NR];
    __shared__ int lbase[NR];
    int tid = threadIdx.x;
    for (int i = tid; i < NR; i += 256) lcnt[i] = 0;
    __syncthreads();
    int e0 = blockIdx.x*EPB;
    int rel[EPB/256], lpos[EPB/256];
#pragma unroll
    for (int q = 0; q < EPB/256; q++){
        int e = e0 + q*256 + tid;
        if (e < EG){
            rel[q]  = et[e];
            lpos[q] = atomicAdd(&lcnt[rel[q]], 1);
        }
    }
    __syncthreads();
    for (int i = tid; i < NR; i += 256)
        if (lcnt[i]) lbase[i] = atomicAdd(&g_cur[i], lcnt[i]);
    __syncthreads();
#pragma unroll
    for (int q = 0; q < EPB/256; q++){
        int e = e0 + q*256 + tid;
        if (e < EG) g_ord[lbase[rel[q]] + lpos[q]] = e;
    }
}

// Wt[l,r][n][k] = sum_b coefs[l,r,b]*bases[b][k][n], fp16, swizzled rows
__global__ void k_relw_hf(const float* __restrict__ bases, const float* __restrict__ coefs){
    int lr = blockIdx.x;
    float c[NB];
#pragma unroll
    for (int b = 0; b < NB; b++) c[b] = coefs[lr*NB + b];
    char* wh = (char*)g_Wh4 + (size_t)lr*32768;
    for (int ch = threadIdx.x; ch < 2048; ch += blockDim.x){
        int n  = ch & 127;
        int kc = ch >> 7;
        float v[8];
#pragma unroll
        for (int j = 0; j < 8; j++){
            int k = kc*8 + j;
            float a = 0.f;
#pragma unroll
            for (int b = 0; b < NB; b++) a += c[b]*bases[b*D*D + k*D + n];
            v[j] = a;
        }
        int off = n*256 + (((kc ^ (n & 7)) & 15) << 4);
        *(uint4*)(wh + off) = pack8h(v);
    }
}

// self_w transposed: SWt[l][n][k] = selfw[l][k][n], fp16
__global__ void k_selfw_hf(const float* __restrict__ selfw){
    int l = blockIdx.x;
    char* wh = (char*)g_SWh4 + (size_t)l*32768;
    for (int ch = threadIdx.x; ch < 2048; ch += blockDim.x){
        int n  = ch & 127;
        int kc = ch >> 7;
        float v[8];
#pragma unroll
        for (int j = 0; j < 8; j++)
            v[j] = selfw[(size_t)l*D*D + (kc*8 + j)*D + n];
        int off = n*256 + (((kc ^ (n & 7)) & 15) << 4);
        *(uint4*)(wh + off) = pack8h(v);
    }
}

// x0 -> fp16 (row-major)
__global__ void k_xh(const float* __restrict__ x){
    int i = blockIdx.x*blockDim.x + threadIdx.x;
    if (i < NE*16){
        const float4* s = (const float4*)x + (size_t)i*2;
        float4 a = s[0], b = s[1];
        float v[8] = {a.x,a.y,a.z,a.w,b.x,b.y,b.z,b.w};
        g_Xh4[i] = pack8h(v);
    }
}

// ---------------- fused GEMM: edge tiles (atomic->AGGh) + self tiles (store->SELFh) ----------------
__global__ void __launch_bounds__(256,2) k_gemm(const int* __restrict__ src,
        const int* __restrict__ tgt, const float* __restrict__ bias, int layer){
    int ntile = g_ntile_all;
    int per = (ntile + gridDim.x - 1) / gridDim.x;
    int i0 = blockIdx.x*per;
    int i1 = min(i0 + per, ntile);
    if (i0 >= i1) return;   // uniform before any barrier

    extern __shared__ __align__(16) char smem[];
    uint32_t sb = smem_u32(smem);
    int tid = threadIdx.x, lane = tid & 31, wid = tid >> 5;
    int mw = wid & 3, nw = wid >> 2;
    int gr = tid >> 1, gh = tid & 1;

    float2 bs[8];
#pragma unroll
    for (int nf = 0; nf < 8; nf++)
        bs[nf] = *(const float2*)(bias + layer*D + nw*64 + nf*8 + (lane & 3)*2);

    auto idx_load = [&](int ent, int& srow, int& tg, float& w){
        int r = ent >> 16, t = ent & 0xffff;
        if (r == NR){
            srow = min(t*128 + gr, NE-1); tg = 0; w = 0.f;
        } else {
            int s0 = g_off[r];
            int valid = min(128, g_off[r+1] - s0 - t*128);
            int e = g_ord[s0 + t*128 + min(gr, valid-1)];
            srow = src[e];
            tg = tgt[e];
            w = (gr < valid) ? (1.f / fmaxf(g_indeg[tg], 1.f)) : 0.f;
        }
    };
    auto copyB = [&](int r){
        const uint4* wh = (r == NR) ? (g_SWh4 + (size_t)layer*2048)
                                    : (g_Wh4 + ((size_t)layer*NR + r)*2048);
        for (int i = tid; i < 2048; i += 256)
            cpa16(sb + SM_BH + (uint32_t)(i*16), wh + i);
    };
    auto gatherA = [&](int srow, int tg, float w){
        const uint4* xh = g_Xh4 + (size_t)srow*16 + gh*8;
#pragma unroll
        for (int j = 0; j < 8; j++){
            int c = gh*8 + j;
            uint32_t off = (uint32_t)(gr*256 + (((c ^ (gr & 7)) & 15) << 4));
            cpa16(sb + SM_A + off, xh + j);
        }
        if (gh == 0){
            ((int*)(smem + SM_TGT))[gr] = tg;
            ((float*)(smem + SM_WGT))[gr] = w;
        }
    };

    // prologue
    int ent_cur = g_tiles[i0];
    int cur_r = ent_cur >> 16;
    int srow, tg; float w;
    idx_load(ent_cur, srow, tg, w);
    copyB(cur_r);
    gatherA(srow, tg, w);
    CP_COMMIT();

    int ent_next = 0;
    for (int i = i0; i < i1; i++){
        bool more = (i + 1 < i1);
        if (more){ ent_next = g_tiles[i + 1]; idx_load(ent_next, srow, tg, w); }
        CP_WAIT0();
        __syncthreads();

        bool isSelf = (ent_cur >> 16) == NR;
        int tgr[2][2]; float wgr[2][2];
        if (!isSelf){
            int* s_tgt = (int*)(smem + SM_TGT);
            float* s_wgt = (float*)(smem + SM_WGT);
            int rb = mw*32 + (lane >> 2);
#pragma unroll
            for (int mi = 0; mi < 2; mi++)
#pragma unroll
                for (int h = 0; h < 2; h++){
                    int rr = rb + mi*16 + h*8;
                    tgr[mi][h] = s_tgt[rr];
                    wgr[mi][h] = s_wgt[rr];
                }
        }

        float acc[2][8][4];
#pragma unroll
        for (int mi = 0; mi < 2; mi++)
#pragma unroll
            for (int nf = 0; nf < 8; nf++)
#pragma unroll
                for (int q = 0; q < 4; q++) acc[mi][nf][q] = 0.f;

        mma_loop(sb + SM_A, sb + SM_BH, lane, mw, nw, acc);
        __syncthreads();                         // A/B/idx reads done

        if (more){                               // overlap next gather with epilogue
            int rn = ent_next >> 16;
            if (rn != cur_r){ copyB(rn); cur_r = rn; }
            gatherA(srow, tg, w);
            CP_COMMIT();
        }

        if (isSelf){
            int t = ent_cur & 0xffff;
#pragma unroll
            for (int mi = 0; mi < 2; mi++){
                int r0 = t*128 + mw*32 + mi*16 + (lane >> 2);
#pragma unroll
                for (int nf = 0; nf < 8; nf++){
                    int cu = nw*32 + nf*4 + (lane & 3);
                    if (r0 < NE)
                        g_SELFh[(size_t)r0*64 + cu] = packh2(acc[mi][nf][0] + bs[nf].x,
                                                             acc[mi][nf][1] + bs[nf].y);
                    if (r0 + 8 < NE)
                        g_SELFh[(size_t)(r0+8)*64 + cu] = packh2(acc[mi][nf][2] + bs[nf].x,
                                                                 acc[mi][nf][3] + bs[nf].y);
                }
            }
        } else {
            // edge epilogue: assemble 16B per row, one v4.f16x2 atomic per 8 cols
            int odd = lane & 1;
#pragma unroll
            for (int mi = 0; mi < 2; mi++){
                float ww = wgr[mi][odd];
                int   tt = tgr[mi][odd];
                unsigned* rowp = g_AGGh + (size_t)tt*64 + nw*32;
#pragma unroll
                for (int nf = 0; nf < 8; nf++){
                    float c0 = acc[mi][nf][0], c1 = acc[mi][nf][1];
                    float c2 = acc[mi][nf][2], c3 = acc[mi][nf][3];
                    float s0 = __shfl_xor_sync(0xffffffffu, odd ? c0 : c2, 1);
                    float s1 = __shfl_xor_sync(0xffffffffu, odd ? c1 : c3, 1);
                    float v0, v1, v2, v3;
                    if (!odd){ v0 = c0; v1 = c1; v2 = s0; v3 = s1; }
                    else     { v0 = s0; v1 = s1; v2 = c2; v3 = c3; }
                    unsigned p0 = packh2(ww*v0, ww*v1);
                    unsigned p1 = packh2(ww*v2, ww*v3);
                    unsigned q0 = __shfl_xor_sync(0xffffffffu, p0, 2);
                    unsigned q1 = __shfl_xor_sync(0xffffffffu, p1, 2);
                    if (!(lane & 2) && ww != 0.f)
                        red16h(rowp + nf*4, p0, p1, q0, q1);
                }
            }
        }
        ent_cur = ent_next;
    }
}

// ---------------- ReLU: (SELFh + AGGh) fp32-add, relu; repack (L0, +zero AGGh) or fp32 out (L1) ----
__global__ void k_relu(float* __restrict__ dout, int layer){
    int i = blockIdx.x*blockDim.x + threadIdx.x;
    if (i < NE*16){
        uint4 a = ((const uint4*)g_AGGh)[i];
        uint4 s = ((const uint4*)g_SELFh)[i];
        float2 f0 = h2f(a.x), f1 = h2f(a.y), f2 = h2f(a.z), f3 = h2f(a.w);
        float2 g0 = h2f(s.x), g1 = h2f(s.y), g2 = h2f(s.z), g3 = h2f(s.w);
        f0.x = fmaxf(f0.x + g0.x, 0.f); f0.y = fmaxf(f0.y + g0.y, 0.f);
        f1.x = fmaxf(f1.x + g1.x, 0.f); f1.y = fmaxf(f1.y + g1.y, 0.f);
        f2.x = fmaxf(f2.x + g2.x, 0.f); f2.y = fmaxf(f2.y + g2.y, 0.f);
        f3.x = fmaxf(f3.x + g3.x, 0.f); f3.y = fmaxf(f3.y + g3.y, 0.f);
        if (layer == 0){
            g_Xh4[i] = make_uint4(packh2(f0.x,f0.y), packh2(f1.x,f1.y),
                                  packh2(f2.x,f2.y), packh2(f3.x,f3.y));
            ((uint4*)g_AGGh)[i] = make_uint4(0,0,0,0);   // ready for layer 1 atomics
        } else {
            float4* o = (float4*)dout + (size_t)i*2;
            o[0] = make_float4(f0.x, f0.y, f1.x, f1.y);
            o[1] = make_float4(f2.x, f2.y, f3.x, f3.y);
        }
    }
}

// ---------------- launch ----------------
extern "C" void kernel_launch(void* const* d_in, const int* in_sizes, int n_in,
                              void* d_out, int out_size){
    const float* x0    = (const float*)d_in[0];
    const float* bases = (const float*)d_in[1];
    const float* coefs = (const float*)d_in[2];
    const float* selfw = (const float*)d_in[3];
    const float* bias  = (const float*)d_in[4];
    const int*   source= (const int*)d_in[5];
    const int*   target= (const int*)d_in[6];
    const int*   etype = (const int*)d_in[7];
    float* out = (float*)d_out;

    static int inited = 0;
    if (!inited){
        cudaFuncSetAttribute(k_gemm, cudaFuncAttributeMaxDynamicSharedMemorySize, SM_TOT);
        inited = 1;
    }

    k_init<<<(NE*16+255)/256, 256>>>();
    k_hist<<<(EG+EPB-1)/EPB, 256>>>(target, etype);
    k_scan<<<1, 128>>>();
    k_scatter<<<(EG+EPB-1)/EPB, 256>>>(etype);
    k_relw_hf<<<NL*NR, 256>>>(bases, coefs);
    k_selfw_hf<<<NL, 256>>>(selfw);
    k_xh<<<(NE*16+255)/256, 256>>>(x0);

    for (int l = 0; l < NL; l++){
        k_gemm<<<EG_GRID, 256, SM_TOT>>>(source, target, bias, l);
        k_relu<<<(NE*16+255)/256, 256>>>(out, l);
    }
}

// round 13
// speedup vs baseline: 5.1601x; 1.0481x over previous
#include <cuda_runtime.h>
#include <cuda_fp16.h>
#include <cstdint>

#define NE 100000
#define NR 100
#define D  128
#define NB 10
#define NL 2
#define EG 600000
#define EPB 2048
#define EG_GRID 296     // persistent blocks, occ 2 on 148 SMs
#define NSELF 782       // ceil(NE/128)

// ---------------- scratch (device globals: no allocation allowed) ----------------
__device__ __align__(256) unsigned g_AGGh[(size_t)NE*64];   // edge msg sum, packed half2 (atomics)
__device__ __align__(256) unsigned g_SELFh[(size_t)NE*64];  // self-term + bias, packed half2
__device__ float g_indeg[NE];
__device__ int   g_cnt[NR];
__device__ int   g_off[NR+1];
__device__ int   g_cur[NR];
__device__ int   g_ord[EG];                // edge ids grouped by relation
__device__ int   g_tiles[8192];            // flat tile table: (r<<16)|t ; r==NR -> self tile
__device__ int   g_ntile_all;
// fp16 operands (single precision-level)
__device__ uint4 g_Wh4[(size_t)NL*NR*2048];   // 32KB per (l,r): Wt[n][k] fp16, swizzled rows
__device__ uint4 g_SWh4[(size_t)NL*2048];     // self_w transposed fp16
__device__ uint4 g_Xh4[(size_t)NE*16];        // row-major: 128 fp16 per row (256B)

// SMEM layout (dynamic, bytes): idx, 1 A buf, B  -> 67584 B (occ 2)
#define SM_TGT 0
#define SM_WGT 512
#define SM_A   2048
#define SM_BH  (SM_A + 32768)
#define SM_TOT (SM_BH + 32768)

// ---------------- helpers ----------------
__device__ __forceinline__ void red16h(unsigned* p, unsigned a, unsigned b, unsigned c, unsigned d){
    asm volatile("red.global.add.noftz.v4.f16x2 [%0], {%1,%2,%3,%4};"
                 :: "l"(p), "r"(a), "r"(b), "r"(c), "r"(d) : "memory");
}
__device__ __forceinline__ void cpa16(uint32_t dst, const void* src){
    asm volatile("cp.async.cg.shared.global [%0], [%1], 16;" :: "r"(dst), "l"(src) : "memory");
}
#define CP_COMMIT() asm volatile("cp.async.commit_group;" ::: "memory")
#define CP_WAIT0()  asm volatile("cp.async.wait_group 0;" ::: "memory")

__device__ __forceinline__ unsigned packh2(float a, float b){
    __half2 h = __floats2half2_rn(a, b);
    return *reinterpret_cast<unsigned*>(&h);
}
__device__ __forceinline__ uint4 pack8h(const float* v){
    return make_uint4(packh2(v[0],v[1]), packh2(v[2],v[3]),
                      packh2(v[4],v[5]), packh2(v[6],v[7]));
}
__device__ __forceinline__ float2 h2f(unsigned u){
    return __half22float2(*reinterpret_cast<__half2*>(&u));
}
__device__ __forceinline__ uint32_t smem_u32(const void* p){
    uint32_t a;
    asm("{ .reg .u64 t; cvta.to.shared.u64 t, %1; cvt.u32.u64 %0, t; }" : "=r"(a) : "l"(p));
    return a;
}
// row-major tile, 256B rows, 16B chunks XOR-swizzled by row
__device__ __forceinline__ uint32_t swa(uint32_t base, int r, int c){
    return base + r*256 + (((c ^ (r & 7)) & 15) << 4);
}
#define LDSM4(d0,d1,d2,d3,a) asm volatile( \
    "ldmatrix.sync.aligned.m8n8.x4.shared.b16 {%0,%1,%2,%3}, [%4];" \
    : "=r"(d0),"=r"(d1),"=r"(d2),"=r"(d3) : "r"(a))
#define MMA16816(c,a0,a1,a2,a3,b0,b1) asm volatile( \
    "mma.sync.aligned.m16n8k16.row.col.f32.f16.f16.f32 " \
    "{%0,%1,%2,%3},{%4,%5,%6,%7},{%8,%9},{%0,%1,%2,%3};" \
    : "+f"((c)[0]),"+f"((c)[1]),"+f"((c)[2]),"+f"((c)[3]) \
    : "r"(a0),"r"(a1),"r"(a2),"r"(a3),"r"(b0),"r"(b1))

// 128x128x128 mainloop: acc += A*B   (A and B single fp16)
__device__ __forceinline__ void mma_loop(uint32_t aT, uint32_t bH,
                                         int lane, int mw, int nw, float acc[2][8][4]){
    int ar = mw*32 + (lane & 15);
    int ac_sel = lane >> 4;
    int br = nw*64 + ((lane >> 4) & 1)*8 + (lane & 7);
    int bc_sel = (lane >> 3) & 1;
    for (int ks = 0; ks < 8; ks++){
        int ac = ks*2 + ac_sel;
        int bc = ks*2 + bc_sel;
        uint32_t a[2][4], bh[8][2];
#pragma unroll
        for (int mi = 0; mi < 2; mi++)
            LDSM4(a[mi][0],a[mi][1],a[mi][2],a[mi][3], swa(aT, ar+mi*16, ac));
#pragma unroll
        for (int p = 0; p < 4; p++)
            LDSM4(bh[2*p][0],bh[2*p][1],bh[2*p+1][0],bh[2*p+1][1], swa(bH, br+p*16, bc));
#pragma unroll
        for (int mi = 0; mi < 2; mi++)
#pragma unroll
        for (int nf = 0; nf < 8; nf++)
            MMA16816(acc[mi][nf], a[mi][0],a[mi][1],a[mi][2],a[mi][3], bh[nf][0],bh[nf][1]);
    }
}

// ---------------- prep kernels ----------------
// fused: zero indeg/cnt/AGGh + convert x0 -> fp16
__global__ void k_init(const float* __restrict__ x){
    int i = blockIdx.x*blockDim.x + threadIdx.x;
    if (i < NE) g_indeg[i] = 0.f;
    if (i < NR) g_cnt[i] = 0;
    if (i < NE*16){
        ((uint4*)g_AGGh)[i] = make_uint4(0,0,0,0);
        const float4* s = (const float4*)x + (size_t)i*2;
        float4 a = s[0], b = s[1];
        float v[8] = {a.x,a.y,a.z,a.w,b.x,b.y,b.z,b.w};
        g_Xh4[i] = pack8h(v);
    }
}

__global__ void k_hist(const int* __restrict__ tgt, const int* __restrict__ et){
    __shared__ int lcnt[NR];
    int tid = threadIdx.x;
    for (int i = tid; i < NR; i += 256) lcnt[i] = 0;
    __syncthreads();
    int e0 = blockIdx.x*EPB;
#pragma unroll
    for (int q = 0; q < EPB/256; q++){
        int e = e0 + q*256 + tid;
        if (e < EG){
            atomicAdd(&g_indeg[tgt[e]], 1.f);
            atomicAdd(&lcnt[et[e]], 1);
        }
    }
    __syncthreads();
    for (int i = tid; i < NR; i += 256)
        if (lcnt[i]) atomicAdd(&g_cnt[i], lcnt[i]);
}

// offsets + flat tile table (edge tiles, then NSELF self tiles with r==NR)
__global__ void k_scan(){
    __shared__ int ptil[NR];
    __shared__ int strun;
    int tid = threadIdx.x;
    if (tid == 0){
        int run = 0, trun = 0;
        for (int r = 0; r < NR; r++){
            g_off[r] = run; g_cur[r] = run;
            ptil[r] = trun;
            trun += (g_cnt[r] + 127) >> 7;
            run += g_cnt[r];
        }
        g_off[NR] = run;
        strun = trun;
        g_ntile_all = trun + NSELF;
    }
    __syncthreads();
    for (int r = tid; r < NR; r += blockDim.x){
        int nt = (g_cnt[r] + 127) >> 7;
        int base = ptil[r];
        for (int t = 0; t < nt; t++) g_tiles[base + t] = (r << 16) | t;
    }
    int et = strun;
    for (int t = tid; t < NSELF; t += blockDim.x)
        g_tiles[et + t] = (NR << 16) | t;
}

__global__ void k_scatter(const int* __restrict__ et){
    __shared__ int lcnt[NR];
    __shared__ int lbase[NR];
    int tid = threadIdx.x;
    for (int i = tid; i < NR; i += 256) lcnt[i] = 0;
    __syncthreads();
    int e0 = blockIdx.x*EPB;
    int rel[EPB/256], lpos[EPB/256];
#pragma unroll
    for (int q = 0; q < EPB/256; q++){
        int e = e0 + q*256 + tid;
        if (e < EG){
            rel[q]  = et[e];
            lpos[q] = atomicAdd(&lcnt[rel[q]], 1);
        }
    }
    __syncthreads();
    for (int i = tid; i < NR; i += 256)
        if (lcnt[i]) lbase[i] = atomicAdd(&g_cur[i], lcnt[i]);
    __syncthreads();
#pragma unroll
    for (int q = 0; q < EPB/256; q++){
        int e = e0 + q*256 + tid;
        if (e < EG) g_ord[lbase[rel[q]] + lpos[q]] = e;
    }
}

// fused W build: blocks [0, NL*NR): Wt; blocks [NL*NR, NL*NR+NL): self_w transposed
__global__ void k_relw_hf(const float* __restrict__ bases, const float* __restrict__ coefs,
                          const float* __restrict__ selfw){
    int blk = blockIdx.x;
    if (blk < NL*NR){
        int lr = blk;
        float c[NB];
#pragma unroll
        for (int b = 0; b < NB; b++) c[b] = coefs[lr*NB + b];
        char* wh = (char*)g_Wh4 + (size_t)lr*32768;
        for (int ch = threadIdx.x; ch < 2048; ch += blockDim.x){
            int n  = ch & 127;
            int kc = ch >> 7;
            float v[8];
#pragma unroll
            for (int j = 0; j < 8; j++){
                int k = kc*8 + j;
                float a = 0.f;
#pragma unroll
                for (int b = 0; b < NB; b++) a += c[b]*bases[b*D*D + k*D + n];
                v[j] = a;
            }
            int off = n*256 + (((kc ^ (n & 7)) & 15) << 4);
            *(uint4*)(wh + off) = pack8h(v);
        }
    } else {
        int l = blk - NL*NR;
        char* wh = (char*)g_SWh4 + (size_t)l*32768;
        for (int ch = threadIdx.x; ch < 2048; ch += blockDim.x){
            int n  = ch & 127;
            int kc = ch >> 7;
            float v[8];
#pragma unroll
            for (int j = 0; j < 8; j++)
                v[j] = selfw[(size_t)l*D*D + (kc*8 + j)*D + n];
            int off = n*256 + (((kc ^ (n & 7)) & 15) << 4);
            *(uint4*)(wh + off) = pack8h(v);
        }
    }
}

// ---------------- fused GEMM: edge tiles (v4 atomic->AGGh) + self tiles (store->SELFh) ----------------
__global__ void __launch_bounds__(256,2) k_gemm(const int* __restrict__ src,
        const int* __restrict__ tgt, const float* __restrict__ bias, int layer){
    int ntile = g_ntile_all;
    int per = (ntile + gridDim.x - 1) / gridDim.x;
    int i0 = blockIdx.x*per;
    int i1 = min(i0 + per, ntile);
    if (i0 >= i1) return;   // uniform before any barrier

    extern __shared__ __align__(16) char smem[];
    uint32_t sb = smem_u32(smem);
    int tid = threadIdx.x, lane = tid & 31, wid = tid >> 5;
    int mw = wid & 3, nw = wid >> 2;
    int gr = tid >> 1, gh = tid & 1;

    float2 bs[8];
#pragma unroll
    for (int nf = 0; nf < 8; nf++)
        bs[nf] = *(const float2*)(bias + layer*D + nw*64 + nf*8 + (lane & 3)*2);

    auto idx_load = [&](int ent, int& srow, int& tg, float& fl){
        int r = ent >> 16, t = ent & 0xffff;
        if (r == NR){
            srow = min(t*128 + gr, NE-1); tg = 0; fl = 0.f;
        } else {
            int s0 = g_off[r];
            int valid = min(128, g_off[r+1] - s0 - t*128);
            int e = g_ord[s0 + t*128 + min(gr, valid-1)];
            srow = src[e];
            tg = tgt[e];
            fl = (gr < valid) ? 1.f : 0.f;
        }
    };
    auto copyB = [&](int r){
        const uint4* wh = (r == NR) ? (g_SWh4 + (size_t)layer*2048)
                                    : (g_Wh4 + ((size_t)layer*NR + r)*2048);
        for (int i = tid; i < 2048; i += 256)
            cpa16(sb + SM_BH + (uint32_t)(i*16), wh + i);
    };
    auto gatherA = [&](int srow, int tg, float fl){
        const uint4* xh = g_Xh4 + (size_t)srow*16 + gh*8;
#pragma unroll
        for (int j = 0; j < 8; j++){
            int c = gh*8 + j;
            uint32_t off = (uint32_t)(gr*256 + (((c ^ (gr & 7)) & 15) << 4));
            cpa16(sb + SM_A + off, xh + j);
        }
        if (gh == 0){
            ((int*)(smem + SM_TGT))[gr] = tg;
            ((float*)(smem + SM_WGT))[gr] = fl;
        }
    };

    // prologue
    int ent_cur = g_tiles[i0];
    int cur_r = ent_cur >> 16;
    int srow, tg; float fl;
    idx_load(ent_cur, srow, tg, fl);
    copyB(cur_r);
    gatherA(srow, tg, fl);
    CP_COMMIT();

    int ent_next = 0;
    for (int i = i0; i < i1; i++){
        bool more = (i + 1 < i1);
        if (more){ ent_next = g_tiles[i + 1]; idx_load(ent_next, srow, tg, fl); }
        CP_WAIT0();
        __syncthreads();

        bool isSelf = (ent_cur >> 16) == NR;
        int tgr[2][2]; float wgr[2][2];
        if (!isSelf){
            int* s_tgt = (int*)(smem + SM_TGT);
            float* s_wgt = (float*)(smem + SM_WGT);
            int rb = mw*32 + (lane >> 2);
#pragma unroll
            for (int mi = 0; mi < 2; mi++)
#pragma unroll
                for (int h = 0; h < 2; h++){
                    int rr = rb + mi*16 + h*8;
                    tgr[mi][h] = s_tgt[rr];
                    wgr[mi][h] = s_wgt[rr];
                }
        }

        float acc[2][8][4];
#pragma unroll
        for (int mi = 0; mi < 2; mi++)
#pragma unroll
            for (int nf = 0; nf < 8; nf++)
#pragma unroll
                for (int q = 0; q < 4; q++) acc[mi][nf][q] = 0.f;

        mma_loop(sb + SM_A, sb + SM_BH, lane, mw, nw, acc);
        __syncthreads();                         // A/B/idx reads done

        if (more){                               // overlap next gather with epilogue
            int rn = ent_next >> 16;
            if (rn != cur_r){ copyB(rn); cur_r = rn; }
            gatherA(srow, tg, fl);
            CP_COMMIT();
        }

        if (isSelf){
            int t = ent_cur & 0xffff;
#pragma unroll
            for (int mi = 0; mi < 2; mi++){
                int r0 = t*128 + mw*32 + mi*16 + (lane >> 2);
#pragma unroll
                for (int nf = 0; nf < 8; nf++){
                    int cu = nw*32 + nf*4 + (lane & 3);
                    if (r0 < NE)
                        g_SELFh[(size_t)r0*64 + cu] = packh2(acc[mi][nf][0] + bs[nf].x,
                                                             acc[mi][nf][1] + bs[nf].y);
                    if (r0 + 8 < NE)
                        g_SELFh[(size_t)(r0+8)*64 + cu] = packh2(acc[mi][nf][2] + bs[nf].x,
                                                                 acc[mi][nf][3] + bs[nf].y);
                }
            }
        } else {
            // edge epilogue: assemble 16B per row (unscaled msg), one v4.f16x2 atomic per 8 cols
            int odd = lane & 1;
#pragma unroll
            for (int mi = 0; mi < 2; mi++){
                float flv = wgr[mi][odd];
                int   tt = tgr[mi][odd];
                unsigned* rowp = g_AGGh + (size_t)tt*64 + nw*32;
#pragma unroll
                for (int nf = 0; nf < 8; nf++){
                    float c0 = acc[mi][nf][0], c1 = acc[mi][nf][1];
                    float c2 = acc[mi][nf][2], c3 = acc[mi][nf][3];
                    float s0 = __shfl_xor_sync(0xffffffffu, odd ? c0 : c2, 1);
                    float s1 = __shfl_xor_sync(0xffffffffu, odd ? c1 : c3, 1);
                    float v0, v1, v2, v3;
                    if (!odd){ v0 = c0; v1 = c1; v2 = s0; v3 = s1; }
                    else     { v0 = s0; v1 = s1; v2 = c2; v3 = c3; }
                    unsigned p0 = packh2(v0, v1);
                    unsigned p1 = packh2(v2, v3);
                    unsigned q0 = __shfl_xor_sync(0xffffffffu, p0, 2);
                    unsigned q1 = __shfl_xor_sync(0xffffffffu, p1, 2);
                    if (!(lane & 2) && flv != 0.f)
                        red16h(rowp + nf*4, p0, p1, q0, q1);
                }
            }
        }
        ent_cur = ent_next;
    }
}

// ---------------- ReLU: relu(SELFh + winv*AGGh); repack (L0, +zero AGGh) or fp32 out (L1) ----
__global__ void k_relu(float* __restrict__ dout, int layer){
    int i = blockIdx.x*blockDim.x + threadIdx.x;
    if (i < NE*16){
        int row = i >> 4;
        float winv = 1.f / fmaxf(g_indeg[row], 1.f);
        uint4 a = ((const uint4*)g_AGGh)[i];
        uint4 s = ((const uint4*)g_SELFh)[i];
        float2 f0 = h2f(a.x), f1 = h2f(a.y), f2 = h2f(a.z), f3 = h2f(a.w);
        float2 g0 = h2f(s.x), g1 = h2f(s.y), g2 = h2f(s.z), g3 = h2f(s.w);
        f0.x = fmaxf(fmaf(f0.x, winv, g0.x), 0.f); f0.y = fmaxf(fmaf(f0.y, winv, g0.y), 0.f);
        f1.x = fmaxf(fmaf(f1.x, winv, g1.x), 0.f); f1.y = fmaxf(fmaf(f1.y, winv, g1.y), 0.f);
        f2.x = fmaxf(fmaf(f2.x, winv, g2.x), 0.f); f2.y = fmaxf(fmaf(f2.y, winv, g2.y), 0.f);
        f3.x = fmaxf(fmaf(f3.x, winv, g3.x), 0.f); f3.y = fmaxf(fmaf(f3.y, winv, g3.y), 0.f);
        if (layer == 0){
            g_Xh4[i] = make_uint4(packh2(f0.x,f0.y), packh2(f1.x,f1.y),
                                  packh2(f2.x,f2.y), packh2(f3.x,f3.y));
            ((uint4*)g_AGGh)[i] = make_uint4(0,0,0,0);   // ready for layer 1 atomics
        } else {
            float4* o = (float4*)dout + (size_t)i*2;
            o[0] = make_float4(f0.x, f0.y, f1.x, f1.y);
            o[1] = make_float4(f2.x, f2.y, f3.x, f3.y);
        }
    }
}

// ---------------- launch ----------------
extern "C" void kernel_launch(void* const* d_in, const int* in_sizes, int n_in,
                              void* d_out, int out_size){
    const float* x0    = (const float*)d_in[0];
    const float* bases = (const float*)d_in[1];
    const float* coefs = (const float*)d_in[2];
    const float* selfw = (const float*)d_in[3];
    const float* bias  = (const float*)d_in[4];
    const int*   source= (const int*)d_in[5];
    const int*   target= (const int*)d_in[6];
    const int*   etype = (const int*)d_in[7];
    float* out = (float*)d_out;

    static int inited = 0;
    if (!inited){
        cudaFuncSetAttribute(k_gemm, cudaFuncAttributeMaxDynamicSharedMemorySize, SM_TOT);
        inited = 1;
    }

    k_init<<<(NE*16+255)/256, 256>>>(x0);
    k_hist<<<(EG+EPB-1)/EPB, 256>>>(target, etype);
    k_scan<<<1, 128>>>();
    k_scatter<<<(EG+EPB-1)/EPB, 256>>>(etype);
    k_relw_hf<<<NL*NR + NL, 256>>>(bases, coefs, selfw);

    for (int l = 0; l < NL; l++){
        k_gemm<<<EG_GRID, 256, SM_TOT>>>(source, target, bias, l);
        k_relu<<<(NE*16+255)/256, 256>>>(out, l);
    }
}